// round 1
// baseline (speedup 1.0000x reference)
#include <cuda_runtime.h>
#include <math.h>

#define EPS 1e-5f

// ---------------- scratch (device globals; no allocation allowed) ----------------
__device__ float g_py1[16L * 256 * 4096];   // 67 MB
__device__ float g_py2[16L * 128 * 4096];   // 33 MB
__device__ float g_e1 [16L * 256 * 512];    // e1 raw [b, c(256), d(512)]
__device__ float g_e1t[16L * 512 * 256];    // e1 propagated+transposed [b, d(512), o(256)]
__device__ float g_e2 [16L * 256 * 128];    // e2 raw [b, d(256), c(128)]
__device__ float g_e2p[16L * 256 * 128];    // e2 propagated
__device__ float g_eng[16L * 512 * 128];    // energy
__device__ float g_att[16L * 512 * 128];    // attention
__device__ float g_opr[16L * 512 * 4096];   // gamma*attnout + x (conv input), 134 MB

__device__ float g_s1[256], g_t1[256];
__device__ float g_s2[128], g_t2[128];
__device__ float g_s3[512], g_t3[512];

// ---------------- fold BN (+conv bias) into per-channel scale/shift --------------
__global__ void fold_kernel(const float* __restrict__ q1b, const float* __restrict__ g1,
                            const float* __restrict__ b1,  const float* __restrict__ m1,
                            const float* __restrict__ v1,
                            const float* __restrict__ q2b, const float* __restrict__ g2,
                            const float* __restrict__ b2,  const float* __restrict__ m2,
                            const float* __restrict__ v2,
                            const float* __restrict__ fb,  const float* __restrict__ g3,
                            const float* __restrict__ b3,  const float* __restrict__ m3,
                            const float* __restrict__ v3)
{
    int i = threadIdx.x;
    if (i < 256) {
        float s = g1[i] * rsqrtf(v1[i] + EPS);
        g_s1[i] = s;
        g_t1[i] = s * q1b[i] + b1[i] - m1[i] * s;
    }
    if (i < 128) {
        float s = g2[i] * rsqrtf(v2[i] + EPS);
        g_s2[i] = s;
        g_t2[i] = s * q2b[i] + b2[i] - m2[i] * s;
    }
    if (i < 512) {
        float s = g3[i] * rsqrtf(v3[i] + EPS);
        g_s3[i] = s;
        g_t3[i] = s * fb[i] + b3[i] - m3[i] * s;
    }
}

// ---------------- generic strided batched SGEMM, 64x64 tile, TK=16 ---------------
// C[b, m, n] = sum_k A[b*aBat + m*aSm + k*aSk] * B[b*bBat + k*bSk + n*bSn]
// EPI: 0 none | 1 +tv[m] | 2 relu(sv[m]*acc+tv[m]) | 3 +tv[n] | 4 gamma*acc + res[..]
template <int EPI>
__global__ __launch_bounds__(256)
void sgemm(const float* __restrict__ A, const float* __restrict__ B,
           float* __restrict__ C,
           int M, int N, int K,
           long aBat, long aSm, long aSk,
           long bBat, long bSk, long bSn,
           long cBat,
           const float* __restrict__ sv, const float* __restrict__ tv,
           const float* __restrict__ res, const float* __restrict__ gptr)
{
    __shared__ float As[16][65];
    __shared__ float Bs[16][65];
    int tid = threadIdx.x;
    int tx = tid & 15, ty = tid >> 4;
    int n0 = blockIdx.x * 64, m0 = blockIdx.y * 64;
    long ab = (long)blockIdx.z * aBat;
    long bb = (long)blockIdx.z * bBat;
    long cb = (long)blockIdx.z * cBat;

    float acc[4][4] = {};

    for (int k0 = 0; k0 < K; k0 += 16) {
        if (aSk == 1) {  // A contiguous in k
            #pragma unroll
            for (int i = 0; i < 4; i++) {
                int idx = tid + i * 256;
                int k = idx & 15, m = idx >> 4;
                As[k][m] = A[ab + (long)(m0 + m) * aSm + (k0 + k)];
            }
        } else {         // A contiguous in m (aSm expected 1)
            #pragma unroll
            for (int i = 0; i < 4; i++) {
                int idx = tid + i * 256;
                int m = idx & 63, k = idx >> 6;
                As[k][m] = A[ab + (long)(m0 + m) * aSm + (long)(k0 + k) * aSk];
            }
        }
        if (bSn == 1) {  // B contiguous in n
            #pragma unroll
            for (int i = 0; i < 4; i++) {
                int idx = tid + i * 256;
                int n = idx & 63, k = idx >> 6;
                Bs[k][n] = B[bb + (long)(k0 + k) * bSk + (n0 + n)];
            }
        } else {         // B contiguous in k (bSk expected 1)
            #pragma unroll
            for (int i = 0; i < 4; i++) {
                int idx = tid + i * 256;
                int k = idx & 15, n = idx >> 4;
                Bs[k][n] = B[bb + (long)(k0 + k) * bSk + (long)(n0 + n) * bSn];
            }
        }
        __syncthreads();
        #pragma unroll
        for (int k = 0; k < 16; k++) {
            float a[4], bv[4];
            #pragma unroll
            for (int i = 0; i < 4; i++) a[i] = As[k][ty + 16 * i];
            #pragma unroll
            for (int j = 0; j < 4; j++) bv[j] = Bs[k][tx + 16 * j];
            #pragma unroll
            for (int i = 0; i < 4; i++)
                #pragma unroll
                for (int j = 0; j < 4; j++)
                    acc[i][j] += a[i] * bv[j];
        }
        __syncthreads();
    }

    float gm = 0.f;
    if (EPI == 4) gm = gptr[0];
    #pragma unroll
    for (int i = 0; i < 4; i++) {
        int m = m0 + ty + 16 * i;
        #pragma unroll
        for (int j = 0; j < 4; j++) {
            int n = n0 + tx + 16 * j;
            float v = acc[i][j];
            if (EPI == 1) v += tv[m];
            else if (EPI == 2) v = fmaxf(sv[m] * v + tv[m], 0.f);
            else if (EPI == 3) v += tv[n];
            else if (EPI == 4) v = gm * v + res[cb + (long)m * N + n];
            C[cb + (long)m * N + n] = v;
        }
    }
}

// ---------------- softmax of (rowmax - E) == softmax over (-E), rows of 128 ------
__global__ void softmax_neg(const float* __restrict__ E, float* __restrict__ A)
{
    int row = blockIdx.x;
    int t = threadIdx.x;
    __shared__ float red[128];
    float v = E[(long)row * 128 + t];
    red[t] = v;
    __syncthreads();
    for (int s = 64; s > 0; s >>= 1) {
        if (t < s) red[t] = fminf(red[t], red[t + s]);
        __syncthreads();
    }
    float mn = red[0];
    __syncthreads();
    float ex = expf(mn - v);
    red[t] = ex;
    __syncthreads();
    for (int s = 64; s > 0; s >>= 1) {
        if (t < s) red[t] += red[t + s];
        __syncthreads();
    }
    A[(long)row * 128 + t] = ex / red[0];
}

// ---------------- direct 3x3 conv, 512->512, pad 1, fused BN+ReLU ---------------
// block: 256 threads (tx 0..31, ty 0..7); spatial tile 32x32 (4 rows / thread),
// 8 output channels / block, input channels chunked by 4.
__global__ __launch_bounds__(256)
void conv3x3_kernel(const float* __restrict__ in, const float* __restrict__ w,
                    float* __restrict__ out)
{
    const int ICB = 4;
    __shared__ float sIn[ICB][34][36];
    __shared__ float sW[8][ICB][9];

    int tid = threadIdx.x;
    int tx = tid & 31, ty = tid >> 5;           // 32 x 8
    int b  = blockIdx.z;
    int oc0 = blockIdx.y * 8;
    int y0 = (blockIdx.x >> 1) * 32;
    int x0 = (blockIdx.x & 1) * 32;

    float acc[8][4] = {};
    const long inB = (long)b * 512 * 4096;

    for (int ic0 = 0; ic0 < 512; ic0 += ICB) {
        __syncthreads();
        for (int idx = tid; idx < ICB * 34 * 34; idx += 256) {
            int c = idx / (34 * 34);
            int r = idx % (34 * 34);
            int iy = r / 34, ix = r % 34;
            int gy = y0 + iy - 1, gx = x0 + ix - 1;
            float v = 0.f;
            if (gy >= 0 && gy < 64 && gx >= 0 && gx < 64)
                v = in[inB + (long)(ic0 + c) * 4096 + gy * 64 + gx];
            sIn[c][iy][ix] = v;
        }
        for (int idx = tid; idx < 8 * ICB * 9; idx += 256) {
            int oc = idx / (ICB * 9);
            int r = idx % (ICB * 9);
            int ic = r / 9, t = r % 9;
            sW[oc][ic][t] = w[((long)(oc0 + oc) * 512 + ic0 + ic) * 9 + t];
        }
        __syncthreads();

        for (int ic = 0; ic < ICB; ic++) {
            #pragma unroll
            for (int ky = 0; ky < 3; ky++)
            #pragma unroll
            for (int kx = 0; kx < 3; kx++) {
                float wr[8];
                #pragma unroll
                for (int oc = 0; oc < 8; oc++) wr[oc] = sW[oc][ic][ky * 3 + kx];
                float i0 = sIn[ic][ty      + ky][tx + kx];
                float i1 = sIn[ic][ty +  8 + ky][tx + kx];
                float i2 = sIn[ic][ty + 16 + ky][tx + kx];
                float i3 = sIn[ic][ty + 24 + ky][tx + kx];
                #pragma unroll
                for (int oc = 0; oc < 8; oc++) {
                    acc[oc][0] += wr[oc] * i0;
                    acc[oc][1] += wr[oc] * i1;
                    acc[oc][2] += wr[oc] * i2;
                    acc[oc][3] += wr[oc] * i3;
                }
            }
        }
    }

    #pragma unroll
    for (int oc = 0; oc < 8; oc++) {
        float s = g_s3[oc0 + oc], t = g_t3[oc0 + oc];
        long base = ((long)b * 512 + oc0 + oc) * 4096;
        #pragma unroll
        for (int py = 0; py < 4; py++)
            out[base + (y0 + ty + 8 * py) * 64 + x0 + tx] =
                fmaxf(s * acc[oc][py] + t, 0.f);
    }
}

// ------------------------------- launcher ---------------------------------------
extern "C" void kernel_launch(void* const* d_in, const int* in_sizes, int n_in,
                              void* d_out, int out_size)
{
    const float* x     = (const float*)d_in[0];
    const float* q1_w  = (const float*)d_in[1];
    const float* q1_b  = (const float*)d_in[2];
    const float* bn1_g = (const float*)d_in[3];
    const float* bn1_b = (const float*)d_in[4];
    const float* bn1_m = (const float*)d_in[5];
    const float* bn1_v = (const float*)d_in[6];
    const float* q2_w  = (const float*)d_in[7];
    const float* q2_b  = (const float*)d_in[8];
    const float* bn2_g = (const float*)d_in[9];
    const float* bn2_b = (const float*)d_in[10];
    const float* bn2_m = (const float*)d_in[11];
    const float* bn2_v = (const float*)d_in[12];
    const float* p1_w  = (const float*)d_in[13];
    const float* p1_b  = (const float*)d_in[14];
    const float* fus_w = (const float*)d_in[15];
    const float* fus_b = (const float*)d_in[16];
    const float* bn3_g = (const float*)d_in[17];
    const float* bn3_b = (const float*)d_in[18];
    const float* bn3_m = (const float*)d_in[19];
    const float* bn3_v = (const float*)d_in[20];
    const float* gamma = (const float*)d_in[21];

    float *py1, *py2, *e1, *e1t, *e2, *e2p, *eng, *att, *opr, *s1, *t1, *s2, *t2;
    cudaGetSymbolAddress((void**)&py1, g_py1);
    cudaGetSymbolAddress((void**)&py2, g_py2);
    cudaGetSymbolAddress((void**)&e1,  g_e1);
    cudaGetSymbolAddress((void**)&e1t, g_e1t);
    cudaGetSymbolAddress((void**)&e2,  g_e2);
    cudaGetSymbolAddress((void**)&e2p, g_e2p);
    cudaGetSymbolAddress((void**)&eng, g_eng);
    cudaGetSymbolAddress((void**)&att, g_att);
    cudaGetSymbolAddress((void**)&opr, g_opr);
    cudaGetSymbolAddress((void**)&s1,  g_s1);
    cudaGetSymbolAddress((void**)&t1,  g_t1);
    cudaGetSymbolAddress((void**)&s2,  g_s2);
    cudaGetSymbolAddress((void**)&t2,  g_t2);

    fold_kernel<<<1, 512>>>(q1_b, bn1_g, bn1_b, bn1_m, bn1_v,
                            q2_b, bn2_g, bn2_b, bn2_m, bn2_v,
                            fus_b, bn3_g, bn3_b, bn3_m, bn3_v);

    // 1) py1 = relu(bn1(q1_w @ x))  [16, 256, 4096]
    sgemm<2><<<dim3(64, 4, 16), 256>>>(q1_w, x, py1, 256, 4096, 512,
        0L, 512L, 1L,  512L * 4096, 4096L, 1L,  256L * 4096,
        s1, t1, nullptr, nullptr);

    // 2) py2 = relu(bn2(q2_w @ py1))  [16, 128, 4096]
    sgemm<2><<<dim3(64, 2, 16), 256>>>(q2_w, py1, py2, 128, 4096, 256,
        0L, 256L, 1L,  256L * 4096, 4096L, 1L,  128L * 4096,
        s2, t2, nullptr, nullptr);

    // 3) e1[c,d] = sum_n py1[c,n] * x[d,n]  [16, 256, 512]
    sgemm<0><<<dim3(8, 4, 16), 256>>>(py1, x, e1, 256, 512, 4096,
        256L * 4096, 4096L, 1L,  512L * 4096, 1L, 4096L,  256L * 512,
        nullptr, nullptr, nullptr, nullptr);

    // 4) e1t[d,o] = sum_c e1[c,d] * p1_w[o,c] + p1_b[o]  [16, 512, 256]
    sgemm<3><<<dim3(4, 8, 16), 256>>>(e1, p1_w, e1t, 512, 256, 256,
        256L * 512, 1L, 512L,  0L, 1L, 256L,  512L * 256,
        nullptr, p1_b, nullptr, nullptr);

    // 5) e2[d,c] = sum_n py1[d,n] * py2[c,n]  [16, 256, 128]
    sgemm<0><<<dim3(2, 4, 16), 256>>>(py1, py2, e2, 256, 128, 4096,
        256L * 4096, 4096L, 1L,  128L * 4096, 1L, 4096L,  256L * 128,
        nullptr, nullptr, nullptr, nullptr);

    // 6) e2p[o,c] = sum_d p1_w[o,d] * e2[d,c] + p1_b[o]  [16, 256, 128]
    sgemm<1><<<dim3(2, 4, 16), 256>>>(p1_w, e2, e2p, 256, 128, 256,
        0L, 256L, 1L,  256L * 128, 128L, 1L,  256L * 128,
        nullptr, p1_b, nullptr, nullptr);

    // 7) energy = e1t @ e2p  [16, 512, 128]
    sgemm<0><<<dim3(2, 8, 16), 256>>>(e1t, e2p, eng, 512, 128, 256,
        512L * 256, 256L, 1L,  256L * 128, 128L, 1L,  512L * 128,
        nullptr, nullptr, nullptr, nullptr);

    // 8) attention = softmax(rowmax - energy)
    softmax_neg<<<16 * 512, 128>>>(eng, att);

    // 9) opr = gamma * (attention @ py2) + x  [16, 512, 4096]
    sgemm<4><<<dim3(64, 8, 16), 256>>>(att, py2, opr, 512, 4096, 128,
        512L * 128, 128L, 1L,  128L * 4096, 4096L, 1L,  512L * 4096,
        nullptr, nullptr, x, gamma);

    // 10) out = relu(bn3(conv3x3(opr) + fus_b))
    conv3x3_kernel<<<dim3(4, 64, 16), 256>>>(opr, fus_w, (float*)d_out);
}

// round 2
// speedup vs baseline: 2.3109x; 2.3109x over previous
#include <cuda_runtime.h>
#include <math.h>
#include <stdint.h>

#define EPS 1e-5f

// ---------------- scratch (device globals; no allocation allowed) ----------------
__device__ float g_py1[16L * 256 * 4096];   // 67 MB
__device__ float g_py2[16L * 128 * 4096];   // 33 MB
__device__ float g_e1 [16L * 256 * 512];
__device__ float g_e1t[16L * 512 * 256];
__device__ float g_e2 [16L * 256 * 128];
__device__ float g_e2p[16L * 256 * 128];
__device__ float g_eng[16L * 512 * 128];
__device__ float g_att[16L * 512 * 128];
__device__ float g_opr[16L * 512 * 4096];   // conv input, 134 MB
__device__ uint32_t g_wT[512L * 9 * 512];   // transposed conv weights [ic][tap][oc], tf32

__device__ float g_s1[256], g_t1[256];
__device__ float g_s2[128], g_t2[128];
__device__ float g_s3[512], g_t3[512];

// ---------------- fold BN (+conv bias) into per-channel scale/shift --------------
__global__ void fold_kernel(const float* __restrict__ q1b, const float* __restrict__ g1,
                            const float* __restrict__ b1,  const float* __restrict__ m1,
                            const float* __restrict__ v1,
                            const float* __restrict__ q2b, const float* __restrict__ g2,
                            const float* __restrict__ b2,  const float* __restrict__ m2,
                            const float* __restrict__ v2,
                            const float* __restrict__ fb,  const float* __restrict__ g3,
                            const float* __restrict__ b3,  const float* __restrict__ m3,
                            const float* __restrict__ v3)
{
    int i = threadIdx.x;
    if (i < 256) {
        float s = g1[i] * rsqrtf(v1[i] + EPS);
        g_s1[i] = s;
        g_t1[i] = s * q1b[i] + b1[i] - m1[i] * s;
    }
    if (i < 128) {
        float s = g2[i] * rsqrtf(v2[i] + EPS);
        g_s2[i] = s;
        g_t2[i] = s * q2b[i] + b2[i] - m2[i] * s;
    }
    if (i < 512) {
        float s = g3[i] * rsqrtf(v3[i] + EPS);
        g_s3[i] = s;
        g_t3[i] = s * fb[i] + b3[i] - m3[i] * s;
    }
}

// ---------------- tf32 helpers ---------------------------------------------------
__device__ __forceinline__ uint32_t f2tf32(float f) {
    uint32_t r;
    asm("cvt.rna.tf32.f32 %0, %1;" : "=r"(r) : "f"(f));
    return r;
}

__device__ __forceinline__ void mma_tf32(float* c, const uint32_t* a, uint32_t b0, uint32_t b1) {
    asm volatile(
        "mma.sync.aligned.m16n8k8.row.col.f32.tf32.tf32.f32 "
        "{%0,%1,%2,%3}, {%4,%5,%6,%7}, {%8,%9}, {%0,%1,%2,%3};"
        : "+f"(c[0]), "+f"(c[1]), "+f"(c[2]), "+f"(c[3])
        : "r"(a[0]), "r"(a[1]), "r"(a[2]), "r"(a[3]), "r"(b0), "r"(b1));
}

// ---------------- conv weight transpose: w[oc][ic][tap] -> wT[ic][tap][oc] (tf32)
__global__ void wtrans_kernel(const float* __restrict__ w)
{
    int idx = blockIdx.x * 256 + threadIdx.x;   // total 512*9*512
    if (idx >= 512 * 9 * 512) return;
    int oc = idx & 511;
    int tap = (idx >> 9) % 9;
    int ic = idx / (9 * 512);
    g_wT[idx] = f2tf32(w[((long)oc * 512 + ic) * 9 + tap]);
}

// ---------------- generic strided batched SGEMM (fp32), 64x64 tile, TK=16 --------
template <int EPI>
__global__ __launch_bounds__(256)
void sgemm(const float* __restrict__ A, const float* __restrict__ B,
           float* __restrict__ C,
           int M, int N, int K,
           long aBat, long aSm, long aSk,
           long bBat, long bSk, long bSn,
           long cBat,
           const float* __restrict__ sv, const float* __restrict__ tv,
           const float* __restrict__ res, const float* __restrict__ gptr)
{
    __shared__ float As[16][65];
    __shared__ float Bs[16][65];
    int tid = threadIdx.x;
    int tx = tid & 15, ty = tid >> 4;
    int n0 = blockIdx.x * 64, m0 = blockIdx.y * 64;
    long ab = (long)blockIdx.z * aBat;
    long bb = (long)blockIdx.z * bBat;
    long cb = (long)blockIdx.z * cBat;

    float acc[4][4] = {};

    for (int k0 = 0; k0 < K; k0 += 16) {
        if (aSk == 1) {
            #pragma unroll
            for (int i = 0; i < 4; i++) {
                int idx = tid + i * 256;
                int k = idx & 15, m = idx >> 4;
                As[k][m] = A[ab + (long)(m0 + m) * aSm + (k0 + k)];
            }
        } else {
            #pragma unroll
            for (int i = 0; i < 4; i++) {
                int idx = tid + i * 256;
                int m = idx & 63, k = idx >> 6;
                As[k][m] = A[ab + (long)(m0 + m) * aSm + (long)(k0 + k) * aSk];
            }
        }
        if (bSn == 1) {
            #pragma unroll
            for (int i = 0; i < 4; i++) {
                int idx = tid + i * 256;
                int n = idx & 63, k = idx >> 6;
                Bs[k][n] = B[bb + (long)(k0 + k) * bSk + (n0 + n)];
            }
        } else {
            #pragma unroll
            for (int i = 0; i < 4; i++) {
                int idx = tid + i * 256;
                int k = idx & 15, n = idx >> 4;
                Bs[k][n] = B[bb + (long)(k0 + k) * bSk + (long)(n0 + n) * bSn];
            }
        }
        __syncthreads();
        #pragma unroll
        for (int k = 0; k < 16; k++) {
            float a[4], bv[4];
            #pragma unroll
            for (int i = 0; i < 4; i++) a[i] = As[k][ty + 16 * i];
            #pragma unroll
            for (int j = 0; j < 4; j++) bv[j] = Bs[k][tx + 16 * j];
            #pragma unroll
            for (int i = 0; i < 4; i++)
                #pragma unroll
                for (int j = 0; j < 4; j++)
                    acc[i][j] += a[i] * bv[j];
        }
        __syncthreads();
    }

    float gm = 0.f;
    if (EPI == 4) gm = gptr[0];
    #pragma unroll
    for (int i = 0; i < 4; i++) {
        int m = m0 + ty + 16 * i;
        #pragma unroll
        for (int j = 0; j < 4; j++) {
            int n = n0 + tx + 16 * j;
            float v = acc[i][j];
            if (EPI == 1) v += tv[m];
            else if (EPI == 2) v = fmaxf(sv[m] * v + tv[m], 0.f);
            else if (EPI == 3) v += tv[n];
            else if (EPI == 4) v = gm * v + res[cb + (long)m * N + n];
            C[cb + (long)m * N + n] = v;
        }
    }
}

// ---------------- softmax of (rowmax - E) == softmax over (-E), rows of 128 ------
__global__ void softmax_neg(const float* __restrict__ E, float* __restrict__ A)
{
    int row = blockIdx.x;
    int t = threadIdx.x;
    __shared__ float red[128];
    float v = E[(long)row * 128 + t];
    red[t] = v;
    __syncthreads();
    for (int s = 64; s > 0; s >>= 1) {
        if (t < s) red[t] = fminf(red[t], red[t + s]);
        __syncthreads();
    }
    float mn = red[0];
    __syncthreads();
    float ex = expf(mn - v);
    red[t] = ex;
    __syncthreads();
    for (int s = 64; s > 0; s >>= 1) {
        if (t < s) red[t] += red[t + s];
        __syncthreads();
    }
    A[(long)row * 128 + t] = ex / red[0];
}

// ---------------- 3x3 conv via implicit GEMM, tf32 mma.sync ---------------------
// Block: 256 thr = 8 warps (warpM 0..3, warpN 0..1).
// Block tile: 128 oc x (2 rows x 64 cols). Warp tile: 32 oc x 64 px = 2x8 m16n8k8.
// K loop: 8 input channels per stage x 9 taps.
__global__ __launch_bounds__(256, 2)
void conv3x3_tc_kernel(const float* __restrict__ in, float* __restrict__ out)
{
    __shared__ uint32_t sW[8][9][136];   // [ic][tap][oc], padded: bank-free frags
    __shared__ uint32_t sIn[8][4][67];   // [ic][y (y0-1..y0+2)][x (-1..65)]

    int tid = threadIdx.x;
    int lane = tid & 31;
    int warp = tid >> 5;
    int warpM = warp >> 1;          // 0..3 -> oc quarter
    int warpN = warp & 1;           // 0..1 -> output row within pair
    int grp = lane >> 2;            // 0..7
    int tig = lane & 3;             // 0..3

    int b   = blockIdx.z;
    int oc0 = blockIdx.y * 128;
    int y0  = blockIdx.x * 2;

    const long inB = (long)b * 512 * 4096;

    float acc[2][8][4] = {};

    for (int ic0 = 0; ic0 < 512; ic0 += 8) {
        __syncthreads();
        // weights: wT[ic0+ic][tap][oc0+oc], contiguous in oc -> coalesced
        for (int idx = tid; idx < 8 * 9 * 128; idx += 256) {
            int ic  = idx >> 10;          // /1152 -> careful: 9*128=1152 not pow2
            ic = idx / 1152;
            int r   = idx - ic * 1152;
            int tap = r >> 7;
            int oc  = r & 127;
            sW[ic][tap][oc] = g_wT[((long)(ic0 + ic) * 9 + tap) * 512 + oc0 + oc];
        }
        // inputs: 8 ic x 4 rows x 66 cols (x index 0..65 == gx -1..64)
        for (int idx = tid; idx < 8 * 4 * 66; idx += 256) {
            int ic = idx / 264;
            int r  = idx - ic * 264;
            int y  = r / 66;
            int x  = r - y * 66;
            int gy = y0 - 1 + y;
            int gx = x - 1;
            float v = 0.f;
            if (gy >= 0 && gy < 64 && gx >= 0 && gx < 64)
                v = in[inB + (long)(ic0 + ic) * 4096 + gy * 64 + gx];
            sIn[ic][y][x] = f2tf32(v);
        }
        __syncthreads();

        #pragma unroll
        for (int ky = 0; ky < 3; ky++) {
            #pragma unroll
            for (int kx = 0; kx < 3; kx++) {
                const int tap = ky * 3 + kx;
                uint32_t a[2][4];
                #pragma unroll
                for (int i = 0; i < 2; i++) {
                    int oc = warpM * 32 + i * 16 + grp;
                    a[i][0] = sW[tig][tap][oc];
                    a[i][1] = sW[tig][tap][oc + 8];
                    a[i][2] = sW[tig + 4][tap][oc];
                    a[i][3] = sW[tig + 4][tap][oc + 8];
                }
                #pragma unroll
                for (int j = 0; j < 8; j++) {
                    int xi = j * 8 + grp + kx;
                    uint32_t b0 = sIn[tig][warpN + ky][xi];
                    uint32_t b1 = sIn[tig + 4][warpN + ky][xi];
                    mma_tf32(acc[0][j], a[0], b0, b1);
                    mma_tf32(acc[1][j], a[1], b0, b1);
                }
            }
        }
    }

    // epilogue: BN+ReLU, write NCHW
    int y = y0 + warpN;
    #pragma unroll
    for (int i = 0; i < 2; i++) {
        int row = oc0 + warpM * 32 + i * 16 + grp;
        float s0 = g_s3[row],     t0 = g_t3[row];
        float s8 = g_s3[row + 8], t8 = g_t3[row + 8];
        long base0 = ((long)b * 512 + row) * 4096 + (long)y * 64;
        long base8 = base0 + 8L * 4096;
        #pragma unroll
        for (int j = 0; j < 8; j++) {
            int x = j * 8 + tig * 2;
            out[base0 + x    ] = fmaxf(s0 * acc[i][j][0] + t0, 0.f);
            out[base0 + x + 1] = fmaxf(s0 * acc[i][j][1] + t0, 0.f);
            out[base8 + x    ] = fmaxf(s8 * acc[i][j][2] + t8, 0.f);
            out[base8 + x + 1] = fmaxf(s8 * acc[i][j][3] + t8, 0.f);
        }
    }
}

// ------------------------------- launcher ---------------------------------------
extern "C" void kernel_launch(void* const* d_in, const int* in_sizes, int n_in,
                              void* d_out, int out_size)
{
    const float* x     = (const float*)d_in[0];
    const float* q1_w  = (const float*)d_in[1];
    const float* q1_b  = (const float*)d_in[2];
    const float* bn1_g = (const float*)d_in[3];
    const float* bn1_b = (const float*)d_in[4];
    const float* bn1_m = (const float*)d_in[5];
    const float* bn1_v = (const float*)d_in[6];
    const float* q2_w  = (const float*)d_in[7];
    const float* q2_b  = (const float*)d_in[8];
    const float* bn2_g = (const float*)d_in[9];
    const float* bn2_b = (const float*)d_in[10];
    const float* bn2_m = (const float*)d_in[11];
    const float* bn2_v = (const float*)d_in[12];
    const float* p1_w  = (const float*)d_in[13];
    const float* p1_b  = (const float*)d_in[14];
    const float* fus_w = (const float*)d_in[15];
    const float* fus_b = (const float*)d_in[16];
    const float* bn3_g = (const float*)d_in[17];
    const float* bn3_b = (const float*)d_in[18];
    const float* bn3_m = (const float*)d_in[19];
    const float* bn3_v = (const float*)d_in[20];
    const float* gamma = (const float*)d_in[21];

    float *py1, *py2, *e1, *e1t, *e2, *e2p, *eng, *att, *opr, *s1, *t1, *s2, *t2;
    cudaGetSymbolAddress((void**)&py1, g_py1);
    cudaGetSymbolAddress((void**)&py2, g_py2);
    cudaGetSymbolAddress((void**)&e1,  g_e1);
    cudaGetSymbolAddress((void**)&e1t, g_e1t);
    cudaGetSymbolAddress((void**)&e2,  g_e2);
    cudaGetSymbolAddress((void**)&e2p, g_e2p);
    cudaGetSymbolAddress((void**)&eng, g_eng);
    cudaGetSymbolAddress((void**)&att, g_att);
    cudaGetSymbolAddress((void**)&opr, g_opr);
    cudaGetSymbolAddress((void**)&s1,  g_s1);
    cudaGetSymbolAddress((void**)&t1,  g_t1);
    cudaGetSymbolAddress((void**)&s2,  g_s2);
    cudaGetSymbolAddress((void**)&t2,  g_t2);

    fold_kernel<<<1, 512>>>(q1_b, bn1_g, bn1_b, bn1_m, bn1_v,
                            q2_b, bn2_g, bn2_b, bn2_m, bn2_v,
                            fus_b, bn3_g, bn3_b, bn3_m, bn3_v);

    wtrans_kernel<<<(512 * 9 * 512 + 255) / 256, 256>>>(fus_w);

    // 1) py1 = relu(bn1(q1_w @ x))  [16, 256, 4096]
    sgemm<2><<<dim3(64, 4, 16), 256>>>(q1_w, x, py1, 256, 4096, 512,
        0L, 512L, 1L,  512L * 4096, 4096L, 1L,  256L * 4096,
        s1, t1, nullptr, nullptr);

    // 2) py2 = relu(bn2(q2_w @ py1))  [16, 128, 4096]
    sgemm<2><<<dim3(64, 2, 16), 256>>>(q2_w, py1, py2, 128, 4096, 256,
        0L, 256L, 1L,  256L * 4096, 4096L, 1L,  128L * 4096,
        s2, t2, nullptr, nullptr);

    // 3) e1[c,d] = sum_n py1[c,n] * x[d,n]  [16, 256, 512]
    sgemm<0><<<dim3(8, 4, 16), 256>>>(py1, x, e1, 256, 512, 4096,
        256L * 4096, 4096L, 1L,  512L * 4096, 1L, 4096L,  256L * 512,
        nullptr, nullptr, nullptr, nullptr);

    // 4) e1t[d,o] = sum_c e1[c,d] * p1_w[o,c] + p1_b[o]  [16, 512, 256]
    sgemm<3><<<dim3(4, 8, 16), 256>>>(e1, p1_w, e1t, 512, 256, 256,
        256L * 512, 1L, 512L,  0L, 1L, 256L,  512L * 256,
        nullptr, p1_b, nullptr, nullptr);

    // 5) e2[d,c] = sum_n py1[d,n] * py2[c,n]  [16, 256, 128]
    sgemm<0><<<dim3(2, 4, 16), 256>>>(py1, py2, e2, 256, 128, 4096,
        256L * 4096, 4096L, 1L,  128L * 4096, 1L, 4096L,  256L * 128,
        nullptr, nullptr, nullptr, nullptr);

    // 6) e2p[o,c] = sum_d p1_w[o,d] * e2[d,c] + p1_b[o]  [16, 256, 128]
    sgemm<1><<<dim3(2, 4, 16), 256>>>(p1_w, e2, e2p, 256, 128, 256,
        0L, 256L, 1L,  256L * 128, 128L, 1L,  256L * 128,
        nullptr, p1_b, nullptr, nullptr);

    // 7) energy = e1t @ e2p  [16, 512, 128]
    sgemm<0><<<dim3(2, 8, 16), 256>>>(e1t, e2p, eng, 512, 128, 256,
        512L * 256, 256L, 1L,  256L * 128, 128L, 1L,  512L * 128,
        nullptr, nullptr, nullptr, nullptr);

    // 8) attention = softmax(rowmax - energy)
    softmax_neg<<<16 * 512, 128>>>(eng, att);

    // 9) opr = gamma * (attention @ py2) + x  [16, 512, 4096]
    sgemm<4><<<dim3(64, 8, 16), 256>>>(att, py2, opr, 512, 4096, 128,
        512L * 128, 128L, 1L,  128L * 4096, 4096L, 1L,  512L * 4096,
        nullptr, nullptr, x, gamma);

    // 10) out = relu(bn3(conv3x3(opr) + fus_b))   — tf32 tensor-core implicit GEMM
    conv3x3_tc_kernel<<<dim3(32, 4, 16), 256>>>(opr, (float*)d_out);
}

// round 3
// speedup vs baseline: 2.8608x; 1.2380x over previous
#include <cuda_runtime.h>
#include <math.h>
#include <stdint.h>

#define EPS 1e-5f

// ---------------- scratch (device globals; no allocation allowed) ----------------
__device__ float g_py1[16L * 256 * 4096];
__device__ float g_py2[16L * 128 * 4096];
__device__ float g_e1 [16L * 256 * 512];
__device__ float g_e1t[16L * 512 * 256];
__device__ float g_e2 [16L * 256 * 128];
__device__ float g_e2p[16L * 256 * 128];
__device__ float g_eng[16L * 512 * 128];
__device__ float g_att[16L * 512 * 128];
__device__ float g_opr[16L * 512 * 4096];
__device__ uint32_t g_wT[512L * 9 * 512];   // conv weights [ic][tap][oc], tf32

__device__ float g_s1[256], g_t1[256];
__device__ float g_s2[128], g_t2[128];
__device__ float g_s3[512], g_t3[512];

// ---------------- fold BN (+conv bias) into per-channel scale/shift --------------
__global__ void fold_kernel(const float* __restrict__ q1b, const float* __restrict__ g1,
                            const float* __restrict__ b1,  const float* __restrict__ m1,
                            const float* __restrict__ v1,
                            const float* __restrict__ q2b, const float* __restrict__ g2,
                            const float* __restrict__ b2,  const float* __restrict__ m2,
                            const float* __restrict__ v2,
                            const float* __restrict__ fb,  const float* __restrict__ g3,
                            const float* __restrict__ b3,  const float* __restrict__ m3,
                            const float* __restrict__ v3)
{
    int i = threadIdx.x;
    if (i < 256) {
        float s = g1[i] * rsqrtf(v1[i] + EPS);
        g_s1[i] = s;
        g_t1[i] = s * q1b[i] + b1[i] - m1[i] * s;
    }
    if (i < 128) {
        float s = g2[i] * rsqrtf(v2[i] + EPS);
        g_s2[i] = s;
        g_t2[i] = s * q2b[i] + b2[i] - m2[i] * s;
    }
    if (i < 512) {
        float s = g3[i] * rsqrtf(v3[i] + EPS);
        g_s3[i] = s;
        g_t3[i] = s * fb[i] + b3[i] - m3[i] * s;
    }
}

// ---------------- tf32 helpers ---------------------------------------------------
__device__ __forceinline__ uint32_t f2tf32(float f) {
    uint32_t r;
    asm("cvt.rna.tf32.f32 %0, %1;" : "=r"(r) : "f"(f));
    return r;
}

__device__ __forceinline__ void split_tf32(float f, uint32_t& hi, uint32_t& lo) {
    asm("cvt.rna.tf32.f32 %0, %1;" : "=r"(hi) : "f"(f));
    float r = f - __uint_as_float(hi);
    asm("cvt.rna.tf32.f32 %0, %1;" : "=r"(lo) : "f"(r));
}

__device__ __forceinline__ void mma_tf32(float* c, const uint32_t* a, uint32_t b0, uint32_t b1) {
    asm volatile(
        "mma.sync.aligned.m16n8k8.row.col.f32.tf32.tf32.f32 "
        "{%0,%1,%2,%3}, {%4,%5,%6,%7}, {%8,%9}, {%0,%1,%2,%3};"
        : "+f"(c[0]), "+f"(c[1]), "+f"(c[2]), "+f"(c[3])
        : "r"(a[0]), "r"(a[1]), "r"(a[2]), "r"(a[3]), "r"(b0), "r"(b1));
}

// ---------------- conv weight transpose: w[oc][ic][tap] -> wT[ic][tap][oc] (tf32)
__global__ void wtrans_kernel(const float* __restrict__ w)
{
    int idx = blockIdx.x * 256 + threadIdx.x;
    if (idx >= 512 * 9 * 512) return;
    int oc = idx & 511;
    int tap = (idx >> 9) % 9;
    int ic = idx / (9 * 512);
    g_wT[idx] = f2tf32(w[((long)oc * 512 + ic) * 9 + tap]);
}

// ====================== tf32x3 tensor-core GEMM ==================================
// C[b,m,n] = sum_k A[m,k] * B[.,.] with ~fp32 precision (3-term tf32 split).
// A: [m][k], k-contiguous, row stride aSm.
// BKC=true : B is [n][k], k-contiguous, row stride bS (i.e. C = A @ B^T).
// BKC=false: B is [k][n], n-contiguous, row stride bS (i.e. C = A @ B).
// Block: 128(M) x 64(N), K chunk 32, 8 warps (warpM 0..3 x warpN 0..1),
// warp tile 32x32 = 2 x 4 m16n8k8.
// EPI: 0 none | 2 relu(sv[m]*v+tv[m]) | 4 gamma*v + res
template <int EPI, bool BKC>
__global__ __launch_bounds__(256)
void tgemm(const float* __restrict__ A, const float* __restrict__ B,
           float* __restrict__ C, int N, int K,
           long aBat, long aSm, long bBat, long bS, long cBat,
           const float* __restrict__ sv, const float* __restrict__ tv,
           const float* __restrict__ res, const float* __restrict__ gptr)
{
    __shared__ float As[128][36];
    __shared__ float Bs[64][36];

    int tid = threadIdx.x;
    int lane = tid & 31, warp = tid >> 5;
    int warpM = warp >> 1, warpN = warp & 1;
    int grp = lane >> 2, tig = lane & 3;
    int n0 = blockIdx.x * 64, m0 = blockIdx.y * 128;
    long ab = (long)blockIdx.z * aBat + (long)m0 * aSm;
    long bb = (long)blockIdx.z * bBat;
    long cb = (long)blockIdx.z * cBat;

    float acc[2][4][4] = {};

    int kq = tid & 7;        // k quad (x4)
    int mrow = tid >> 3;     // 0..31

    for (int k0 = 0; k0 < K; k0 += 32) {
        __syncthreads();
        // A: 128 x 32, float4 along k
        #pragma unroll
        for (int i = 0; i < 4; i++) {
            int m = mrow + 32 * i;
            float4 v = *(const float4*)&A[ab + (long)m * aSm + k0 + 4 * kq];
            *(float4*)&As[m][4 * kq] = v;
        }
        if (BKC) {
            #pragma unroll
            for (int i = 0; i < 2; i++) {
                int n = mrow + 32 * i;
                float4 v = *(const float4*)&B[bb + (long)(n0 + n) * bS + k0 + 4 * kq];
                *(float4*)&Bs[n][4 * kq] = v;
            }
        } else {
            int nq = tid & 15, kk = tid >> 4;
            #pragma unroll
            for (int i = 0; i < 2; i++) {
                int k = kk + 16 * i;
                float4 v = *(const float4*)&B[bb + (long)(k0 + k) * bS + n0 + 4 * nq];
                Bs[4 * nq + 0][k] = v.x;
                Bs[4 * nq + 1][k] = v.y;
                Bs[4 * nq + 2][k] = v.z;
                Bs[4 * nq + 3][k] = v.w;
            }
        }
        __syncthreads();

        #pragma unroll
        for (int s = 0; s < 4; s++) {
            int k = s * 8 + tig;
            uint32_t ahi[2][4], alo[2][4];
            #pragma unroll
            for (int mt = 0; mt < 2; mt++) {
                int m = warpM * 32 + mt * 16 + grp;
                split_tf32(As[m    ][k    ], ahi[mt][0], alo[mt][0]);
                split_tf32(As[m + 8][k    ], ahi[mt][1], alo[mt][1]);
                split_tf32(As[m    ][k + 4], ahi[mt][2], alo[mt][2]);
                split_tf32(As[m + 8][k + 4], ahi[mt][3], alo[mt][3]);
            }
            uint32_t bhi[4][2], blo[4][2];
            #pragma unroll
            for (int nt = 0; nt < 4; nt++) {
                int n = warpN * 32 + nt * 8 + grp;
                split_tf32(Bs[n][k    ], bhi[nt][0], blo[nt][0]);
                split_tf32(Bs[n][k + 4], bhi[nt][1], blo[nt][1]);
            }
            #pragma unroll
            for (int mt = 0; mt < 2; mt++)
                #pragma unroll
                for (int nt = 0; nt < 4; nt++) {
                    mma_tf32(acc[mt][nt], ahi[mt], blo[nt][0], blo[nt][1]);
                    mma_tf32(acc[mt][nt], alo[mt], bhi[nt][0], bhi[nt][1]);
                    mma_tf32(acc[mt][nt], ahi[mt], bhi[nt][0], bhi[nt][1]);
                }
        }
    }

    float gm = (EPI == 4) ? gptr[0] : 0.f;
    #pragma unroll
    for (int mt = 0; mt < 2; mt++) {
        #pragma unroll
        for (int h = 0; h < 2; h++) {
            int m = m0 + warpM * 32 + mt * 16 + grp + h * 8;
            float s = 0.f, t = 0.f;
            if (EPI == 2) { s = sv[m]; t = tv[m]; }
            #pragma unroll
            for (int nt = 0; nt < 4; nt++) {
                int n = n0 + warpN * 32 + nt * 8 + tig * 2;
                float v0 = acc[mt][nt][2 * h];
                float v1 = acc[mt][nt][2 * h + 1];
                if (EPI == 2) {
                    v0 = fmaxf(s * v0 + t, 0.f);
                    v1 = fmaxf(s * v1 + t, 0.f);
                } else if (EPI == 4) {
                    v0 = gm * v0 + res[cb + (long)m * N + n];
                    v1 = gm * v1 + res[cb + (long)m * N + n + 1];
                }
                C[cb + (long)m * N + n] = v0;
                C[cb + (long)m * N + n + 1] = v1;
            }
        }
    }
}

// ---------------- generic strided batched SGEMM (fp32) — small stages only -------
template <int EPI>
__global__ __launch_bounds__(256)
void sgemm(const float* __restrict__ A, const float* __restrict__ B,
           float* __restrict__ C,
           int M, int N, int K,
           long aBat, long aSm, long aSk,
           long bBat, long bSk, long bSn,
           long cBat,
           const float* __restrict__ sv, const float* __restrict__ tv)
{
    __shared__ float As[16][65];
    __shared__ float Bs[16][65];
    int tid = threadIdx.x;
    int tx = tid & 15, ty = tid >> 4;
    int n0 = blockIdx.x * 64, m0 = blockIdx.y * 64;
    long ab = (long)blockIdx.z * aBat;
    long bb = (long)blockIdx.z * bBat;
    long cb = (long)blockIdx.z * cBat;

    float acc[4][4] = {};

    for (int k0 = 0; k0 < K; k0 += 16) {
        if (aSk == 1) {
            #pragma unroll
            for (int i = 0; i < 4; i++) {
                int idx = tid + i * 256;
                int k = idx & 15, m = idx >> 4;
                As[k][m] = A[ab + (long)(m0 + m) * aSm + (k0 + k)];
            }
        } else {
            #pragma unroll
            for (int i = 0; i < 4; i++) {
                int idx = tid + i * 256;
                int m = idx & 63, k = idx >> 6;
                As[k][m] = A[ab + (long)(m0 + m) * aSm + (long)(k0 + k) * aSk];
            }
        }
        if (bSn == 1) {
            #pragma unroll
            for (int i = 0; i < 4; i++) {
                int idx = tid + i * 256;
                int n = idx & 63, k = idx >> 6;
                Bs[k][n] = B[bb + (long)(k0 + k) * bSk + (n0 + n)];
            }
        } else {
            #pragma unroll
            for (int i = 0; i < 4; i++) {
                int idx = tid + i * 256;
                int k = idx & 15, n = idx >> 4;
                Bs[k][n] = B[bb + (long)(k0 + k) * bSk + (long)(n0 + n) * bSn];
            }
        }
        __syncthreads();
        #pragma unroll
        for (int k = 0; k < 16; k++) {
            float a[4], bv[4];
            #pragma unroll
            for (int i = 0; i < 4; i++) a[i] = As[k][ty + 16 * i];
            #pragma unroll
            for (int j = 0; j < 4; j++) bv[j] = Bs[k][tx + 16 * j];
            #pragma unroll
            for (int i = 0; i < 4; i++)
                #pragma unroll
                for (int j = 0; j < 4; j++)
                    acc[i][j] += a[i] * bv[j];
        }
        __syncthreads();
    }

    #pragma unroll
    for (int i = 0; i < 4; i++) {
        int m = m0 + ty + 16 * i;
        #pragma unroll
        for (int j = 0; j < 4; j++) {
            int n = n0 + tx + 16 * j;
            float v = acc[i][j];
            if (EPI == 1) v += tv[m];
            else if (EPI == 3) v += tv[n];
            C[cb + (long)m * N + n] = v;
        }
    }
}

// ---------------- softmax of (rowmax - E) == softmax over (-E), rows of 128 ------
__global__ void softmax_neg(const float* __restrict__ E, float* __restrict__ A)
{
    int row = blockIdx.x;
    int t = threadIdx.x;
    __shared__ float red[128];
    float v = E[(long)row * 128 + t];
    red[t] = v;
    __syncthreads();
    for (int s = 64; s > 0; s >>= 1) {
        if (t < s) red[t] = fminf(red[t], red[t + s]);
        __syncthreads();
    }
    float mn = red[0];
    __syncthreads();
    float ex = expf(mn - v);
    red[t] = ex;
    __syncthreads();
    for (int s = 64; s > 0; s >>= 1) {
        if (t < s) red[t] += red[t + s];
        __syncthreads();
    }
    A[(long)row * 128 + t] = ex / red[0];
}

// ---------------- 3x3 conv via implicit GEMM, tf32 mma.sync ---------------------
// Block: 512 thr = 16 warps (warpM 0..3 -> oc quarter, warpN 0..3 -> row).
// Block tile: 128 oc x (4 rows x 64 cols). Warp tile: 32 oc x 64 px = 2x8 m16n8k8.
// Dynamic smem: sW[8][9][136] u32 + sIn[8][6][68] u32 = 52224 B.
#define CONV_SMEM (8 * 9 * 136 * 4 + 8 * 6 * 68 * 4)
__global__ __launch_bounds__(512, 1)
void conv3x3_tc_kernel(const float* __restrict__ in, float* __restrict__ out)
{
    extern __shared__ uint32_t smem[];
    uint32_t* sW  = smem;                   // [ic][tap][oc]: (ic*9+tap)*136+oc
    uint32_t* sIn = smem + 8 * 9 * 136;     // [ic][y][x]: (ic*6+y)*68+x

    int tid = threadIdx.x;
    int lane = tid & 31;
    int warp = tid >> 5;
    int warpM = warp >> 2;          // 0..3 oc quarter
    int warpN = warp & 3;           // 0..3 row
    int grp = lane >> 2;
    int tig = lane & 3;

    int b   = blockIdx.z;
    int oc0 = blockIdx.y * 128;
    int y0  = blockIdx.x * 4;

    const long inB = (long)b * 512 * 4096;

    float acc[2][8][4] = {};

    for (int ic0 = 0; ic0 < 512; ic0 += 8) {
        __syncthreads();
        for (int idx = tid; idx < 8 * 9 * 128; idx += 512) {
            int ic  = idx / 1152;
            int r   = idx - ic * 1152;
            int tap = r >> 7;
            int oc  = r & 127;
            sW[(ic * 9 + tap) * 136 + oc] =
                g_wT[((long)(ic0 + ic) * 9 + tap) * 512 + oc0 + oc];
        }
        // inputs: 8 ic x 6 rows x 66 cols (x index 0..65 == gx -1..64)
        for (int idx = tid; idx < 8 * 6 * 66; idx += 512) {
            int ic = idx / 396;
            int r  = idx - ic * 396;
            int y  = r / 66;
            int x  = r - y * 66;
            int gy = y0 - 1 + y;
            int gx = x - 1;
            float v = 0.f;
            if (gy >= 0 && gy < 64 && gx >= 0 && gx < 64)
                v = in[inB + (long)(ic0 + ic) * 4096 + gy * 64 + gx];
            sIn[(ic * 6 + y) * 68 + x] = f2tf32(v);
        }
        __syncthreads();

        #pragma unroll
        for (int ky = 0; ky < 3; ky++) {
            #pragma unroll
            for (int kx = 0; kx < 3; kx++) {
                const int tap = ky * 3 + kx;
                uint32_t a[2][4];
                #pragma unroll
                for (int i = 0; i < 2; i++) {
                    int oc = warpM * 32 + i * 16 + grp;
                    a[i][0] = sW[(tig * 9 + tap) * 136 + oc];
                    a[i][1] = sW[(tig * 9 + tap) * 136 + oc + 8];
                    a[i][2] = sW[((tig + 4) * 9 + tap) * 136 + oc];
                    a[i][3] = sW[((tig + 4) * 9 + tap) * 136 + oc + 8];
                }
                #pragma unroll
                for (int j = 0; j < 8; j++) {
                    int xi = j * 8 + grp + kx;
                    uint32_t b0 = sIn[(tig * 6 + warpN + ky) * 68 + xi];
                    uint32_t b1 = sIn[((tig + 4) * 6 + warpN + ky) * 68 + xi];
                    mma_tf32(acc[0][j], a[0], b0, b1);
                    mma_tf32(acc[1][j], a[1], b0, b1);
                }
            }
        }
    }

    int y = y0 + warpN;
    #pragma unroll
    for (int i = 0; i < 2; i++) {
        int row = oc0 + warpM * 32 + i * 16 + grp;
        float s0 = g_s3[row],     t0 = g_t3[row];
        float s8 = g_s3[row + 8], t8 = g_t3[row + 8];
        long base0 = ((long)b * 512 + row) * 4096 + (long)y * 64;
        long base8 = base0 + 8L * 4096;
        #pragma unroll
        for (int j = 0; j < 8; j++) {
            int x = j * 8 + tig * 2;
            out[base0 + x    ] = fmaxf(s0 * acc[i][j][0] + t0, 0.f);
            out[base0 + x + 1] = fmaxf(s0 * acc[i][j][1] + t0, 0.f);
            out[base8 + x    ] = fmaxf(s8 * acc[i][j][2] + t8, 0.f);
            out[base8 + x + 1] = fmaxf(s8 * acc[i][j][3] + t8, 0.f);
        }
    }
}

// ------------------------------- launcher ---------------------------------------
extern "C" void kernel_launch(void* const* d_in, const int* in_sizes, int n_in,
                              void* d_out, int out_size)
{
    const float* x     = (const float*)d_in[0];
    const float* q1_w  = (const float*)d_in[1];
    const float* q1_b  = (const float*)d_in[2];
    const float* bn1_g = (const float*)d_in[3];
    const float* bn1_b = (const float*)d_in[4];
    const float* bn1_m = (const float*)d_in[5];
    const float* bn1_v = (const float*)d_in[6];
    const float* q2_w  = (const float*)d_in[7];
    const float* q2_b  = (const float*)d_in[8];
    const float* bn2_g = (const float*)d_in[9];
    const float* bn2_b = (const float*)d_in[10];
    const float* bn2_m = (const float*)d_in[11];
    const float* bn2_v = (const float*)d_in[12];
    const float* p1_w  = (const float*)d_in[13];
    const float* p1_b  = (const float*)d_in[14];
    const float* fus_w = (const float*)d_in[15];
    const float* bn3_g = (const float*)d_in[17];
    const float* bn3_b = (const float*)d_in[18];
    const float* bn3_m = (const float*)d_in[19];
    const float* bn3_v = (const float*)d_in[20];
    const float* fus_b = (const float*)d_in[16];
    const float* gamma = (const float*)d_in[21];

    float *py1, *py2, *e1, *e1t, *e2, *e2p, *eng, *att, *opr, *s1, *t1, *s2, *t2;
    cudaGetSymbolAddress((void**)&py1, g_py1);
    cudaGetSymbolAddress((void**)&py2, g_py2);
    cudaGetSymbolAddress((void**)&e1,  g_e1);
    cudaGetSymbolAddress((void**)&e1t, g_e1t);
    cudaGetSymbolAddress((void**)&e2,  g_e2);
    cudaGetSymbolAddress((void**)&e2p, g_e2p);
    cudaGetSymbolAddress((void**)&eng, g_eng);
    cudaGetSymbolAddress((void**)&att, g_att);
    cudaGetSymbolAddress((void**)&opr, g_opr);
    cudaGetSymbolAddress((void**)&s1,  g_s1);
    cudaGetSymbolAddress((void**)&t1,  g_t1);
    cudaGetSymbolAddress((void**)&s2,  g_s2);
    cudaGetSymbolAddress((void**)&t2,  g_t2);

    static bool attr_set = false;
    if (!attr_set) {
        cudaFuncSetAttribute(conv3x3_tc_kernel,
                             cudaFuncAttributeMaxDynamicSharedMemorySize, CONV_SMEM);
        attr_set = true;
    }

    fold_kernel<<<1, 512>>>(q1_b, bn1_g, bn1_b, bn1_m, bn1_v,
                            q2_b, bn2_g, bn2_b, bn2_m, bn2_v,
                            fus_b, bn3_g, bn3_b, bn3_m, bn3_v);

    wtrans_kernel<<<(512 * 9 * 512 + 255) / 256, 256>>>(fus_w);

    // 1) py1 = relu(bn1(q1_w @ x))  [16, 256, 4096]   (B n-contig)
    tgemm<2, false><<<dim3(64, 2, 16), 256>>>(q1_w, x, py1, 4096, 512,
        0L, 512L,  512L * 4096, 4096L,  256L * 4096, s1, t1, nullptr, nullptr);

    // 2) py2 = relu(bn2(q2_w @ py1))  [16, 128, 4096]
    tgemm<2, false><<<dim3(64, 1, 16), 256>>>(q2_w, py1, py2, 4096, 256,
        0L, 256L,  256L * 4096, 4096L,  128L * 4096, s2, t2, nullptr, nullptr);

    // 3) e1[c,d] = py1 @ x^T  [16, 256, 512]   (both k-contig)
    tgemm<0, true><<<dim3(8, 2, 16), 256>>>(py1, x, e1, 512, 4096,
        256L * 4096, 4096L,  512L * 4096, 4096L,  256L * 512,
        nullptr, nullptr, nullptr, nullptr);

    // 4) e1t[d,o] = e1^T @ p1_w^T + p1_b[o]  [16, 512, 256]  (fp32)
    sgemm<3><<<dim3(4, 8, 16), 256>>>(e1, p1_w, e1t, 512, 256, 256,
        256L * 512, 1L, 512L,  0L, 1L, 256L,  512L * 256, nullptr, p1_b);

    // 5) e2[d,c] = py1 @ py2^T  [16, 256, 128]
    tgemm<0, true><<<dim3(2, 2, 16), 256>>>(py1, py2, e2, 128, 4096,
        256L * 4096, 4096L,  128L * 4096, 4096L,  256L * 128,
        nullptr, nullptr, nullptr, nullptr);

    // 6) e2p[o,c] = p1_w @ e2 + p1_b[o]  [16, 256, 128]  (fp32)
    sgemm<1><<<dim3(2, 4, 16), 256>>>(p1_w, e2, e2p, 256, 128, 256,
        0L, 256L, 1L,  256L * 128, 128L, 1L,  256L * 128, nullptr, p1_b);

    // 7) energy = e1t @ e2p  [16, 512, 128]  (fp32)
    sgemm<0><<<dim3(2, 8, 16), 256>>>(e1t, e2p, eng, 512, 128, 256,
        512L * 256, 256L, 1L,  256L * 128, 128L, 1L,  512L * 128, nullptr, nullptr);

    // 8) attention = softmax(rowmax - energy)
    softmax_neg<<<16 * 512, 128>>>(eng, att);

    // 9) opr = gamma * (attention @ py2) + x  [16, 512, 4096]
    tgemm<4, false><<<dim3(64, 4, 16), 256>>>(att, py2, opr, 4096, 128,
        512L * 128, 128L,  128L * 4096, 4096L,  512L * 4096,
        nullptr, nullptr, x, gamma);

    // 10) out = relu(bn3(conv3x3(opr)))  — tf32 tensor-core implicit GEMM
    conv3x3_tc_kernel<<<dim3(16, 4, 16), 512, CONV_SMEM>>>(opr, (float*)d_out);
}

// round 4
// speedup vs baseline: 4.4123x; 1.5423x over previous
#include <cuda_runtime.h>
#include <math.h>
#include <stdint.h>

#define EPS 1e-5f

// ---------------- scratch (device globals; no allocation allowed) ----------------
__device__ float g_py1[16L * 256 * 4096];
__device__ float g_py2[16L * 128 * 4096];
__device__ float g_e1 [16L * 256 * 512];
__device__ float g_e1t[16L * 512 * 256];
__device__ float g_e2 [16L * 256 * 128];
__device__ float g_e2p[16L * 256 * 128];
__device__ float g_eng[16L * 512 * 128];
__device__ float g_att[16L * 512 * 128];
__device__ float g_opr[16L * 512 * 4096];   // conv input (tf32-rounded at producer)
__device__ uint32_t g_wT[512L * 9 * 512];   // conv weights [ic][tap][oc], tf32

__device__ float g_s1[256], g_t1[256];
__device__ float g_s2[128], g_t2[128];
__device__ float g_s3[512], g_t3[512];

// ---------------- fold BN (+conv bias) into per-channel scale/shift --------------
__global__ void fold_kernel(const float* __restrict__ q1b, const float* __restrict__ g1,
                            const float* __restrict__ b1,  const float* __restrict__ m1,
                            const float* __restrict__ v1,
                            const float* __restrict__ q2b, const float* __restrict__ g2,
                            const float* __restrict__ b2,  const float* __restrict__ m2,
                            const float* __restrict__ v2,
                            const float* __restrict__ fb,  const float* __restrict__ g3,
                            const float* __restrict__ b3,  const float* __restrict__ m3,
                            const float* __restrict__ v3)
{
    int i = threadIdx.x;
    if (i < 256) {
        float s = g1[i] * rsqrtf(v1[i] + EPS);
        g_s1[i] = s;
        g_t1[i] = s * q1b[i] + b1[i] - m1[i] * s;
    }
    if (i < 128) {
        float s = g2[i] * rsqrtf(v2[i] + EPS);
        g_s2[i] = s;
        g_t2[i] = s * q2b[i] + b2[i] - m2[i] * s;
    }
    if (i < 512) {
        float s = g3[i] * rsqrtf(v3[i] + EPS);
        g_s3[i] = s;
        g_t3[i] = s * fb[i] + b3[i] - m3[i] * s;
    }
}

// ---------------- tf32 helpers ---------------------------------------------------
__device__ __forceinline__ uint32_t f2tf32(float f) {
    uint32_t r;
    asm("cvt.rna.tf32.f32 %0, %1;" : "=r"(r) : "f"(f));
    return r;
}

__device__ __forceinline__ void split_tf32(float f, uint32_t& hi, uint32_t& lo) {
    asm("cvt.rna.tf32.f32 %0, %1;" : "=r"(hi) : "f"(f));
    float r = f - __uint_as_float(hi);
    asm("cvt.rna.tf32.f32 %0, %1;" : "=r"(lo) : "f"(r));
}

__device__ __forceinline__ void mma_tf32(float* c, const uint32_t* a, uint32_t b0, uint32_t b1) {
    asm volatile(
        "mma.sync.aligned.m16n8k8.row.col.f32.tf32.tf32.f32 "
        "{%0,%1,%2,%3}, {%4,%5,%6,%7}, {%8,%9}, {%0,%1,%2,%3};"
        : "+f"(c[0]), "+f"(c[1]), "+f"(c[2]), "+f"(c[3])
        : "r"(a[0]), "r"(a[1]), "r"(a[2]), "r"(a[3]), "r"(b0), "r"(b1));
}

__device__ __forceinline__ void cp16(uint32_t dst, const void* src) {
    asm volatile("cp.async.cg.shared.global [%0], [%1], 16;" :: "r"(dst), "l"(src));
}

// ---------------- conv weight transpose: w[oc][ic][tap] -> wT[ic][tap][oc] (tf32)
__global__ void wtrans_kernel(const float* __restrict__ w)
{
    int idx = blockIdx.x * 256 + threadIdx.x;
    if (idx >= 512 * 9 * 512) return;
    int oc = idx & 511;
    int tap = (idx >> 9) % 9;
    int ic = idx / (9 * 512);
    g_wT[idx] = f2tf32(w[((long)oc * 512 + ic) * 9 + tap]);
}

// ====================== tf32x3 tensor-core GEMM (hoisted splits) =================
// C[b,m,n] = A @ B(^T), ~fp32 precision via 3-term tf32 split done at smem load.
// A: [m][k] k-contig, row stride aSm.
// BKC=true : B [n][k] k-contig (C = A @ B^T). BKC=false: B [k][n] n-contig.
// Block 128(M) x 64(N), K chunk 32, 8 warps, warp tile 32x32 = 2x4 m16n8k8.
// Dynamic smem: Ah/Al[128*36] + Bh/Bl[64*36] u32 = 55296 B.
#define TG_SMEM ((128 * 36 * 2 + 64 * 36 * 2) * 4)
// EPI: 0 none | 2 relu(sv[m]*v+tv[m]) | 4 tf32round(gamma*v + res)
template <int EPI, bool BKC>
__global__ __launch_bounds__(256)
void tgemm(const float* __restrict__ A, const float* __restrict__ B,
           float* __restrict__ C, int N, int K,
           long aBat, long aSm, long bBat, long bS, long cBat,
           const float* __restrict__ sv, const float* __restrict__ tv,
           const float* __restrict__ res, const float* __restrict__ gptr)
{
    extern __shared__ uint32_t dsm[];
    uint32_t* Ah = dsm;
    uint32_t* Al = Ah + 128 * 36;
    uint32_t* Bh = Al + 128 * 36;
    uint32_t* Bl = Bh + 64 * 36;

    int tid = threadIdx.x;
    int lane = tid & 31, warp = tid >> 5;
    int warpM = warp >> 1, warpN = warp & 1;
    int grp = lane >> 2, tig = lane & 3;
    int n0 = blockIdx.x * 64, m0 = blockIdx.y * 128;
    long ab = (long)blockIdx.z * aBat + (long)m0 * aSm;
    long bb = (long)blockIdx.z * bBat;
    long cb = (long)blockIdx.z * cBat;

    float acc[2][4][4] = {};

    int kq = tid & 7;        // k quad (x4)
    int mrow = tid >> 3;     // 0..31

    for (int k0 = 0; k0 < K; k0 += 32) {
        __syncthreads();
        #pragma unroll
        for (int i = 0; i < 4; i++) {
            int m = mrow + 32 * i;
            float4 v = *(const float4*)&A[ab + (long)m * aSm + k0 + 4 * kq];
            uint32_t h0, l0, h1, l1, h2, l2, h3, l3;
            split_tf32(v.x, h0, l0); split_tf32(v.y, h1, l1);
            split_tf32(v.z, h2, l2); split_tf32(v.w, h3, l3);
            *(uint4*)&Ah[m * 36 + 4 * kq] = make_uint4(h0, h1, h2, h3);
            *(uint4*)&Al[m * 36 + 4 * kq] = make_uint4(l0, l1, l2, l3);
        }
        if (BKC) {
            #pragma unroll
            for (int i = 0; i < 2; i++) {
                int n = mrow + 32 * i;
                float4 v = *(const float4*)&B[bb + (long)(n0 + n) * bS + k0 + 4 * kq];
                uint32_t h0, l0, h1, l1, h2, l2, h3, l3;
                split_tf32(v.x, h0, l0); split_tf32(v.y, h1, l1);
                split_tf32(v.z, h2, l2); split_tf32(v.w, h3, l3);
                *(uint4*)&Bh[n * 36 + 4 * kq] = make_uint4(h0, h1, h2, h3);
                *(uint4*)&Bl[n * 36 + 4 * kq] = make_uint4(l0, l1, l2, l3);
            }
        } else {
            int nq = tid & 15, kk = tid >> 4;
            #pragma unroll
            for (int i = 0; i < 2; i++) {
                int k = kk + 16 * i;
                float4 v = *(const float4*)&B[bb + (long)(k0 + k) * bS + n0 + 4 * nq];
                uint32_t h, l;
                split_tf32(v.x, h, l); Bh[(4 * nq + 0) * 36 + k] = h; Bl[(4 * nq + 0) * 36 + k] = l;
                split_tf32(v.y, h, l); Bh[(4 * nq + 1) * 36 + k] = h; Bl[(4 * nq + 1) * 36 + k] = l;
                split_tf32(v.z, h, l); Bh[(4 * nq + 2) * 36 + k] = h; Bl[(4 * nq + 2) * 36 + k] = l;
                split_tf32(v.w, h, l); Bh[(4 * nq + 3) * 36 + k] = h; Bl[(4 * nq + 3) * 36 + k] = l;
            }
        }
        __syncthreads();

        #pragma unroll
        for (int s = 0; s < 4; s++) {
            int k = s * 8 + tig;
            uint32_t ahi[2][4], alo[2][4];
            #pragma unroll
            for (int mt = 0; mt < 2; mt++) {
                int m = warpM * 32 + mt * 16 + grp;
                ahi[mt][0] = Ah[m * 36 + k];       alo[mt][0] = Al[m * 36 + k];
                ahi[mt][1] = Ah[(m + 8) * 36 + k]; alo[mt][1] = Al[(m + 8) * 36 + k];
                ahi[mt][2] = Ah[m * 36 + k + 4];   alo[mt][2] = Al[m * 36 + k + 4];
                ahi[mt][3] = Ah[(m + 8) * 36 + k + 4]; alo[mt][3] = Al[(m + 8) * 36 + k + 4];
            }
            uint32_t bhi[4][2], blo[4][2];
            #pragma unroll
            for (int nt = 0; nt < 4; nt++) {
                int n = warpN * 32 + nt * 8 + grp;
                bhi[nt][0] = Bh[n * 36 + k];     blo[nt][0] = Bl[n * 36 + k];
                bhi[nt][1] = Bh[n * 36 + k + 4]; blo[nt][1] = Bl[n * 36 + k + 4];
            }
            #pragma unroll
            for (int mt = 0; mt < 2; mt++)
                #pragma unroll
                for (int nt = 0; nt < 4; nt++) {
                    mma_tf32(acc[mt][nt], ahi[mt], blo[nt][0], blo[nt][1]);
                    mma_tf32(acc[mt][nt], alo[mt], bhi[nt][0], bhi[nt][1]);
                    mma_tf32(acc[mt][nt], ahi[mt], bhi[nt][0], bhi[nt][1]);
                }
        }
    }

    float gm = (EPI == 4) ? gptr[0] : 0.f;
    #pragma unroll
    for (int mt = 0; mt < 2; mt++) {
        #pragma unroll
        for (int h = 0; h < 2; h++) {
            int m = m0 + warpM * 32 + mt * 16 + grp + h * 8;
            float s = 0.f, t = 0.f;
            if (EPI == 2) { s = sv[m]; t = tv[m]; }
            #pragma unroll
            for (int nt = 0; nt < 4; nt++) {
                int n = n0 + warpN * 32 + nt * 8 + tig * 2;
                float v0 = acc[mt][nt][2 * h];
                float v1 = acc[mt][nt][2 * h + 1];
                if (EPI == 2) {
                    v0 = fmaxf(s * v0 + t, 0.f);
                    v1 = fmaxf(s * v1 + t, 0.f);
                } else if (EPI == 4) {
                    v0 = gm * v0 + res[cb + (long)m * N + n];
                    v1 = gm * v1 + res[cb + (long)m * N + n + 1];
                    v0 = __uint_as_float(f2tf32(v0));   // conv input: pre-round to tf32
                    v1 = __uint_as_float(f2tf32(v1));
                }
                C[cb + (long)m * N + n] = v0;
                C[cb + (long)m * N + n + 1] = v1;
            }
        }
    }
}

// ---------------- generic strided batched SGEMM (fp32) — small stages only -------
template <int EPI>
__global__ __launch_bounds__(256)
void sgemm(const float* __restrict__ A, const float* __restrict__ B,
           float* __restrict__ C,
           int M, int N, int K,
           long aBat, long aSm, long aSk,
           long bBat, long bSk, long bSn,
           long cBat,
           const float* __restrict__ sv, const float* __restrict__ tv)
{
    __shared__ float As[16][65];
    __shared__ float Bs[16][65];
    int tid = threadIdx.x;
    int tx = tid & 15, ty = tid >> 4;
    int n0 = blockIdx.x * 64, m0 = blockIdx.y * 64;
    long ab = (long)blockIdx.z * aBat;
    long bb = (long)blockIdx.z * bBat;
    long cb = (long)blockIdx.z * cBat;

    float acc[4][4] = {};

    for (int k0 = 0; k0 < K; k0 += 16) {
        if (aSk == 1) {
            #pragma unroll
            for (int i = 0; i < 4; i++) {
                int idx = tid + i * 256;
                int k = idx & 15, m = idx >> 4;
                As[k][m] = A[ab + (long)(m0 + m) * aSm + (k0 + k)];
            }
        } else {
            #pragma unroll
            for (int i = 0; i < 4; i++) {
                int idx = tid + i * 256;
                int m = idx & 63, k = idx >> 6;
                As[k][m] = A[ab + (long)(m0 + m) * aSm + (long)(k0 + k) * aSk];
            }
        }
        if (bSn == 1) {
            #pragma unroll
            for (int i = 0; i < 4; i++) {
                int idx = tid + i * 256;
                int n = idx & 63, k = idx >> 6;
                Bs[k][n] = B[bb + (long)(k0 + k) * bSk + (n0 + n)];
            }
        } else {
            #pragma unroll
            for (int i = 0; i < 4; i++) {
                int idx = tid + i * 256;
                int k = idx & 15, n = idx >> 4;
                Bs[k][n] = B[bb + (long)(k0 + k) * bSk + (long)(n0 + n) * bSn];
            }
        }
        __syncthreads();
        #pragma unroll
        for (int k = 0; k < 16; k++) {
            float a[4], bv[4];
            #pragma unroll
            for (int i = 0; i < 4; i++) a[i] = As[k][ty + 16 * i];
            #pragma unroll
            for (int j = 0; j < 4; j++) bv[j] = Bs[k][tx + 16 * j];
            #pragma unroll
            for (int i = 0; i < 4; i++)
                #pragma unroll
                for (int j = 0; j < 4; j++)
                    acc[i][j] += a[i] * bv[j];
        }
        __syncthreads();
    }

    #pragma unroll
    for (int i = 0; i < 4; i++) {
        int m = m0 + ty + 16 * i;
        #pragma unroll
        for (int j = 0; j < 4; j++) {
            int n = n0 + tx + 16 * j;
            float v = acc[i][j];
            if (EPI == 1) v += tv[m];
            else if (EPI == 3) v += tv[n];
            C[cb + (long)m * N + n] = v;
        }
    }
}

// ---------------- softmax of (rowmax - E) == softmax over (-E), rows of 128 ------
__global__ void softmax_neg(const float* __restrict__ E, float* __restrict__ A)
{
    int row = blockIdx.x;
    int t = threadIdx.x;
    __shared__ float red[128];
    float v = E[(long)row * 128 + t];
    red[t] = v;
    __syncthreads();
    for (int s = 64; s > 0; s >>= 1) {
        if (t < s) red[t] = fminf(red[t], red[t + s]);
        __syncthreads();
    }
    float mn = red[0];
    __syncthreads();
    float ex = expf(mn - v);
    red[t] = ex;
    __syncthreads();
    for (int s = 64; s > 0; s >>= 1) {
        if (t < s) red[t] += red[t + s];
        __syncthreads();
    }
    A[(long)row * 128 + t] = ex / red[0];
}

// ---------------- 3x3 conv, tf32 mma.sync, cp.async double-buffered --------------
// Block: 512 thr = 16 warps (warpM 0..3 oc quarter, warpN 0..3 row).
// Block tile: 128 oc x (4 rows x 64 cols). Warp tile: 32 oc x 64 px = 2x8 m16n8k8.
// sW stage: [ic(8)][tap(9)] x 136-stride oc row.  sIn stage: [ic(8)][y(6)] x 76-stride,
// interior gx 0..63 at word offset 4 (16B-aligned for cp.async), halos at 3 / 68.
#define SW_WORDS  (8 * 9 * 136)     // 9792
#define SIN_WORDS (8 * 6 * 76)      // 3648
#define CONV_SMEM ((2 * SW_WORDS + 2 * SIN_WORDS) * 4)

__device__ __forceinline__ void conv_issue(int ic0, uint32_t swb, uint32_t sinb,
                                           const float* __restrict__ in, long inB,
                                           int y0, int oc0, int tid)
{
    // weights: 72 rows (ic*9+tap) x 32 chunks of 16B
    for (int idx = tid; idx < 2304; idx += 512) {
        int row = idx >> 5;
        int ch  = idx & 31;
        int ic = row / 9, tap = row - ic * 9;
        cp16(swb + (uint32_t)(row * 136 + ch * 4) * 4,
             &g_wT[((long)(ic0 + ic) * 9 + tap) * 512 + oc0 + ch * 4]);
    }
    // inputs: 48 rows (ic*6+y) x 16 chunks of 16B (interior only)
    for (int idx = tid; idx < 768; idx += 512) {
        int r  = idx >> 4;
        int ch = idx & 15;
        int ic = r / 6, y = r - ic * 6;
        int gy = y0 - 1 + y;
        if (gy >= 0 && gy < 64)
            cp16(sinb + (uint32_t)(r * 76 + 4 + ch * 4) * 4,
                 &in[inB + (long)(ic0 + ic) * 4096 + gy * 64 + ch * 4]);
    }
}

__global__ __launch_bounds__(512, 1)
void conv3x3_tc_kernel(const float* __restrict__ in, float* __restrict__ out)
{
    extern __shared__ uint32_t smem[];
    uint32_t* sW  = smem;                     // 2 stages
    uint32_t* sIn = smem + 2 * SW_WORDS;      // 2 stages
    uint32_t sw_base  = (uint32_t)__cvta_generic_to_shared(sW);
    uint32_t sin_base = (uint32_t)__cvta_generic_to_shared(sIn);

    int tid = threadIdx.x;
    int lane = tid & 31;
    int warp = tid >> 5;
    int warpM = warp >> 2;
    int warpN = warp & 3;
    int grp = lane >> 2;
    int tig = lane & 3;

    int b   = blockIdx.z;
    int oc0 = blockIdx.y * 128;
    int y0  = blockIdx.x * 4;

    const long inB = (long)b * 512 * 4096;

    // zero both sIn buffers (halos + invalid rows persist as zero; cp.async only
    // ever writes valid interiors)
    for (int i = tid; i < 2 * SIN_WORDS; i += 512) sIn[i] = 0;
    __syncthreads();

    conv_issue(0, sw_base, sin_base, in, inB, y0, oc0, tid);
    asm volatile("cp.async.commit_group;");

    float acc[2][8][4] = {};

    for (int it = 0; it < 64; it++) {
        int buf = it & 1;
        if (it < 63) {
            int nb = (it + 1) & 1;
            conv_issue((it + 1) * 8, sw_base + nb * SW_WORDS * 4,
                       sin_base + nb * SIN_WORDS * 4, in, inB, y0, oc0, tid);
            asm volatile("cp.async.commit_group;");
            asm volatile("cp.async.wait_group 1;");
        } else {
            asm volatile("cp.async.wait_group 0;");
        }
        __syncthreads();

        const uint32_t* sWb  = sW + buf * SW_WORDS;
        const uint32_t* sInb = sIn + buf * SIN_WORDS;

        #pragma unroll
        for (int ky = 0; ky < 3; ky++) {
            #pragma unroll
            for (int kx = 0; kx < 3; kx++) {
                const int tap = ky * 3 + kx;
                uint32_t a[2][4];
                #pragma unroll
                for (int i = 0; i < 2; i++) {
                    int oc = warpM * 32 + i * 16 + grp;
                    a[i][0] = sWb[(tig * 9 + tap) * 136 + oc];
                    a[i][1] = sWb[(tig * 9 + tap) * 136 + oc + 8];
                    a[i][2] = sWb[((tig + 4) * 9 + tap) * 136 + oc];
                    a[i][3] = sWb[((tig + 4) * 9 + tap) * 136 + oc + 8];
                }
                #pragma unroll
                for (int j = 0; j < 8; j++) {
                    int xi = 3 + j * 8 + grp + kx;
                    uint32_t b0 = sInb[(tig * 6 + warpN + ky) * 76 + xi];
                    uint32_t b1 = sInb[((tig + 4) * 6 + warpN + ky) * 76 + xi];
                    mma_tf32(acc[0][j], a[0], b0, b1);
                    mma_tf32(acc[1][j], a[1], b0, b1);
                }
            }
        }
        __syncthreads();
    }

    int y = y0 + warpN;
    #pragma unroll
    for (int i = 0; i < 2; i++) {
        int row = oc0 + warpM * 32 + i * 16 + grp;
        float s0 = g_s3[row],     t0 = g_t3[row];
        float s8 = g_s3[row + 8], t8 = g_t3[row + 8];
        long base0 = ((long)b * 512 + row) * 4096 + (long)y * 64;
        long base8 = base0 + 8L * 4096;
        #pragma unroll
        for (int j = 0; j < 8; j++) {
            int x = j * 8 + tig * 2;
            out[base0 + x    ] = fmaxf(s0 * acc[i][j][0] + t0, 0.f);
            out[base0 + x + 1] = fmaxf(s0 * acc[i][j][1] + t0, 0.f);
            out[base8 + x    ] = fmaxf(s8 * acc[i][j][2] + t8, 0.f);
            out[base8 + x + 1] = fmaxf(s8 * acc[i][j][3] + t8, 0.f);
        }
    }
}

// ------------------------------- launcher ---------------------------------------
extern "C" void kernel_launch(void* const* d_in, const int* in_sizes, int n_in,
                              void* d_out, int out_size)
{
    const float* x     = (const float*)d_in[0];
    const float* q1_w  = (const float*)d_in[1];
    const float* q1_b  = (const float*)d_in[2];
    const float* bn1_g = (const float*)d_in[3];
    const float* bn1_b = (const float*)d_in[4];
    const float* bn1_m = (const float*)d_in[5];
    const float* bn1_v = (const float*)d_in[6];
    const float* q2_w  = (const float*)d_in[7];
    const float* q2_b  = (const float*)d_in[8];
    const float* bn2_g = (const float*)d_in[9];
    const float* bn2_b = (const float*)d_in[10];
    const float* bn2_m = (const float*)d_in[11];
    const float* bn2_v = (const float*)d_in[12];
    const float* p1_w  = (const float*)d_in[13];
    const float* p1_b  = (const float*)d_in[14];
    const float* fus_w = (const float*)d_in[15];
    const float* fus_b = (const float*)d_in[16];
    const float* bn3_g = (const float*)d_in[17];
    const float* bn3_b = (const float*)d_in[18];
    const float* bn3_m = (const float*)d_in[19];
    const float* bn3_v = (const float*)d_in[20];
    const float* gamma = (const float*)d_in[21];

    float *py1, *py2, *e1, *e1t, *e2, *e2p, *eng, *att, *opr, *s1, *t1, *s2, *t2;
    cudaGetSymbolAddress((void**)&py1, g_py1);
    cudaGetSymbolAddress((void**)&py2, g_py2);
    cudaGetSymbolAddress((void**)&e1,  g_e1);
    cudaGetSymbolAddress((void**)&e1t, g_e1t);
    cudaGetSymbolAddress((void**)&e2,  g_e2);
    cudaGetSymbolAddress((void**)&e2p, g_e2p);
    cudaGetSymbolAddress((void**)&eng, g_eng);
    cudaGetSymbolAddress((void**)&att, g_att);
    cudaGetSymbolAddress((void**)&opr, g_opr);
    cudaGetSymbolAddress((void**)&s1,  g_s1);
    cudaGetSymbolAddress((void**)&t1,  g_t1);
    cudaGetSymbolAddress((void**)&s2,  g_s2);
    cudaGetSymbolAddress((void**)&t2,  g_t2);

    static bool attr_set = false;
    if (!attr_set) {
        cudaFuncSetAttribute(conv3x3_tc_kernel,
                             cudaFuncAttributeMaxDynamicSharedMemorySize, CONV_SMEM);
        cudaFuncSetAttribute(tgemm<2, false>,
                             cudaFuncAttributeMaxDynamicSharedMemorySize, TG_SMEM);
        cudaFuncSetAttribute(tgemm<0, true>,
                             cudaFuncAttributeMaxDynamicSharedMemorySize, TG_SMEM);
        cudaFuncSetAttribute(tgemm<4, false>,
                             cudaFuncAttributeMaxDynamicSharedMemorySize, TG_SMEM);
        attr_set = true;
    }

    fold_kernel<<<1, 512>>>(q1_b, bn1_g, bn1_b, bn1_m, bn1_v,
                            q2_b, bn2_g, bn2_b, bn2_m, bn2_v,
                            fus_b, bn3_g, bn3_b, bn3_m, bn3_v);

    wtrans_kernel<<<(512 * 9 * 512 + 255) / 256, 256>>>(fus_w);

    // 1) py1 = relu(bn1(q1_w @ x))  [16, 256, 4096]
    tgemm<2, false><<<dim3(64, 2, 16), 256, TG_SMEM>>>(q1_w, x, py1, 4096, 512,
        0L, 512L,  512L * 4096, 4096L,  256L * 4096, s1, t1, nullptr, nullptr);

    // 2) py2 = relu(bn2(q2_w @ py1))  [16, 128, 4096]
    tgemm<2, false><<<dim3(64, 1, 16), 256, TG_SMEM>>>(q2_w, py1, py2, 4096, 256,
        0L, 256L,  256L * 4096, 4096L,  128L * 4096, s2, t2, nullptr, nullptr);

    // 3) e1[c,d] = py1 @ x^T  [16, 256, 512]
    tgemm<0, true><<<dim3(8, 2, 16), 256, TG_SMEM>>>(py1, x, e1, 512, 4096,
        256L * 4096, 4096L,  512L * 4096, 4096L,  256L * 512,
        nullptr, nullptr, nullptr, nullptr);

    // 4) e1t[d,o] = e1^T @ p1_w^T + p1_b[o]  [16, 512, 256]  (fp32)
    sgemm<3><<<dim3(4, 8, 16), 256>>>(e1, p1_w, e1t, 512, 256, 256,
        256L * 512, 1L, 512L,  0L, 1L, 256L,  512L * 256, nullptr, p1_b);

    // 5) e2[d,c] = py1 @ py2^T  [16, 256, 128]
    tgemm<0, true><<<dim3(2, 2, 16), 256, TG_SMEM>>>(py1, py2, e2, 128, 4096,
        256L * 4096, 4096L,  128L * 4096, 4096L,  256L * 128,
        nullptr, nullptr, nullptr, nullptr);

    // 6) e2p[o,c] = p1_w @ e2 + p1_b[o]  [16, 256, 128]  (fp32)
    sgemm<1><<<dim3(2, 4, 16), 256>>>(p1_w, e2, e2p, 256, 128, 256,
        0L, 256L, 1L,  256L * 128, 128L, 1L,  256L * 128, nullptr, p1_b);

    // 7) energy = e1t @ e2p  [16, 512, 128]  (fp32)
    sgemm<0><<<dim3(2, 8, 16), 256>>>(e1t, e2p, eng, 512, 128, 256,
        512L * 256, 256L, 1L,  256L * 128, 128L, 1L,  512L * 128, nullptr, nullptr);

    // 8) attention = softmax(rowmax - energy)
    softmax_neg<<<16 * 512, 128>>>(eng, att);

    // 9) opr = tf32round(gamma * (attention @ py2) + x)  [16, 512, 4096]
    tgemm<4, false><<<dim3(64, 4, 16), 256, TG_SMEM>>>(att, py2, opr, 4096, 128,
        512L * 128, 128L,  128L * 4096, 4096L,  512L * 4096,
        nullptr, nullptr, x, gamma);

    // 10) out = relu(bn3(conv3x3(opr)))  — double-buffered tf32 implicit GEMM
    conv3x3_tc_kernel<<<dim3(16, 4, 16), 512, CONV_SMEM>>>(opr, (float*)d_out);
}

// round 5
// speedup vs baseline: 4.6838x; 1.0615x over previous
#include <cuda_runtime.h>
#include <math.h>
#include <stdint.h>

#define EPS 1e-5f

// ---------------- scratch (device globals; no allocation allowed) ----------------
__device__ float g_py1[16L * 256 * 4096];
__device__ float g_py2[16L * 128 * 4096];
__device__ float g_e1 [16L * 256 * 512];
__device__ float g_e1t[16L * 512 * 256];
__device__ float g_e2 [16L * 256 * 128];
__device__ float g_e2p[16L * 256 * 128];
__device__ float g_eng[16L * 512 * 128];
__device__ float g_att[16L * 512 * 128];
__device__ float g_opr[16L * 512 * 4096];   // conv input (tf32-rounded at producer)
__device__ uint32_t g_wT[512L * 9 * 512];   // conv weights [ic][tap][oc], tf32

__device__ float g_s1[256], g_t1[256];
__device__ float g_s2[128], g_t2[128];
__device__ float g_s3[512], g_t3[512];

// ---------------- fold BN (+conv bias) into per-channel scale/shift --------------
__global__ void fold_kernel(const float* __restrict__ q1b, const float* __restrict__ g1,
                            const float* __restrict__ b1,  const float* __restrict__ m1,
                            const float* __restrict__ v1,
                            const float* __restrict__ q2b, const float* __restrict__ g2,
                            const float* __restrict__ b2,  const float* __restrict__ m2,
                            const float* __restrict__ v2,
                            const float* __restrict__ fb,  const float* __restrict__ g3,
                            const float* __restrict__ b3,  const float* __restrict__ m3,
                            const float* __restrict__ v3)
{
    int i = threadIdx.x;
    if (i < 256) {
        float s = g1[i] * rsqrtf(v1[i] + EPS);
        g_s1[i] = s;
        g_t1[i] = s * q1b[i] + b1[i] - m1[i] * s;
    }
    if (i < 128) {
        float s = g2[i] * rsqrtf(v2[i] + EPS);
        g_s2[i] = s;
        g_t2[i] = s * q2b[i] + b2[i] - m2[i] * s;
    }
    if (i < 512) {
        float s = g3[i] * rsqrtf(v3[i] + EPS);
        g_s3[i] = s;
        g_t3[i] = s * fb[i] + b3[i] - m3[i] * s;
    }
}

// ---------------- tf32 helpers ---------------------------------------------------
__device__ __forceinline__ uint32_t f2tf32(float f) {
    uint32_t r;
    asm("cvt.rna.tf32.f32 %0, %1;" : "=r"(r) : "f"(f));
    return r;
}

__device__ __forceinline__ void split_tf32(float f, uint32_t& hi, uint32_t& lo) {
    asm("cvt.rna.tf32.f32 %0, %1;" : "=r"(hi) : "f"(f));
    float r = f - __uint_as_float(hi);
    asm("cvt.rna.tf32.f32 %0, %1;" : "=r"(lo) : "f"(r));
}

__device__ __forceinline__ void mma_tf32(float* c, const uint32_t* a, uint32_t b0, uint32_t b1) {
    asm volatile(
        "mma.sync.aligned.m16n8k8.row.col.f32.tf32.tf32.f32 "
        "{%0,%1,%2,%3}, {%4,%5,%6,%7}, {%8,%9}, {%0,%1,%2,%3};"
        : "+f"(c[0]), "+f"(c[1]), "+f"(c[2]), "+f"(c[3])
        : "r"(a[0]), "r"(a[1]), "r"(a[2]), "r"(a[3]), "r"(b0), "r"(b1));
}

__device__ __forceinline__ void cp16(uint32_t dst, const void* src) {
    asm volatile("cp.async.cg.shared.global [%0], [%1], 16;" :: "r"(dst), "l"(src));
}

// ---------------- conv weight transpose: w[oc][ic][tap] -> wT[ic][tap][oc] (tf32)
__global__ void wtrans_kernel(const float* __restrict__ w)
{
    int idx = blockIdx.x * 256 + threadIdx.x;
    if (idx >= 512 * 9 * 512) return;
    int oc = idx & 511;
    int tap = (idx >> 9) % 9;
    int ic = idx / (9 * 512);
    g_wT[idx] = f2tf32(w[((long)oc * 512 + ic) * 9 + tap]);
}

// ====================== tf32x3 tensor-core GEMM ==================================
// Block 128(M) x 128(N), K chunk 32, 8 warps (warpM 0..3, warpN 0..1),
// warp tile 32x64 = 2(m) x 8(n) m16n8k8.  Splits hoisted to smem-store time.
// A: [m][k] k-contig. BKC=true: B [n][k] k-contig (layout [n][36]).
// BKC=false: B [k][n] n-contig (layout k-major [k][136] — conflict-free both ways).
#define TG_SMEM ((128 * 36 * 2 + 4608 * 2) * 4)   // 73728 B
// EPI: 0 none | 2 relu(sv[m]*v+tv[m]) | 4 tf32round(gamma*v + res)
template <int EPI, bool BKC>
__global__ __launch_bounds__(256)
void tgemm(const float* __restrict__ A, const float* __restrict__ B,
           float* __restrict__ C, int N, int K,
           long aBat, long aSm, long bBat, long bS, long cBat,
           const float* __restrict__ sv, const float* __restrict__ tv,
           const float* __restrict__ res, const float* __restrict__ gptr)
{
    extern __shared__ uint32_t dsm[];
    uint32_t* Ah = dsm;                  // 128 x 36
    uint32_t* Al = Ah + 128 * 36;
    uint32_t* Bh = Al + 128 * 36;        // BKC: [n(128)][36]; !BKC: [k(32)][136]
    uint32_t* Bl = Bh + 4608;

    int tid = threadIdx.x;
    int lane = tid & 31, warp = tid >> 5;
    int warpM = warp >> 1, warpN = warp & 1;
    int grp = lane >> 2, tig = lane & 3;
    int n0 = blockIdx.x * 128, m0 = blockIdx.y * 128;
    long ab = (long)blockIdx.z * aBat + (long)m0 * aSm;
    long bb = (long)blockIdx.z * bBat;
    long cb = (long)blockIdx.z * cBat;

    float acc[2][8][4] = {};

    int kq = tid & 7;        // k quad (x4)
    int mrow = tid >> 3;     // 0..31

    for (int k0 = 0; k0 < K; k0 += 32) {
        __syncthreads();
        #pragma unroll
        for (int i = 0; i < 4; i++) {
            int m = mrow + 32 * i;
            float4 v = *(const float4*)&A[ab + (long)m * aSm + k0 + 4 * kq];
            uint32_t h0, l0, h1, l1, h2, l2, h3, l3;
            split_tf32(v.x, h0, l0); split_tf32(v.y, h1, l1);
            split_tf32(v.z, h2, l2); split_tf32(v.w, h3, l3);
            *(uint4*)&Ah[m * 36 + 4 * kq] = make_uint4(h0, h1, h2, h3);
            *(uint4*)&Al[m * 36 + 4 * kq] = make_uint4(l0, l1, l2, l3);
        }
        if (BKC) {
            #pragma unroll
            for (int i = 0; i < 4; i++) {
                int n = mrow + 32 * i;
                float4 v = *(const float4*)&B[bb + (long)(n0 + n) * bS + k0 + 4 * kq];
                uint32_t h0, l0, h1, l1, h2, l2, h3, l3;
                split_tf32(v.x, h0, l0); split_tf32(v.y, h1, l1);
                split_tf32(v.z, h2, l2); split_tf32(v.w, h3, l3);
                *(uint4*)&Bh[n * 36 + 4 * kq] = make_uint4(h0, h1, h2, h3);
                *(uint4*)&Bl[n * 36 + 4 * kq] = make_uint4(l0, l1, l2, l3);
            }
        } else {
            int nq = tid & 31, kk = tid >> 5;
            #pragma unroll
            for (int i = 0; i < 4; i++) {
                int k = kk + 8 * i;
                float4 v = *(const float4*)&B[bb + (long)(k0 + k) * bS + n0 + 4 * nq];
                uint32_t h0, l0, h1, l1, h2, l2, h3, l3;
                split_tf32(v.x, h0, l0); split_tf32(v.y, h1, l1);
                split_tf32(v.z, h2, l2); split_tf32(v.w, h3, l3);
                *(uint4*)&Bh[k * 136 + 4 * nq] = make_uint4(h0, h1, h2, h3);
                *(uint4*)&Bl[k * 136 + 4 * nq] = make_uint4(l0, l1, l2, l3);
            }
        }
        __syncthreads();

        #pragma unroll
        for (int s = 0; s < 4; s++) {
            int k = s * 8 + tig;
            uint32_t ahi[2][4], alo[2][4];
            #pragma unroll
            for (int mt = 0; mt < 2; mt++) {
                int m = warpM * 32 + mt * 16 + grp;
                ahi[mt][0] = Ah[m * 36 + k];           alo[mt][0] = Al[m * 36 + k];
                ahi[mt][1] = Ah[(m + 8) * 36 + k];     alo[mt][1] = Al[(m + 8) * 36 + k];
                ahi[mt][2] = Ah[m * 36 + k + 4];       alo[mt][2] = Al[m * 36 + k + 4];
                ahi[mt][3] = Ah[(m + 8) * 36 + k + 4]; alo[mt][3] = Al[(m + 8) * 36 + k + 4];
            }
            uint32_t bhi[8][2], blo[8][2];
            #pragma unroll
            for (int nt = 0; nt < 8; nt++) {
                int n = warpN * 64 + nt * 8 + grp;
                int i0 = BKC ? (n * 36 + k)     : (k * 136 + n);
                int i1 = BKC ? (n * 36 + k + 4) : ((k + 4) * 136 + n);
                bhi[nt][0] = Bh[i0]; blo[nt][0] = Bl[i0];
                bhi[nt][1] = Bh[i1]; blo[nt][1] = Bl[i1];
            }
            #pragma unroll
            for (int mt = 0; mt < 2; mt++)
                #pragma unroll
                for (int nt = 0; nt < 8; nt++) {
                    mma_tf32(acc[mt][nt], ahi[mt], blo[nt][0], blo[nt][1]);
                    mma_tf32(acc[mt][nt], alo[mt], bhi[nt][0], bhi[nt][1]);
                    mma_tf32(acc[mt][nt], ahi[mt], bhi[nt][0], bhi[nt][1]);
                }
        }
    }

    float gm = (EPI == 4) ? gptr[0] : 0.f;
    #pragma unroll
    for (int mt = 0; mt < 2; mt++) {
        #pragma unroll
        for (int h = 0; h < 2; h++) {
            int m = m0 + warpM * 32 + mt * 16 + grp + h * 8;
            float s = 0.f, t = 0.f;
            if (EPI == 2) { s = sv[m]; t = tv[m]; }
            #pragma unroll
            for (int nt = 0; nt < 8; nt++) {
                int n = n0 + warpN * 64 + nt * 8 + tig * 2;
                float v0 = acc[mt][nt][2 * h];
                float v1 = acc[mt][nt][2 * h + 1];
                if (EPI == 2) {
                    v0 = fmaxf(s * v0 + t, 0.f);
                    v1 = fmaxf(s * v1 + t, 0.f);
                } else if (EPI == 4) {
                    v0 = gm * v0 + res[cb + (long)m * N + n];
                    v1 = gm * v1 + res[cb + (long)m * N + n + 1];
                    v0 = __uint_as_float(f2tf32(v0));
                    v1 = __uint_as_float(f2tf32(v1));
                }
                C[cb + (long)m * N + n] = v0;
                C[cb + (long)m * N + n + 1] = v1;
            }
        }
    }
}

// ---------------- generic strided batched SGEMM (fp32) — small stages only -------
template <int EPI>
__global__ __launch_bounds__(256)
void sgemm(const float* __restrict__ A, const float* __restrict__ B,
           float* __restrict__ C,
           int M, int N, int K,
           long aBat, long aSm, long aSk,
           long bBat, long bSk, long bSn,
           long cBat,
           const float* __restrict__ sv, const float* __restrict__ tv)
{
    __shared__ float As[16][65];
    __shared__ float Bs[16][65];
    int tid = threadIdx.x;
    int tx = tid & 15, ty = tid >> 4;
    int n0 = blockIdx.x * 64, m0 = blockIdx.y * 64;
    long ab = (long)blockIdx.z * aBat;
    long bb = (long)blockIdx.z * bBat;
    long cb = (long)blockIdx.z * cBat;

    float acc[4][4] = {};

    for (int k0 = 0; k0 < K; k0 += 16) {
        if (aSk == 1) {
            #pragma unroll
            for (int i = 0; i < 4; i++) {
                int idx = tid + i * 256;
                int k = idx & 15, m = idx >> 4;
                As[k][m] = A[ab + (long)(m0 + m) * aSm + (k0 + k)];
            }
        } else {
            #pragma unroll
            for (int i = 0; i < 4; i++) {
                int idx = tid + i * 256;
                int m = idx & 63, k = idx >> 6;
                As[k][m] = A[ab + (long)(m0 + m) * aSm + (long)(k0 + k) * aSk];
            }
        }
        if (bSn == 1) {
            #pragma unroll
            for (int i = 0; i < 4; i++) {
                int idx = tid + i * 256;
                int n = idx & 63, k = idx >> 6;
                Bs[k][n] = B[bb + (long)(k0 + k) * bSk + (n0 + n)];
            }
        } else {
            #pragma unroll
            for (int i = 0; i < 4; i++) {
                int idx = tid + i * 256;
                int k = idx & 15, n = idx >> 4;
                Bs[k][n] = B[bb + (long)(k0 + k) * bSk + (long)(n0 + n) * bSn];
            }
        }
        __syncthreads();
        #pragma unroll
        for (int k = 0; k < 16; k++) {
            float a[4], bv[4];
            #pragma unroll
            for (int i = 0; i < 4; i++) a[i] = As[k][ty + 16 * i];
            #pragma unroll
            for (int j = 0; j < 4; j++) bv[j] = Bs[k][tx + 16 * j];
            #pragma unroll
            for (int i = 0; i < 4; i++)
                #pragma unroll
                for (int j = 0; j < 4; j++)
                    acc[i][j] += a[i] * bv[j];
        }
        __syncthreads();
    }

    #pragma unroll
    for (int i = 0; i < 4; i++) {
        int m = m0 + ty + 16 * i;
        #pragma unroll
        for (int j = 0; j < 4; j++) {
            int n = n0 + tx + 16 * j;
            float v = acc[i][j];
            if (EPI == 1) v += tv[m];
            else if (EPI == 3) v += tv[n];
            C[cb + (long)m * N + n] = v;
        }
    }
}

// ---------------- softmax of (rowmax - E) == softmax over (-E), rows of 128 ------
__global__ void softmax_neg(const float* __restrict__ E, float* __restrict__ A)
{
    int row = blockIdx.x;
    int t = threadIdx.x;
    __shared__ float red[128];
    float v = E[(long)row * 128 + t];
    red[t] = v;
    __syncthreads();
    for (int s = 64; s > 0; s >>= 1) {
        if (t < s) red[t] = fminf(red[t], red[t + s]);
        __syncthreads();
    }
    float mn = red[0];
    __syncthreads();
    float ex = expf(mn - v);
    red[t] = ex;
    __syncthreads();
    for (int s = 64; s > 0; s >>= 1) {
        if (t < s) red[t] += red[t + s];
        __syncthreads();
    }
    A[(long)row * 128 + t] = ex / red[0];
}

// ---------------- 3x3 conv, tf32 mma.sync, cp.async double-buffered --------------
// Block: 256 thr = 8 warps (warpM 0..1 -> 64 oc, warpN 0..3 -> row).
// Block tile: 128 oc x (4 rows x 64 cols). Warp: 64 oc x 64 px = 4x8 m16n8k8,
// so each b-fragment feeds 4 MMAs. ICB=16 (2 k-chunks of 8 ic) -> 32 stages.
#define SW_WORDS  (16 * 9 * 136)    // 19584
#define SIN_WORDS (16 * 6 * 76)     // 7296
#define CONV_SMEM ((2 * SW_WORDS + 2 * SIN_WORDS) * 4)   // 215040 B

__device__ __forceinline__ void conv_issue(int ic0, uint32_t swb, uint32_t sinb,
                                           const float* __restrict__ in, long inB,
                                           int y0, int oc0, int tid)
{
    // weights: 144 rows (ic*9+tap) x 32 chunks of 16B
    for (int idx = tid; idx < 4608; idx += 256) {
        int row = idx >> 5;
        int ch  = idx & 31;
        int ic = row / 9, tap = row - ic * 9;
        cp16(swb + (uint32_t)(row * 136 + ch * 4) * 4,
             &g_wT[((long)(ic0 + ic) * 9 + tap) * 512 + oc0 + ch * 4]);
    }
    // inputs: 96 rows (ic*6+y) x 16 chunks of 16B (interior only)
    for (int idx = tid; idx < 1536; idx += 256) {
        int r  = idx >> 4;
        int ch = idx & 15;
        int ic = r / 6, y = r - ic * 6;
        int gy = y0 - 1 + y;
        if (gy >= 0 && gy < 64)
            cp16(sinb + (uint32_t)(r * 76 + 4 + ch * 4) * 4,
                 &in[inB + (long)(ic0 + ic) * 4096 + gy * 64 + ch * 4]);
    }
}

__global__ __launch_bounds__(256, 1)
void conv3x3_tc_kernel(const float* __restrict__ in, float* __restrict__ out)
{
    extern __shared__ uint32_t smem[];
    uint32_t* sW  = smem;                     // 2 stages
    uint32_t* sIn = smem + 2 * SW_WORDS;      // 2 stages
    uint32_t sw_base  = (uint32_t)__cvta_generic_to_shared(sW);
    uint32_t sin_base = (uint32_t)__cvta_generic_to_shared(sIn);

    int tid = threadIdx.x;
    int lane = tid & 31;
    int warp = tid >> 5;
    int warpM = warp >> 2;          // 0..1 -> 64-oc half
    int warpN = warp & 3;           // 0..3 -> row
    int grp = lane >> 2;
    int tig = lane & 3;

    int b   = blockIdx.z;
    int oc0 = blockIdx.y * 128;
    int y0  = blockIdx.x * 4;

    const long inB = (long)b * 512 * 4096;

    // zero both sIn buffers once (halos + out-of-range rows stay zero forever;
    // cp.async only ever writes valid interiors)
    for (int i = tid; i < 2 * SIN_WORDS; i += 256) sIn[i] = 0;
    __syncthreads();

    conv_issue(0, sw_base, sin_base, in, inB, y0, oc0, tid);
    asm volatile("cp.async.commit_group;");

    float acc[4][8][4] = {};

    for (int it = 0; it < 32; it++) {
        int buf = it & 1;
        if (it < 31) {
            int nb = (it + 1) & 1;
            conv_issue((it + 1) * 16, sw_base + nb * SW_WORDS * 4,
                       sin_base + nb * SIN_WORDS * 4, in, inB, y0, oc0, tid);
            asm volatile("cp.async.commit_group;");
            asm volatile("cp.async.wait_group 1;");
        } else {
            asm volatile("cp.async.wait_group 0;");
        }
        __syncthreads();

        const uint32_t* sWb  = sW + buf * SW_WORDS;
        const uint32_t* sInb = sIn + buf * SIN_WORDS;

        #pragma unroll
        for (int kc = 0; kc < 2; kc++) {
            int icb = kc * 8;
            #pragma unroll
            for (int ky = 0; ky < 3; ky++) {
                #pragma unroll
                for (int kx = 0; kx < 3; kx++) {
                    const int tap = ky * 3 + kx;
                    const int wr0 = ((icb + tig) * 9 + tap) * 136;
                    const int wr4 = ((icb + tig + 4) * 9 + tap) * 136;
                    uint32_t a[4][4];
                    #pragma unroll
                    for (int mt = 0; mt < 4; mt++) {
                        int oc = warpM * 64 + mt * 16 + grp;
                        a[mt][0] = sWb[wr0 + oc];
                        a[mt][1] = sWb[wr0 + oc + 8];
                        a[mt][2] = sWb[wr4 + oc];
                        a[mt][3] = sWb[wr4 + oc + 8];
                    }
                    const int ir0 = ((icb + tig) * 6 + warpN + ky) * 76;
                    const int ir4 = ((icb + tig + 4) * 6 + warpN + ky) * 76;
                    #pragma unroll
                    for (int j = 0; j < 8; j++) {
                        int xi = 3 + j * 8 + grp + kx;
                        uint32_t b0 = sInb[ir0 + xi];
                        uint32_t b1 = sInb[ir4 + xi];
                        #pragma unroll
                        for (int mt = 0; mt < 4; mt++)
                            mma_tf32(acc[mt][j], a[mt], b0, b1);
                    }
                }
            }
        }
        __syncthreads();
    }

    int y = y0 + warpN;
    #pragma unroll
    for (int mt = 0; mt < 4; mt++) {
        int row = oc0 + warpM * 64 + mt * 16 + grp;
        float s0 = g_s3[row],     t0 = g_t3[row];
        float s8 = g_s3[row + 8], t8 = g_t3[row + 8];
        long base0 = ((long)b * 512 + row) * 4096 + (long)y * 64;
        long base8 = base0 + 8L * 4096;
        #pragma unroll
        for (int j = 0; j < 8; j++) {
            int x = j * 8 + tig * 2;
            out[base0 + x    ] = fmaxf(s0 * acc[mt][j][0] + t0, 0.f);
            out[base0 + x + 1] = fmaxf(s0 * acc[mt][j][1] + t0, 0.f);
            out[base8 + x    ] = fmaxf(s8 * acc[mt][j][2] + t8, 0.f);
            out[base8 + x + 1] = fmaxf(s8 * acc[mt][j][3] + t8, 0.f);
        }
    }
}

// ------------------------------- launcher ---------------------------------------
extern "C" void kernel_launch(void* const* d_in, const int* in_sizes, int n_in,
                              void* d_out, int out_size)
{
    const float* x     = (const float*)d_in[0];
    const float* q1_w  = (const float*)d_in[1];
    const float* q1_b  = (const float*)d_in[2];
    const float* bn1_g = (const float*)d_in[3];
    const float* bn1_b = (const float*)d_in[4];
    const float* bn1_m = (const float*)d_in[5];
    const float* bn1_v = (const float*)d_in[6];
    const float* q2_w  = (const float*)d_in[7];
    const float* q2_b  = (const float*)d_in[8];
    const float* bn2_g = (const float*)d_in[9];
    const float* bn2_b = (const float*)d_in[10];
    const float* bn2_m = (const float*)d_in[11];
    const float* bn2_v = (const float*)d_in[12];
    const float* p1_w  = (const float*)d_in[13];
    const float* p1_b  = (const float*)d_in[14];
    const float* fus_w = (const float*)d_in[15];
    const float* fus_b = (const float*)d_in[16];
    const float* bn3_g = (const float*)d_in[17];
    const float* bn3_b = (const float*)d_in[18];
    const float* bn3_m = (const float*)d_in[19];
    const float* bn3_v = (const float*)d_in[20];
    const float* gamma = (const float*)d_in[21];

    float *py1, *py2, *e1, *e1t, *e2, *e2p, *eng, *att, *opr, *s1, *t1, *s2, *t2;
    cudaGetSymbolAddress((void**)&py1, g_py1);
    cudaGetSymbolAddress((void**)&py2, g_py2);
    cudaGetSymbolAddress((void**)&e1,  g_e1);
    cudaGetSymbolAddress((void**)&e1t, g_e1t);
    cudaGetSymbolAddress((void**)&e2,  g_e2);
    cudaGetSymbolAddress((void**)&e2p, g_e2p);
    cudaGetSymbolAddress((void**)&eng, g_eng);
    cudaGetSymbolAddress((void**)&att, g_att);
    cudaGetSymbolAddress((void**)&opr, g_opr);
    cudaGetSymbolAddress((void**)&s1,  g_s1);
    cudaGetSymbolAddress((void**)&t1,  g_t1);
    cudaGetSymbolAddress((void**)&s2,  g_s2);
    cudaGetSymbolAddress((void**)&t2,  g_t2);

    static bool attr_set = false;
    if (!attr_set) {
        cudaFuncSetAttribute(conv3x3_tc_kernel,
                             cudaFuncAttributeMaxDynamicSharedMemorySize, CONV_SMEM);
        cudaFuncSetAttribute(tgemm<2, false>,
                             cudaFuncAttributeMaxDynamicSharedMemorySize, TG_SMEM);
        cudaFuncSetAttribute(tgemm<0, true>,
                             cudaFuncAttributeMaxDynamicSharedMemorySize, TG_SMEM);
        cudaFuncSetAttribute(tgemm<4, false>,
                             cudaFuncAttributeMaxDynamicSharedMemorySize, TG_SMEM);
        attr_set = true;
    }

    fold_kernel<<<1, 512>>>(q1_b, bn1_g, bn1_b, bn1_m, bn1_v,
                            q2_b, bn2_g, bn2_b, bn2_m, bn2_v,
                            fus_b, bn3_g, bn3_b, bn3_m, bn3_v);

    wtrans_kernel<<<(512 * 9 * 512 + 255) / 256, 256>>>(fus_w);

    // 1) py1 = relu(bn1(q1_w @ x))  [16, 256, 4096]
    tgemm<2, false><<<dim3(32, 2, 16), 256, TG_SMEM>>>(q1_w, x, py1, 4096, 512,
        0L, 512L,  512L * 4096, 4096L,  256L * 4096, s1, t1, nullptr, nullptr);

    // 2) py2 = relu(bn2(q2_w @ py1))  [16, 128, 4096]
    tgemm<2, false><<<dim3(32, 1, 16), 256, TG_SMEM>>>(q2_w, py1, py2, 4096, 256,
        0L, 256L,  256L * 4096, 4096L,  128L * 4096, s2, t2, nullptr, nullptr);

    // 3) e1[c,d] = py1 @ x^T  [16, 256, 512]
    tgemm<0, true><<<dim3(4, 2, 16), 256, TG_SMEM>>>(py1, x, e1, 512, 4096,
        256L * 4096, 4096L,  512L * 4096, 4096L,  256L * 512,
        nullptr, nullptr, nullptr, nullptr);

    // 4) e1t[d,o] = e1^T @ p1_w^T + p1_b[o]  [16, 512, 256]  (fp32)
    sgemm<3><<<dim3(4, 8, 16), 256>>>(e1, p1_w, e1t, 512, 256, 256,
        256L * 512, 1L, 512L,  0L, 1L, 256L,  512L * 256, nullptr, p1_b);

    // 5) e2[d,c] = py1 @ py2^T  [16, 256, 128]
    tgemm<0, true><<<dim3(1, 2, 16), 256, TG_SMEM>>>(py1, py2, e2, 128, 4096,
        256L * 4096, 4096L,  128L * 4096, 4096L,  256L * 128,
        nullptr, nullptr, nullptr, nullptr);

    // 6) e2p[o,c] = p1_w @ e2 + p1_b[o]  [16, 256, 128]  (fp32)
    sgemm<1><<<dim3(2, 4, 16), 256>>>(p1_w, e2, e2p, 256, 128, 256,
        0L, 256L, 1L,  256L * 128, 128L, 1L,  256L * 128, nullptr, p1_b);

    // 7) energy = e1t @ e2p  [16, 512, 128]  (fp32)
    sgemm<0><<<dim3(2, 8, 16), 256>>>(e1t, e2p, eng, 512, 128, 256,
        512L * 256, 256L, 1L,  256L * 128, 128L, 1L,  512L * 128, nullptr, nullptr);

    // 8) attention = softmax(rowmax - energy)
    softmax_neg<<<16 * 512, 128>>>(eng, att);

    // 9) opr = tf32round(gamma * (attention @ py2) + x)  [16, 512, 4096]
    tgemm<4, false><<<dim3(32, 4, 16), 256, TG_SMEM>>>(att, py2, opr, 4096, 128,
        512L * 128, 128L,  128L * 4096, 4096L,  512L * 4096,
        nullptr, nullptr, x, gamma);

    // 10) out = relu(bn3(conv3x3(opr)))  — retiled double-buffered tf32 conv
    conv3x3_tc_kernel<<<dim3(16, 4, 16), 256, CONV_SMEM>>>(opr, (float*)d_out);
}

// round 6
// speedup vs baseline: 6.7034x; 1.4312x over previous
#include <cuda_runtime.h>
#include <cuda_fp16.h>
#include <math.h>
#include <stdint.h>

#define EPS 1e-5f

// ---------------- scratch (device globals; no allocation allowed) ----------------
__device__ float g_py1[16L * 256 * 4096];
__device__ float g_py2[16L * 128 * 4096];
__device__ float g_e1 [16L * 256 * 512];
__device__ float g_e1t[16L * 512 * 256];
__device__ float g_e2 [16L * 256 * 128];
__device__ float g_e2prt[4L * 16 * 256 * 128];   // split-K partials for e2
__device__ float g_e2p[16L * 256 * 128];
__device__ float g_eng[16L * 512 * 128];
__device__ float g_att[16L * 512 * 128];
__device__ __half g_oprh[16L * 512 * 4096];      // conv input, fp16, ch-pair packed
__device__ uint32_t g_wTh[256L * 9 * 512];       // conv weights half2 [icp][tap][oc]

__device__ float g_s1[256], g_t1[256];
__device__ float g_s2[128], g_t2[128];
__device__ float g_s3[512], g_t3[512];

// ---------------- fold BN (+conv bias) into per-channel scale/shift --------------
__global__ void fold_kernel(const float* __restrict__ q1b, const float* __restrict__ g1,
                            const float* __restrict__ b1,  const float* __restrict__ m1,
                            const float* __restrict__ v1,
                            const float* __restrict__ q2b, const float* __restrict__ g2,
                            const float* __restrict__ b2,  const float* __restrict__ m2,
                            const float* __restrict__ v2,
                            const float* __restrict__ fb,  const float* __restrict__ g3,
                            const float* __restrict__ b3,  const float* __restrict__ m3,
                            const float* __restrict__ v3)
{
    int i = threadIdx.x;
    if (i < 256) {
        float s = g1[i] * rsqrtf(v1[i] + EPS);
        g_s1[i] = s;
        g_t1[i] = s * q1b[i] + b1[i] - m1[i] * s;
    }
    if (i < 128) {
        float s = g2[i] * rsqrtf(v2[i] + EPS);
        g_s2[i] = s;
        g_t2[i] = s * q2b[i] + b2[i] - m2[i] * s;
    }
    if (i < 512) {
        float s = g3[i] * rsqrtf(v3[i] + EPS);
        g_s3[i] = s;
        g_t3[i] = s * fb[i] + b3[i] - m3[i] * s;
    }
}

// ---------------- helpers ---------------------------------------------------------
__device__ __forceinline__ void split_tf32(float f, uint32_t& hi, uint32_t& lo) {
    asm("cvt.rna.tf32.f32 %0, %1;" : "=r"(hi) : "f"(f));
    float r = f - __uint_as_float(hi);
    asm("cvt.rna.tf32.f32 %0, %1;" : "=r"(lo) : "f"(r));
}

__device__ __forceinline__ void mma_tf32(float* c, const uint32_t* a, uint32_t b0, uint32_t b1) {
    asm volatile(
        "mma.sync.aligned.m16n8k8.row.col.f32.tf32.tf32.f32 "
        "{%0,%1,%2,%3}, {%4,%5,%6,%7}, {%8,%9}, {%0,%1,%2,%3};"
        : "+f"(c[0]), "+f"(c[1]), "+f"(c[2]), "+f"(c[3])
        : "r"(a[0]), "r"(a[1]), "r"(a[2]), "r"(a[3]), "r"(b0), "r"(b1));
}

__device__ __forceinline__ void mma_f16(float* c, const uint32_t* a, uint32_t b0, uint32_t b1) {
    asm volatile(
        "mma.sync.aligned.m16n8k16.row.col.f32.f16.f16.f32 "
        "{%0,%1,%2,%3}, {%4,%5,%6,%7}, {%8,%9}, {%0,%1,%2,%3};"
        : "+f"(c[0]), "+f"(c[1]), "+f"(c[2]), "+f"(c[3])
        : "r"(a[0]), "r"(a[1]), "r"(a[2]), "r"(a[3]), "r"(b0), "r"(b1));
}

__device__ __forceinline__ void cp16(uint32_t dst, const void* src) {
    asm volatile("cp.async.cg.shared.global [%0], [%1], 16;" :: "r"(dst), "l"(src));
}

// ---------------- conv weight pack: w[oc][ic][tap] -> half2 [icp][tap][oc] -------
__global__ void wtrans_h(const float* __restrict__ w)
{
    int idx = blockIdx.x * 256 + threadIdx.x;   // 256*9*512
    if (idx >= 256 * 9 * 512) return;
    int oc = idx & 511;
    int tap = (idx >> 9) % 9;
    int icp = idx / (9 * 512);
    float w0 = w[((long)oc * 512 + 2 * icp) * 9 + tap];
    float w1 = w[((long)oc * 512 + 2 * icp + 1) * 9 + tap];
    __half2 h = __floats2half2_rn(w0, w1);
    g_wTh[idx] = *(uint32_t*)&h;
}

// ====================== tf32x3 tensor-core GEMM ==================================
// Block 128(M) x 128(N), K chunk 32, 8 warps, warp tile 32x64 = 2x8 m16n8k8.
// Split-K: blockIdx.x = sp*ntx + nblk; k range [sp*splitChunk, ...), C += sp*partStride.
#define TG_SMEM ((128 * 36 * 2 + 4608 * 2) * 4)   // 73728 B
// EPI: 0 none | 2 relu(sv[m]*v+tv[m]) | 4 fp16(gamma*v + res) packed ch-pairs
template <int EPI, bool BKC>
__global__ __launch_bounds__(256)
void tgemm(const float* __restrict__ A, const float* __restrict__ B,
           float* __restrict__ C, int N, int K,
           int ntx, int splitChunk, long partStride,
           long aBat, long aSm, long bBat, long bS, long cBat,
           const float* __restrict__ sv, const float* __restrict__ tv,
           const float* __restrict__ res, const float* __restrict__ gptr)
{
    extern __shared__ uint32_t dsm[];
    uint32_t* Ah = dsm;                  // 128 x 36
    uint32_t* Al = Ah + 128 * 36;
    uint32_t* Bh = Al + 128 * 36;        // BKC: [n(128)][36]; !BKC: [k(32)][136]
    uint32_t* Bl = Bh + 4608;

    int tid = threadIdx.x;
    int lane = tid & 31, warp = tid >> 5;
    int warpM = warp >> 1, warpN = warp & 1;
    int grp = lane >> 2, tig = lane & 3;
    int sp = blockIdx.x / ntx;
    int n0 = (blockIdx.x % ntx) * 128, m0 = blockIdx.y * 128;
    int kBeg = sp * splitChunk;
    int kEnd = kBeg + splitChunk < K ? kBeg + splitChunk : K;
    long ab = (long)blockIdx.z * aBat + (long)m0 * aSm;
    long bb = (long)blockIdx.z * bBat;
    long cb = (long)blockIdx.z * cBat + (long)sp * partStride;

    float acc[2][8][4] = {};

    int kq = tid & 7;        // k quad (x4)
    int mrow = tid >> 3;     // 0..31

    for (int k0 = kBeg; k0 < kEnd; k0 += 32) {
        __syncthreads();
        #pragma unroll
        for (int i = 0; i < 4; i++) {
            int m = mrow + 32 * i;
            float4 v = *(const float4*)&A[ab + (long)m * aSm + k0 + 4 * kq];
            uint32_t h0, l0, h1, l1, h2, l2, h3, l3;
            split_tf32(v.x, h0, l0); split_tf32(v.y, h1, l1);
            split_tf32(v.z, h2, l2); split_tf32(v.w, h3, l3);
            *(uint4*)&Ah[m * 36 + 4 * kq] = make_uint4(h0, h1, h2, h3);
            *(uint4*)&Al[m * 36 + 4 * kq] = make_uint4(l0, l1, l2, l3);
        }
        if (BKC) {
            #pragma unroll
            for (int i = 0; i < 4; i++) {
                int n = mrow + 32 * i;
                float4 v = *(const float4*)&B[bb + (long)(n0 + n) * bS + k0 + 4 * kq];
                uint32_t h0, l0, h1, l1, h2, l2, h3, l3;
                split_tf32(v.x, h0, l0); split_tf32(v.y, h1, l1);
                split_tf32(v.z, h2, l2); split_tf32(v.w, h3, l3);
                *(uint4*)&Bh[n * 36 + 4 * kq] = make_uint4(h0, h1, h2, h3);
                *(uint4*)&Bl[n * 36 + 4 * kq] = make_uint4(l0, l1, l2, l3);
            }
        } else {
            int nq = tid & 31, kk = tid >> 5;
            #pragma unroll
            for (int i = 0; i < 4; i++) {
                int k = kk + 8 * i;
                float4 v = *(const float4*)&B[bb + (long)(k0 + k) * bS + n0 + 4 * nq];
                uint32_t h0, l0, h1, l1, h2, l2, h3, l3;
                split_tf32(v.x, h0, l0); split_tf32(v.y, h1, l1);
                split_tf32(v.z, h2, l2); split_tf32(v.w, h3, l3);
                *(uint4*)&Bh[k * 136 + 4 * nq] = make_uint4(h0, h1, h2, h3);
                *(uint4*)&Bl[k * 136 + 4 * nq] = make_uint4(l0, l1, l2, l3);
            }
        }
        __syncthreads();

        #pragma unroll
        for (int s = 0; s < 4; s++) {
            int k = s * 8 + tig;
            uint32_t ahi[2][4], alo[2][4];
            #pragma unroll
            for (int mt = 0; mt < 2; mt++) {
                int m = warpM * 32 + mt * 16 + grp;
                ahi[mt][0] = Ah[m * 36 + k];           alo[mt][0] = Al[m * 36 + k];
                ahi[mt][1] = Ah[(m + 8) * 36 + k];     alo[mt][1] = Al[(m + 8) * 36 + k];
                ahi[mt][2] = Ah[m * 36 + k + 4];       alo[mt][2] = Al[m * 36 + k + 4];
                ahi[mt][3] = Ah[(m + 8) * 36 + k + 4]; alo[mt][3] = Al[(m + 8) * 36 + k + 4];
            }
            uint32_t bhi[8][2], blo[8][2];
            #pragma unroll
            for (int nt = 0; nt < 8; nt++) {
                int n = warpN * 64 + nt * 8 + grp;
                int i0 = BKC ? (n * 36 + k)     : (k * 136 + n);
                int i1 = BKC ? (n * 36 + k + 4) : ((k + 4) * 136 + n);
                bhi[nt][0] = Bh[i0]; blo[nt][0] = Bl[i0];
                bhi[nt][1] = Bh[i1]; blo[nt][1] = Bl[i1];
            }
            #pragma unroll
            for (int mt = 0; mt < 2; mt++)
                #pragma unroll
                for (int nt = 0; nt < 8; nt++) {
                    mma_tf32(acc[mt][nt], ahi[mt], blo[nt][0], blo[nt][1]);
                    mma_tf32(acc[mt][nt], alo[mt], bhi[nt][0], bhi[nt][1]);
                    mma_tf32(acc[mt][nt], ahi[mt], bhi[nt][0], bhi[nt][1]);
                }
        }
    }

    float gm = (EPI == 4) ? gptr[0] : 0.f;
    #pragma unroll
    for (int mt = 0; mt < 2; mt++) {
        #pragma unroll
        for (int h = 0; h < 2; h++) {
            int m = m0 + warpM * 32 + mt * 16 + grp + h * 8;
            float s = 0.f, t = 0.f;
            if (EPI == 2) { s = sv[m]; t = tv[m]; }
            #pragma unroll
            for (int nt = 0; nt < 8; nt++) {
                int n = n0 + warpN * 64 + nt * 8 + tig * 2;
                float v0 = acc[mt][nt][2 * h];
                float v1 = acc[mt][nt][2 * h + 1];
                if (EPI == 4) {
                    v0 = gm * v0 + res[cb + (long)m * N + n];
                    v1 = gm * v1 + res[cb + (long)m * N + n + 1];
                    __half* Ch = (__half*)C;
                    long base = cb + (long)(m >> 1) * 2 * N + (long)n * 2 + (m & 1);
                    Ch[base]     = __float2half(v0);
                    Ch[base + 2] = __float2half(v1);
                } else {
                    if (EPI == 2) {
                        v0 = fmaxf(s * v0 + t, 0.f);
                        v1 = fmaxf(s * v1 + t, 0.f);
                    }
                    C[cb + (long)m * N + n] = v0;
                    C[cb + (long)m * N + n + 1] = v1;
                }
            }
        }
    }
}

// ---------------- reduce 4 split-K partials --------------------------------------
__global__ void reduce4(const float* __restrict__ p, float* __restrict__ o, int n)
{
    int i = blockIdx.x * 256 + threadIdx.x;
    if (i < n)
        o[i] = p[i] + p[i + n] + p[i + 2 * n] + p[i + 3 * n];
}

// ---------------- generic strided batched SGEMM (fp32) — small stages only -------
template <int EPI>
__global__ __launch_bounds__(256)
void sgemm(const float* __restrict__ A, const float* __restrict__ B,
           float* __restrict__ C,
           int M, int N, int K,
           long aBat, long aSm, long aSk,
           long bBat, long bSk, long bSn,
           long cBat,
           const float* __restrict__ sv, const float* __restrict__ tv)
{
    __shared__ float As[16][65];
    __shared__ float Bs[16][65];
    int tid = threadIdx.x;
    int tx = tid & 15, ty = tid >> 4;
    int n0 = blockIdx.x * 64, m0 = blockIdx.y * 64;
    long ab = (long)blockIdx.z * aBat;
    long bb = (long)blockIdx.z * bBat;
    long cb = (long)blockIdx.z * cBat;

    float acc[4][4] = {};

    for (int k0 = 0; k0 < K; k0 += 16) {
        if (aSk == 1) {
            #pragma unroll
            for (int i = 0; i < 4; i++) {
                int idx = tid + i * 256;
                int k = idx & 15, m = idx >> 4;
                As[k][m] = A[ab + (long)(m0 + m) * aSm + (k0 + k)];
            }
        } else {
            #pragma unroll
            for (int i = 0; i < 4; i++) {
                int idx = tid + i * 256;
                int m = idx & 63, k = idx >> 6;
                As[k][m] = A[ab + (long)(m0 + m) * aSm + (long)(k0 + k) * aSk];
            }
        }
        if (bSn == 1) {
            #pragma unroll
            for (int i = 0; i < 4; i++) {
                int idx = tid + i * 256;
                int n = idx & 63, k = idx >> 6;
                Bs[k][n] = B[bb + (long)(k0 + k) * bSk + (n0 + n)];
            }
        } else {
            #pragma unroll
            for (int i = 0; i < 4; i++) {
                int idx = tid + i * 256;
                int k = idx & 15, n = idx >> 4;
                Bs[k][n] = B[bb + (long)(k0 + k) * bSk + (long)(n0 + n) * bSn];
            }
        }
        __syncthreads();
        #pragma unroll
        for (int k = 0; k < 16; k++) {
            float a[4], bv[4];
            #pragma unroll
            for (int i = 0; i < 4; i++) a[i] = As[k][ty + 16 * i];
            #pragma unroll
            for (int j = 0; j < 4; j++) bv[j] = Bs[k][tx + 16 * j];
            #pragma unroll
            for (int i = 0; i < 4; i++)
                #pragma unroll
                for (int j = 0; j < 4; j++)
                    acc[i][j] += a[i] * bv[j];
        }
        __syncthreads();
    }

    #pragma unroll
    for (int i = 0; i < 4; i++) {
        int m = m0 + ty + 16 * i;
        #pragma unroll
        for (int j = 0; j < 4; j++) {
            int n = n0 + tx + 16 * j;
            float v = acc[i][j];
            if (EPI == 1) v += tv[m];
            else if (EPI == 3) v += tv[n];
            C[cb + (long)m * N + n] = v;
        }
    }
}

// ---------------- softmax of (rowmax - E) == softmax over (-E), rows of 128 ------
__global__ void softmax_neg(const float* __restrict__ E, float* __restrict__ A)
{
    int row = blockIdx.x;
    int t = threadIdx.x;
    __shared__ float red[128];
    float v = E[(long)row * 128 + t];
    red[t] = v;
    __syncthreads();
    for (int s = 64; s > 0; s >>= 1) {
        if (t < s) red[t] = fminf(red[t], red[t + s]);
        __syncthreads();
    }
    float mn = red[0];
    __syncthreads();
    float ex = expf(mn - v);
    red[t] = ex;
    __syncthreads();
    for (int s = 64; s > 0; s >>= 1) {
        if (t < s) red[t] += red[t + s];
        __syncthreads();
    }
    A[(long)row * 128 + t] = ex / red[0];
}

// ---------------- 3x3 conv, fp16 m16n8k16, 3-stage cp.async pipeline -------------
// Block: 256 thr = 8 warps (warpM 0..1 -> 64 oc, warpN 0..3 -> row).
// Block tile: 128 oc x (4 rows x 64 cols). Warp: 64 oc x 64 px = 4x8 m16n8k16.
// Stage = 16 ic (8 ic-pairs), 32 stages.
// sW stage [icp(8)][tap(9)] stride 136; sIn stage [icp(8)][y(6)] stride 76 (half2/px).
#define SW_WORDS  (8 * 9 * 136)     // 9792
#define SIN_WORDS (8 * 6 * 76)      // 3648
#define CONV_SMEM (3 * (SW_WORDS + SIN_WORDS) * 4)   // 161280 B

__device__ __forceinline__ void conv_issue(int icp0, uint32_t swb, uint32_t sinb,
                                           const __half* __restrict__ inB,
                                           int y0, int oc0, int tid)
{
    // weights: 72 rows (icp*9+tap) x 32 chunks of 16B
    for (int idx = tid; idx < 2304; idx += 256) {
        int row = idx >> 5;
        int ch  = idx & 31;
        int icp = row / 9, tap = row - icp * 9;
        cp16(swb + (uint32_t)(row * 136 + ch * 4) * 4,
             &g_wTh[(((long)(icp0 + icp)) * 9 + tap) * 512 + oc0 + ch * 4]);
    }
    // inputs: 48 rows (icp*6+y) x 16 chunks of 16B (4 px of half2 each)
    for (int idx = tid; idx < 768; idx += 256) {
        int r  = idx >> 4;
        int ch = idx & 15;
        int icp = r / 6, y = r - icp * 6;
        int gy = y0 - 1 + y;
        if (gy >= 0 && gy < 64)
            cp16(sinb + (uint32_t)(r * 76 + 4 + ch * 4) * 4,
                 inB + (long)(icp0 + icp) * 8192 + (long)gy * 128 + ch * 8);
    }
}

__global__ __launch_bounds__(256, 1)
void conv3x3_tc_kernel(const __half* __restrict__ in, float* __restrict__ out)
{
    extern __shared__ uint32_t smem[];
    uint32_t* sW  = smem;                     // 3 stages
    uint32_t* sIn = smem + 3 * SW_WORDS;      // 3 stages
    uint32_t sw_base  = (uint32_t)__cvta_generic_to_shared(sW);
    uint32_t sin_base = (uint32_t)__cvta_generic_to_shared(sIn);

    int tid = threadIdx.x;
    int lane = tid & 31;
    int warp = tid >> 5;
    int warpM = warp >> 2;          // 0..1 -> 64-oc half
    int warpN = warp & 3;           // 0..3 -> row
    int grp = lane >> 2;
    int tig = lane & 3;

    int b   = blockIdx.z;
    int oc0 = blockIdx.y * 128;
    int y0  = blockIdx.x * 4;

    const __half* inB = in + (long)b * 256 * 8192;

    // zero all three sIn buffers once (halos / invalid rows stay zero)
    for (int i = tid; i < 3 * SIN_WORDS; i += 256) sIn[i] = 0;
    __syncthreads();

    conv_issue(0, sw_base, sin_base, inB, y0, oc0, tid);
    asm volatile("cp.async.commit_group;");
    conv_issue(8, sw_base + SW_WORDS * 4, sin_base + SIN_WORDS * 4, inB, y0, oc0, tid);
    asm volatile("cp.async.commit_group;");

    float acc[4][8][4] = {};

    for (int it = 0; it < 32; it++) {
        int buf = it % 3;
        if (it < 30) {
            int nb = (it + 2) % 3;
            conv_issue((it + 2) * 8, sw_base + nb * SW_WORDS * 4,
                       sin_base + nb * SIN_WORDS * 4, inB, y0, oc0, tid);
            asm volatile("cp.async.commit_group;");
            asm volatile("cp.async.wait_group 2;");
        } else if (it == 30) {
            asm volatile("cp.async.wait_group 1;");
        } else {
            asm volatile("cp.async.wait_group 0;");
        }
        __syncthreads();

        const uint32_t* sWb  = sW + buf * SW_WORDS;
        const uint32_t* sInb = sIn + buf * SIN_WORDS;

        #pragma unroll
        for (int ky = 0; ky < 3; ky++) {
            #pragma unroll
            for (int kx = 0; kx < 3; kx++) {
                const int tap = ky * 3 + kx;
                const int wr0 = (tig * 9 + tap) * 136;
                const int wr4 = ((tig + 4) * 9 + tap) * 136;
                uint32_t a[4][4];
                #pragma unroll
                for (int mt = 0; mt < 4; mt++) {
                    int oc = warpM * 64 + mt * 16 + grp;
                    a[mt][0] = sWb[wr0 + oc];
                    a[mt][1] = sWb[wr0 + oc + 8];
                    a[mt][2] = sWb[wr4 + oc];
                    a[mt][3] = sWb[wr4 + oc + 8];
                }
                const int ir0 = (tig * 6 + warpN + ky) * 76;
                const int ir4 = ((tig + 4) * 6 + warpN + ky) * 76;
                #pragma unroll
                for (int j = 0; j < 8; j++) {
                    int xi = 3 + j * 8 + grp + kx;
                    uint32_t b0 = sInb[ir0 + xi];
                    uint32_t b1 = sInb[ir4 + xi];
                    #pragma unroll
                    for (int mt = 0; mt < 4; mt++)
                        mma_f16(acc[mt][j], a[mt], b0, b1);
                }
            }
        }
        __syncthreads();
    }

    int y = y0 + warpN;
    #pragma unroll
    for (int mt = 0; mt < 4; mt++) {
        int row = oc0 + warpM * 64 + mt * 16 + grp;
        float s0 = g_s3[row],     t0 = g_t3[row];
        float s8 = g_s3[row + 8], t8 = g_t3[row + 8];
        long base0 = ((long)b * 512 + row) * 4096 + (long)y * 64;
        long base8 = base0 + 8L * 4096;
        #pragma unroll
        for (int j = 0; j < 8; j++) {
            int x = j * 8 + tig * 2;
            out[base0 + x    ] = fmaxf(s0 * acc[mt][j][0] + t0, 0.f);
            out[base0 + x + 1] = fmaxf(s0 * acc[mt][j][1] + t0, 0.f);
            out[base8 + x    ] = fmaxf(s8 * acc[mt][j][2] + t8, 0.f);
            out[base8 + x + 1] = fmaxf(s8 * acc[mt][j][3] + t8, 0.f);
        }
    }
}

// ------------------------------- launcher ---------------------------------------
extern "C" void kernel_launch(void* const* d_in, const int* in_sizes, int n_in,
                              void* d_out, int out_size)
{
    const float* x     = (const float*)d_in[0];
    const float* q1_w  = (const float*)d_in[1];
    const float* q1_b  = (const float*)d_in[2];
    const float* bn1_g = (const float*)d_in[3];
    const float* bn1_b = (const float*)d_in[4];
    const float* bn1_m = (const float*)d_in[5];
    const float* bn1_v = (const float*)d_in[6];
    const float* q2_w  = (const float*)d_in[7];
    const float* q2_b  = (const float*)d_in[8];
    const float* bn2_g = (const float*)d_in[9];
    const float* bn2_b = (const float*)d_in[10];
    const float* bn2_m = (const float*)d_in[11];
    const float* bn2_v = (const float*)d_in[12];
    const float* p1_w  = (const float*)d_in[13];
    const float* p1_b  = (const float*)d_in[14];
    const float* fus_w = (const float*)d_in[15];
    const float* fus_b = (const float*)d_in[16];
    const float* bn3_g = (const float*)d_in[17];
    const float* bn3_b = (const float*)d_in[18];
    const float* bn3_m = (const float*)d_in[19];
    const float* bn3_v = (const float*)d_in[20];
    const float* gamma = (const float*)d_in[21];

    float *py1, *py2, *e1, *e1t, *e2, *e2prt, *e2p, *eng, *att, *s1, *t1, *s2, *t2;
    __half* oprh;
    cudaGetSymbolAddress((void**)&py1, g_py1);
    cudaGetSymbolAddress((void**)&py2, g_py2);
    cudaGetSymbolAddress((void**)&e1,  g_e1);
    cudaGetSymbolAddress((void**)&e1t, g_e1t);
    cudaGetSymbolAddress((void**)&e2,  g_e2);
    cudaGetSymbolAddress((void**)&e2prt, g_e2prt);
    cudaGetSymbolAddress((void**)&e2p, g_e2p);
    cudaGetSymbolAddress((void**)&eng, g_eng);
    cudaGetSymbolAddress((void**)&att, g_att);
    cudaGetSymbolAddress((void**)&oprh, g_oprh);
    cudaGetSymbolAddress((void**)&s1,  g_s1);
    cudaGetSymbolAddress((void**)&t1,  g_t1);
    cudaGetSymbolAddress((void**)&s2,  g_s2);
    cudaGetSymbolAddress((void**)&t2,  g_t2);

    static bool attr_set = false;
    if (!attr_set) {
        cudaFuncSetAttribute(conv3x3_tc_kernel,
                             cudaFuncAttributeMaxDynamicSharedMemorySize, CONV_SMEM);
        cudaFuncSetAttribute(tgemm<2, false>,
                             cudaFuncAttributeMaxDynamicSharedMemorySize, TG_SMEM);
        cudaFuncSetAttribute(tgemm<0, true>,
                             cudaFuncAttributeMaxDynamicSharedMemorySize, TG_SMEM);
        cudaFuncSetAttribute(tgemm<4, false>,
                             cudaFuncAttributeMaxDynamicSharedMemorySize, TG_SMEM);
        attr_set = true;
    }

    fold_kernel<<<1, 512>>>(q1_b, bn1_g, bn1_b, bn1_m, bn1_v,
                            q2_b, bn2_g, bn2_b, bn2_m, bn2_v,
                            fus_b, bn3_g, bn3_b, bn3_m, bn3_v);

    wtrans_h<<<(256 * 9 * 512 + 255) / 256, 256>>>(fus_w);

    // 1) py1 = relu(bn1(q1_w @ x))  [16, 256, 4096]
    tgemm<2, false><<<dim3(32, 2, 16), 256, TG_SMEM>>>(q1_w, x, py1, 4096, 512,
        32, 512, 0L,
        0L, 512L,  512L * 4096, 4096L,  256L * 4096, s1, t1, nullptr, nullptr);

    // 2) py2 = relu(bn2(q2_w @ py1))  [16, 128, 4096]
    tgemm<2, false><<<dim3(32, 1, 16), 256, TG_SMEM>>>(q2_w, py1, py2, 4096, 256,
        32, 256, 0L,
        0L, 256L,  256L * 4096, 4096L,  128L * 4096, s2, t2, nullptr, nullptr);

    // 3) e1[c,d] = py1 @ x^T  [16, 256, 512]
    tgemm<0, true><<<dim3(4, 2, 16), 256, TG_SMEM>>>(py1, x, e1, 512, 4096,
        4, 4096, 0L,
        256L * 4096, 4096L,  512L * 4096, 4096L,  256L * 512,
        nullptr, nullptr, nullptr, nullptr);

    // 4) e1t[d,o] = e1^T @ p1_w^T + p1_b[o]  [16, 512, 256]  (fp32)
    sgemm<3><<<dim3(4, 8, 16), 256>>>(e1, p1_w, e1t, 512, 256, 256,
        256L * 512, 1L, 512L,  0L, 1L, 256L,  512L * 256, nullptr, p1_b);

    // 5) e2 = py1 @ py2^T  [16, 256, 128]  — split-K x4 into partials, then reduce
    tgemm<0, true><<<dim3(4, 2, 16), 256, TG_SMEM>>>(py1, py2, e2prt, 128, 4096,
        1, 1024, 16L * 256 * 128,
        256L * 4096, 4096L,  128L * 4096, 4096L,  256L * 128,
        nullptr, nullptr, nullptr, nullptr);
    reduce4<<<(16 * 256 * 128 + 255) / 256, 256>>>(e2prt, e2, 16 * 256 * 128);

    // 6) e2p[o,c] = p1_w @ e2 + p1_b[o]  [16, 256, 128]  (fp32)
    sgemm<1><<<dim3(2, 4, 16), 256>>>(p1_w, e2, e2p, 256, 128, 256,
        0L, 256L, 1L,  256L * 128, 128L, 1L,  256L * 128, nullptr, p1_b);

    // 7) energy = e1t @ e2p  [16, 512, 128]  (fp32)
    sgemm<0><<<dim3(2, 8, 16), 256>>>(e1t, e2p, eng, 512, 128, 256,
        512L * 256, 256L, 1L,  256L * 128, 128L, 1L,  512L * 128, nullptr, nullptr);

    // 8) attention = softmax(rowmax - energy)
    softmax_neg<<<16 * 512, 128>>>(eng, att);

    // 9) oprh = fp16(gamma * (attention @ py2) + x), ch-pair packed  [16, 512, 4096]
    tgemm<4, false><<<dim3(32, 4, 16), 256, TG_SMEM>>>(att, py2, (float*)oprh, 4096, 128,
        32, 128, 0L,
        512L * 128, 128L,  128L * 4096, 4096L,  512L * 4096,
        nullptr, nullptr, x, gamma);

    // 10) out = relu(bn3(conv3x3(oprh)))  — fp16 tensor-core, 3-stage pipeline
    conv3x3_tc_kernel<<<dim3(16, 4, 16), 256, CONV_SMEM>>>(oprh, (float*)d_out);
}

// round 7
// speedup vs baseline: 7.2114x; 1.0758x over previous
#include <cuda_runtime.h>
#include <cuda_fp16.h>
#include <math.h>
#include <stdint.h>

#define EPS 1e-5f

// ---------------- scratch (device globals; no allocation allowed) ----------------
__device__ float g_py1[16L * 256 * 4096];
__device__ float g_py2[16L * 128 * 4096];
__device__ uint32_t g_py2h[16L * 64 * 4096];     // py2 fp16 packed k-pairs [b][kp][n]
__device__ float g_e1T[16L * 512 * 256];         // e1 transposed [b][d][c]
__device__ float g_e1t[16L * 512 * 256];
__device__ float g_e2 [16L * 256 * 128];
__device__ float g_e2prt[4L * 16 * 256 * 128];
__device__ float g_e2p[16L * 256 * 128];
__device__ float g_eng[16L * 512 * 128];
__device__ __half g_atth[16L * 512 * 128];       // attention, fp16
__device__ __half g_oprh[16L * 512 * 4096];      // conv input, fp16, ch-pair packed
__device__ uint4 g_wfrag[294912];                // conv weight MMA fragments

__device__ float g_s1[256], g_t1[256];
__device__ float g_s2[128], g_t2[128];
__device__ float g_s3[512], g_t3[512];

// ---------------- fold BN (+conv bias) into per-channel scale/shift --------------
__global__ void fold_kernel(const float* __restrict__ q1b, const float* __restrict__ g1,
                            const float* __restrict__ b1,  const float* __restrict__ m1,
                            const float* __restrict__ v1,
                            const float* __restrict__ q2b, const float* __restrict__ g2,
                            const float* __restrict__ b2,  const float* __restrict__ m2,
                            const float* __restrict__ v2,
                            const float* __restrict__ fb,  const float* __restrict__ g3,
                            const float* __restrict__ b3,  const float* __restrict__ m3,
                            const float* __restrict__ v3)
{
    int i = threadIdx.x;
    if (i < 256) {
        float s = g1[i] * rsqrtf(v1[i] + EPS);
        g_s1[i] = s;
        g_t1[i] = s * q1b[i] + b1[i] - m1[i] * s;
    }
    if (i < 128) {
        float s = g2[i] * rsqrtf(v2[i] + EPS);
        g_s2[i] = s;
        g_t2[i] = s * q2b[i] + b2[i] - m2[i] * s;
    }
    if (i < 512) {
        float s = g3[i] * rsqrtf(v3[i] + EPS);
        g_s3[i] = s;
        g_t3[i] = s * fb[i] + b3[i] - m3[i] * s;
    }
}

// ---------------- helpers ---------------------------------------------------------
__device__ __forceinline__ void split_tf32(float f, uint32_t& hi, uint32_t& lo) {
    asm("cvt.rna.tf32.f32 %0, %1;" : "=r"(hi) : "f"(f));
    float r = f - __uint_as_float(hi);
    asm("cvt.rna.tf32.f32 %0, %1;" : "=r"(lo) : "f"(r));
}

__device__ __forceinline__ void mma_tf32(float* c, const uint32_t* a, uint32_t b0, uint32_t b1) {
    asm volatile(
        "mma.sync.aligned.m16n8k8.row.col.f32.tf32.tf32.f32 "
        "{%0,%1,%2,%3}, {%4,%5,%6,%7}, {%8,%9}, {%0,%1,%2,%3};"
        : "+f"(c[0]), "+f"(c[1]), "+f"(c[2]), "+f"(c[3])
        : "r"(a[0]), "r"(a[1]), "r"(a[2]), "r"(a[3]), "r"(b0), "r"(b1));
}

__device__ __forceinline__ void mma_f16(float* c, const uint32_t* a, uint32_t b0, uint32_t b1) {
    asm volatile(
        "mma.sync.aligned.m16n8k16.row.col.f32.f16.f16.f32 "
        "{%0,%1,%2,%3}, {%4,%5,%6,%7}, {%8,%9}, {%0,%1,%2,%3};"
        : "+f"(c[0]), "+f"(c[1]), "+f"(c[2]), "+f"(c[3])
        : "r"(a[0]), "r"(a[1]), "r"(a[2]), "r"(a[3]), "r"(b0), "r"(b1));
}

__device__ __forceinline__ void cp16(uint32_t dst, const void* src) {
    asm volatile("cp.async.cg.shared.global [%0], [%1], 16;" :: "r"(dst), "l"(src));
}

// ---------------- conv weight fragment pack --------------------------------------
// fragment id = ((((ocblk*32+stage)*9+tap)*8+mslot)*8+grp)*4+tig
// v = { W(icp=stage*8+tig,   oc), W(icp, oc+8), W(icp+4, oc), W(icp+4, oc+8) }
// where oc = ocblk*128 + mslot*16 + grp, W = half2(w[oc][2icp][tap], w[oc][2icp+1][tap])
__device__ __forceinline__ uint32_t wpair(const float* w, int oc, int icp, int tap) {
    float w0 = w[((long)oc * 512 + 2 * icp) * 9 + tap];
    float w1 = w[((long)oc * 512 + 2 * icp + 1) * 9 + tap];
    __half2 h = __floats2half2_rn(w0, w1);
    return *(uint32_t*)&h;
}

__global__ void wpack(const float* __restrict__ w)
{
    int idx = blockIdx.x * 256 + threadIdx.x;
    if (idx >= 294912) return;
    int tig = idx & 3;
    int grp = (idx >> 2) & 7;
    int mslot = (idx >> 5) & 7;
    int t = idx >> 8;
    int tap = t % 9;
    int t2 = t / 9;
    int stage = t2 & 31;
    int ocblk = t2 >> 5;
    int oc = ocblk * 128 + mslot * 16 + grp;
    int icp = stage * 8 + tig;
    uint4 v;
    v.x = wpair(w, oc,     icp,     tap);
    v.y = wpair(w, oc + 8, icp,     tap);
    v.z = wpair(w, oc,     icp + 4, tap);
    v.w = wpair(w, oc + 8, icp + 4, tap);
    g_wfrag[idx] = v;
}

// ====================== tf32x3 tensor-core GEMM ==================================
// Block 128(M) x 128(N), K chunk 32, 8 warps, warp tile 32x64 = 2x8 m16n8k8.
#define TG_SMEM ((128 * 36 * 2 + 4608 * 2) * 4)   // 73728 B
// EPI: 0 none | 1 +tv[m] | 2 relu(sv[m]v+tv[m]) (+opt packed fp16 copy) | 3 +tv[n]
template <int EPI, bool BKC, bool SPLITK>
__global__ __launch_bounds__(256)
void tgemm(const float* __restrict__ A, const float* __restrict__ B,
           float* __restrict__ C, int N, int K,
           int ntx, int splitChunk, long partStride,
           long aBat, long aSm, long bBat, long bS, long cBat,
           const float* __restrict__ sv, const float* __restrict__ tv,
           __half* __restrict__ h16)
{
    extern __shared__ uint32_t dsm[];
    uint32_t* Ah = dsm;                  // 128 x 36
    uint32_t* Al = Ah + 128 * 36;
    uint32_t* Bh = Al + 128 * 36;        // BKC: [n(128)][36]; !BKC: [k(32)][136]
    uint32_t* Bl = Bh + 4608;

    int tid = threadIdx.x;
    int lane = tid & 31, warp = tid >> 5;
    int warpM = warp >> 1, warpN = warp & 1;
    int grp = lane >> 2, tig = lane & 3;
    int sp = SPLITK ? (blockIdx.x / ntx) : 0;
    int n0 = SPLITK ? (blockIdx.x % ntx) * 128 : blockIdx.x * 128;
    int m0 = blockIdx.y * 128;
    int kBeg = SPLITK ? sp * splitChunk : 0;
    int kEnd = SPLITK ? (kBeg + splitChunk < K ? kBeg + splitChunk : K) : K;
    long ab = (long)blockIdx.z * aBat + (long)m0 * aSm;
    long bb = (long)blockIdx.z * bBat;
    long cb = (long)blockIdx.z * cBat + (SPLITK ? (long)sp * partStride : 0L);

    float acc[2][8][4] = {};

    int kq = tid & 7;
    int mrow = tid >> 3;

    for (int k0 = kBeg; k0 < kEnd; k0 += 32) {
        __syncthreads();
        #pragma unroll
        for (int i = 0; i < 4; i++) {
            int m = mrow + 32 * i;
            float4 v = *(const float4*)&A[ab + (long)m * aSm + k0 + 4 * kq];
            uint32_t h0, l0, h1, l1, h2, l2, h3, l3;
            split_tf32(v.x, h0, l0); split_tf32(v.y, h1, l1);
            split_tf32(v.z, h2, l2); split_tf32(v.w, h3, l3);
            *(uint4*)&Ah[m * 36 + 4 * kq] = make_uint4(h0, h1, h2, h3);
            *(uint4*)&Al[m * 36 + 4 * kq] = make_uint4(l0, l1, l2, l3);
        }
        if (BKC) {
            #pragma unroll
            for (int i = 0; i < 4; i++) {
                int n = mrow + 32 * i;
                float4 v = *(const float4*)&B[bb + (long)(n0 + n) * bS + k0 + 4 * kq];
                uint32_t h0, l0, h1, l1, h2, l2, h3, l3;
                split_tf32(v.x, h0, l0); split_tf32(v.y, h1, l1);
                split_tf32(v.z, h2, l2); split_tf32(v.w, h3, l3);
                *(uint4*)&Bh[n * 36 + 4 * kq] = make_uint4(h0, h1, h2, h3);
                *(uint4*)&Bl[n * 36 + 4 * kq] = make_uint4(l0, l1, l2, l3);
            }
        } else {
            int nq = tid & 31, kk = tid >> 5;
            #pragma unroll
            for (int i = 0; i < 4; i++) {
                int k = kk + 8 * i;
                float4 v = *(const float4*)&B[bb + (long)(k0 + k) * bS + n0 + 4 * nq];
                uint32_t h0, l0, h1, l1, h2, l2, h3, l3;
                split_tf32(v.x, h0, l0); split_tf32(v.y, h1, l1);
                split_tf32(v.z, h2, l2); split_tf32(v.w, h3, l3);
                *(uint4*)&Bh[k * 136 + 4 * nq] = make_uint4(h0, h1, h2, h3);
                *(uint4*)&Bl[k * 136 + 4 * nq] = make_uint4(l0, l1, l2, l3);
            }
        }
        __syncthreads();

        #pragma unroll
        for (int s = 0; s < 4; s++) {
            int k = s * 8 + tig;
            uint32_t ahi[2][4], alo[2][4];
            #pragma unroll
            for (int mt = 0; mt < 2; mt++) {
                int m = warpM * 32 + mt * 16 + grp;
                ahi[mt][0] = Ah[m * 36 + k];           alo[mt][0] = Al[m * 36 + k];
                ahi[mt][1] = Ah[(m + 8) * 36 + k];     alo[mt][1] = Al[(m + 8) * 36 + k];
                ahi[mt][2] = Ah[m * 36 + k + 4];       alo[mt][2] = Al[m * 36 + k + 4];
                ahi[mt][3] = Ah[(m + 8) * 36 + k + 4]; alo[mt][3] = Al[(m + 8) * 36 + k + 4];
            }
            uint32_t bhi[8][2], blo[8][2];
            #pragma unroll
            for (int nt = 0; nt < 8; nt++) {
                int n = warpN * 64 + nt * 8 + grp;
                int i0 = BKC ? (n * 36 + k)     : (k * 136 + n);
                int i1 = BKC ? (n * 36 + k + 4) : ((k + 4) * 136 + n);
                bhi[nt][0] = Bh[i0]; blo[nt][0] = Bl[i0];
                bhi[nt][1] = Bh[i1]; blo[nt][1] = Bl[i1];
            }
            #pragma unroll
            for (int mt = 0; mt < 2; mt++)
                #pragma unroll
                for (int nt = 0; nt < 8; nt++) {
                    mma_tf32(acc[mt][nt], ahi[mt], blo[nt][0], blo[nt][1]);
                    mma_tf32(acc[mt][nt], alo[mt], bhi[nt][0], bhi[nt][1]);
                    mma_tf32(acc[mt][nt], ahi[mt], bhi[nt][0], bhi[nt][1]);
                }
        }
    }

    #pragma unroll
    for (int mt = 0; mt < 2; mt++) {
        #pragma unroll
        for (int h = 0; h < 2; h++) {
            int m = m0 + warpM * 32 + mt * 16 + grp + h * 8;
            float s = 0.f, t = 0.f;
            if (EPI == 1) t = tv[m];
            if (EPI == 2) { s = sv[m]; t = tv[m]; }
            #pragma unroll
            for (int nt = 0; nt < 8; nt++) {
                int n = n0 + warpN * 64 + nt * 8 + tig * 2;
                float v0 = acc[mt][nt][2 * h];
                float v1 = acc[mt][nt][2 * h + 1];
                if (EPI == 1) { v0 += t; v1 += t; }
                else if (EPI == 2) {
                    v0 = fmaxf(s * v0 + t, 0.f);
                    v1 = fmaxf(s * v1 + t, 0.f);
                } else if (EPI == 3) { v0 += tv[n]; v1 += tv[n + 1]; }
                C[cb + (long)m * N + n] = v0;
                C[cb + (long)m * N + n + 1] = v1;
                if (EPI == 2 && h16) {
                    long hb = (long)blockIdx.z * 2L * 64 * N
                            + (long)(m >> 1) * 2 * N + (long)n * 2 + (m & 1);
                    h16[hb]     = __float2half(v0);
                    h16[hb + 2] = __float2half(v1);
                }
            }
        }
    }
}

// ---------------- reduce 4 split-K partials --------------------------------------
__global__ void reduce4(const float* __restrict__ p, float* __restrict__ o, int n)
{
    int i = blockIdx.x * 256 + threadIdx.x;
    if (i < n)
        o[i] = p[i] + p[i + n] + p[i + 2 * n] + p[i + 3 * n];
}

// ---------------- softmax of (rowmax - E) -> fp16, rows of 128 -------------------
__global__ void softmax_neg(const float* __restrict__ E, __half* __restrict__ A)
{
    int row = blockIdx.x;
    int t = threadIdx.x;
    __shared__ float red[128];
    float v = E[(long)row * 128 + t];
    red[t] = v;
    __syncthreads();
    for (int s = 64; s > 0; s >>= 1) {
        if (t < s) red[t] = fminf(red[t], red[t + s]);
        __syncthreads();
    }
    float mn = red[0];
    __syncthreads();
    float ex = expf(mn - v);
    red[t] = ex;
    __syncthreads();
    for (int s = 64; s > 0; s >>= 1) {
        if (t < s) red[t] += red[t + s];
        __syncthreads();
    }
    A[(long)row * 128 + t] = __float2half(ex / red[0]);
}

// ---------------- step 9: fp16 GEMM, oprh = fp16(gamma * att@py2 + x) ------------
// M=512 N=4096 K=128. Block 128x128, 8 warps (warpM 0..3, warpN 0..1),
// warp 32x64 = 2x8 m16n8k16. Single K pass (whole K fits smem).
#define HG_SMEM ((128 * 68 + 64 * 136) * 4)   // 69632 B
__global__ __launch_bounds__(256)
void hgemm9(const __half* __restrict__ att, const uint32_t* __restrict__ py2h,
            __half* __restrict__ oprh, const float* __restrict__ res,
            const float* __restrict__ gptr)
{
    extern __shared__ uint32_t dsm[];
    uint32_t* Ap = dsm;             // [m(128)][kp 64] stride 68
    uint32_t* Bp = dsm + 128 * 68;  // [kp(64)][n 128] stride 136

    int tid = threadIdx.x;
    int lane = tid & 31, warp = tid >> 5;
    int warpM = warp >> 1, warpN = warp & 1;
    int grp = lane >> 2, tig = lane & 3;
    int b = blockIdx.z;
    int m0 = blockIdx.y * 128, n0 = blockIdx.x * 128;

    // load A (att fp16, k-contig): 128 rows x 64 uint32
    {
        int r = tid >> 1;
        int hf = tid & 1;
        const uint32_t* src = (const uint32_t*)(att + (long)b * 512 * 128 + (long)(m0 + r) * 128);
        #pragma unroll
        for (int i = 0; i < 8; i++) {
            uint4 v = *(const uint4*)&src[hf * 32 + i * 4];
            *(uint4*)&Ap[r * 68 + hf * 32 + i * 4] = v;
        }
    }
    // load B (py2h packed pairs): 64 rows x 128 uint32
    {
        int kp = tid >> 2;
        int ch = tid & 3;
        const uint32_t* src = py2h + (long)b * 64 * 4096 + (long)kp * 4096 + n0;
        #pragma unroll
        for (int i = 0; i < 8; i++) {
            int c = ch + i * 4;
            uint4 v = *(const uint4*)&src[c * 4];
            *(uint4*)&Bp[kp * 136 + c * 4] = v;
        }
    }
    __syncthreads();

    float acc[2][8][4] = {};
    #pragma unroll
    for (int s = 0; s < 8; s++) {
        int kp0 = s * 8;
        uint32_t a[2][4];
        #pragma unroll
        for (int mt = 0; mt < 2; mt++) {
            int m = warpM * 32 + mt * 16 + grp;
            a[mt][0] = Ap[m * 68 + kp0 + tig];
            a[mt][1] = Ap[(m + 8) * 68 + kp0 + tig];
            a[mt][2] = Ap[m * 68 + kp0 + tig + 4];
            a[mt][3] = Ap[(m + 8) * 68 + kp0 + tig + 4];
        }
        uint32_t bf[8][2];
        #pragma unroll
        for (int nt = 0; nt < 8; nt++) {
            int n = warpN * 64 + nt * 8 + grp;
            bf[nt][0] = Bp[(kp0 + tig) * 136 + n];
            bf[nt][1] = Bp[(kp0 + tig + 4) * 136 + n];
        }
        #pragma unroll
        for (int mt = 0; mt < 2; mt++)
            #pragma unroll
            for (int nt = 0; nt < 8; nt++)
                mma_f16(acc[mt][nt], a[mt], bf[nt][0], bf[nt][1]);
    }

    float gm = gptr[0];
    long rb = (long)b * 512 * 4096;
    #pragma unroll
    for (int mt = 0; mt < 2; mt++) {
        #pragma unroll
        for (int h = 0; h < 2; h++) {
            int m = m0 + warpM * 32 + mt * 16 + grp + h * 8;
            #pragma unroll
            for (int nt = 0; nt < 8; nt++) {
                int n = n0 + warpN * 64 + nt * 8 + tig * 2;
                float v0 = gm * acc[mt][nt][2 * h]     + res[rb + (long)m * 4096 + n];
                float v1 = gm * acc[mt][nt][2 * h + 1] + res[rb + (long)m * 4096 + n + 1];
                long base = rb + (long)(m >> 1) * 8192 + (long)n * 2 + (m & 1);
                oprh[base]     = __float2half(v0);
                oprh[base + 2] = __float2half(v1);
            }
        }
    }
}

// ---------------- 3x3 conv, fp16 m16n8k16, 3-stage cp.async pipeline -------------
// Block: 256 thr = 8 warps (warpM 0..1 -> 64 oc, warpN 0..3 -> row).
// Weights pre-packed as uint4 MMA fragments -> one LDS.128 per a-fragment.
#define SW_WORDS  9216               // 2304 fragments x 4 words per stage
#define SIN_WORDS (8 * 6 * 76)       // 3648
#define CONV_SMEM (3 * (SW_WORDS + SIN_WORDS) * 4)   // 154368 B

__device__ __forceinline__ void conv_issue(int stage, uint32_t swb, uint32_t sinb,
                                           const __half* __restrict__ inB,
                                           int y0, int ocblk, int tid)
{
    const uint4* wsrc = g_wfrag + (long)(ocblk * 32 + stage) * 2304;
    for (int idx = tid; idx < 2304; idx += 256)
        cp16(swb + (uint32_t)idx * 16, wsrc + idx);
    int icp0 = stage * 8;
    for (int idx = tid; idx < 768; idx += 256) {
        int r  = idx >> 4;
        int ch = idx & 15;
        int icp = r / 6, y = r - icp * 6;
        int gy = y0 - 1 + y;
        if (gy >= 0 && gy < 64)
            cp16(sinb + (uint32_t)(r * 76 + 4 + ch * 4) * 4,
                 inB + (long)(icp0 + icp) * 8192 + (long)gy * 128 + ch * 8);
    }
}

__global__ __launch_bounds__(256, 1)
void conv3x3_tc_kernel(const __half* __restrict__ in, float* __restrict__ out)
{
    extern __shared__ uint32_t smem[];
    uint32_t* sW  = smem;                     // 3 stages
    uint32_t* sIn = smem + 3 * SW_WORDS;      // 3 stages
    uint32_t sw_base  = (uint32_t)__cvta_generic_to_shared(sW);
    uint32_t sin_base = (uint32_t)__cvta_generic_to_shared(sIn);

    int tid = threadIdx.x;
    int lane = tid & 31;
    int warp = tid >> 5;
    int warpM = warp >> 2;          // 0..1 -> 64-oc half
    int warpN = warp & 3;           // 0..3 -> row
    int grp = lane >> 2;
    int tig = lane & 3;

    int b     = blockIdx.z;
    int ocblk = blockIdx.y;
    int oc0   = ocblk * 128;
    int y0    = blockIdx.x * 4;

    const __half* inB = in + (long)b * 256 * 8192;

    for (int i = tid; i < 3 * SIN_WORDS; i += 256) sIn[i] = 0;
    __syncthreads();

    conv_issue(0, sw_base, sin_base, inB, y0, ocblk, tid);
    asm volatile("cp.async.commit_group;");
    conv_issue(1, sw_base + SW_WORDS * 4, sin_base + SIN_WORDS * 4, inB, y0, ocblk, tid);
    asm volatile("cp.async.commit_group;");

    float acc[4][8][4] = {};

    for (int it = 0; it < 32; it++) {
        int buf = it % 3;
        if (it < 30) {
            int nb = (it + 2) % 3;
            conv_issue(it + 2, sw_base + nb * SW_WORDS * 4,
                       sin_base + nb * SIN_WORDS * 4, inB, y0, ocblk, tid);
            asm volatile("cp.async.commit_group;");
            asm volatile("cp.async.wait_group 2;");
        } else if (it == 30) {
            asm volatile("cp.async.wait_group 1;");
        } else {
            asm volatile("cp.async.wait_group 0;");
        }
        __syncthreads();

        const uint32_t* sWb  = sW + buf * SW_WORDS;
        const uint32_t* sInb = sIn + buf * SIN_WORDS;

        #pragma unroll
        for (int ky = 0; ky < 3; ky++) {
            #pragma unroll
            for (int kx = 0; kx < 3; kx++) {
                const int tap = ky * 3 + kx;
                uint4 av[4];
                #pragma unroll
                for (int mt = 0; mt < 4; mt++) {
                    int mslot = warpM * 4 + mt;
                    av[mt] = *(const uint4*)&sWb[((tap * 8 + mslot) * 8 + grp) * 16 + tig * 4];
                }
                const int ir0 = (tig * 6 + warpN + ky) * 76;
                const int ir4 = ((tig + 4) * 6 + warpN + ky) * 76;
                #pragma unroll
                for (int j = 0; j < 8; j++) {
                    int xi = 3 + j * 8 + grp + kx;
                    uint32_t b0 = sInb[ir0 + xi];
                    uint32_t b1 = sInb[ir4 + xi];
                    #pragma unroll
                    for (int mt = 0; mt < 4; mt++)
                        mma_f16(acc[mt][j], (const uint32_t*)&av[mt], b0, b1);
                }
            }
        }
        __syncthreads();
    }

    int y = y0 + warpN;
    #pragma unroll
    for (int mt = 0; mt < 4; mt++) {
        int row = oc0 + warpM * 64 + mt * 16 + grp;
        float s0 = g_s3[row],     t0 = g_t3[row];
        float s8 = g_s3[row + 8], t8 = g_t3[row + 8];
        long base0 = ((long)b * 512 + row) * 4096 + (long)y * 64;
        long base8 = base0 + 8L * 4096;
        #pragma unroll
        for (int j = 0; j < 8; j++) {
            int x = j * 8 + tig * 2;
            out[base0 + x    ] = fmaxf(s0 * acc[mt][j][0] + t0, 0.f);
            out[base0 + x + 1] = fmaxf(s0 * acc[mt][j][1] + t0, 0.f);
            out[base8 + x    ] = fmaxf(s8 * acc[mt][j][2] + t8, 0.f);
            out[base8 + x + 1] = fmaxf(s8 * acc[mt][j][3] + t8, 0.f);
        }
    }
}

// ------------------------------- launcher ---------------------------------------
extern "C" void kernel_launch(void* const* d_in, const int* in_sizes, int n_in,
                              void* d_out, int out_size)
{
    const float* x     = (const float*)d_in[0];
    const float* q1_w  = (const float*)d_in[1];
    const float* q1_b  = (const float*)d_in[2];
    const float* bn1_g = (const float*)d_in[3];
    const float* bn1_b = (const float*)d_in[4];
    const float* bn1_m = (const float*)d_in[5];
    const float* bn1_v = (const float*)d_in[6];
    const float* q2_w  = (const float*)d_in[7];
    const float* q2_b  = (const float*)d_in[8];
    const float* bn2_g = (const float*)d_in[9];
    const float* bn2_b = (const float*)d_in[10];
    const float* bn2_m = (const float*)d_in[11];
    const float* bn2_v = (const float*)d_in[12];
    const float* p1_w  = (const float*)d_in[13];
    const float* p1_b  = (const float*)d_in[14];
    const float* fus_w = (const float*)d_in[15];
    const float* fus_b = (const float*)d_in[16];
    const float* bn3_g = (const float*)d_in[17];
    const float* bn3_b = (const float*)d_in[18];
    const float* bn3_m = (const float*)d_in[19];
    const float* bn3_v = (const float*)d_in[20];
    const float* gamma = (const float*)d_in[21];

    float *py1, *py2, *e1T, *e1t, *e2, *e2prt, *e2p, *eng, *s1, *t1, *s2, *t2;
    uint32_t* py2h;
    __half *atth, *oprh;
    cudaGetSymbolAddress((void**)&py1, g_py1);
    cudaGetSymbolAddress((void**)&py2, g_py2);
    cudaGetSymbolAddress((void**)&py2h, g_py2h);
    cudaGetSymbolAddress((void**)&e1T, g_e1T);
    cudaGetSymbolAddress((void**)&e1t, g_e1t);
    cudaGetSymbolAddress((void**)&e2,  g_e2);
    cudaGetSymbolAddress((void**)&e2prt, g_e2prt);
    cudaGetSymbolAddress((void**)&e2p, g_e2p);
    cudaGetSymbolAddress((void**)&eng, g_eng);
    cudaGetSymbolAddress((void**)&atth, g_atth);
    cudaGetSymbolAddress((void**)&oprh, g_oprh);
    cudaGetSymbolAddress((void**)&s1,  g_s1);
    cudaGetSymbolAddress((void**)&t1,  g_t1);
    cudaGetSymbolAddress((void**)&s2,  g_s2);
    cudaGetSymbolAddress((void**)&t2,  g_t2);

    static bool attr_set = false;
    if (!attr_set) {
        cudaFuncSetAttribute(conv3x3_tc_kernel,
                             cudaFuncAttributeMaxDynamicSharedMemorySize, CONV_SMEM);
        cudaFuncSetAttribute(hgemm9,
                             cudaFuncAttributeMaxDynamicSharedMemorySize, HG_SMEM);
        cudaFuncSetAttribute(tgemm<2, false, false>,
                             cudaFuncAttributeMaxDynamicSharedMemorySize, TG_SMEM);
        cudaFuncSetAttribute(tgemm<0, true, false>,
                             cudaFuncAttributeMaxDynamicSharedMemorySize, TG_SMEM);
        cudaFuncSetAttribute(tgemm<0, true, true>,
                             cudaFuncAttributeMaxDynamicSharedMemorySize, TG_SMEM);
        cudaFuncSetAttribute(tgemm<3, true, false>,
                             cudaFuncAttributeMaxDynamicSharedMemorySize, TG_SMEM);
        cudaFuncSetAttribute(tgemm<1, false, false>,
                             cudaFuncAttributeMaxDynamicSharedMemorySize, TG_SMEM);
        cudaFuncSetAttribute(tgemm<0, false, false>,
                             cudaFuncAttributeMaxDynamicSharedMemorySize, TG_SMEM);
        attr_set = true;
    }

    fold_kernel<<<1, 512>>>(q1_b, bn1_g, bn1_b, bn1_m, bn1_v,
                            q2_b, bn2_g, bn2_b, bn2_m, bn2_v,
                            fus_b, bn3_g, bn3_b, bn3_m, bn3_v);

    wpack<<<(294912 + 255) / 256, 256>>>(fus_w);

    // 1) py1 = relu(bn1(q1_w @ x))  [16, 256, 4096]
    tgemm<2, false, false><<<dim3(32, 2, 16), 256, TG_SMEM>>>(q1_w, x, py1, 4096, 512,
        0, 0, 0L,  0L, 512L,  512L * 4096, 4096L,  256L * 4096, s1, t1, nullptr);

    // 2) py2 = relu(bn2(q2_w @ py1))  [16, 128, 4096]  (+ packed fp16 copy)
    tgemm<2, false, false><<<dim3(32, 1, 16), 256, TG_SMEM>>>(q2_w, py1, py2, 4096, 256,
        0, 0, 0L,  0L, 256L,  256L * 4096, 4096L,  128L * 4096, s2, t2, (__half*)py2h);

    // 3) e1T[d,c] = x @ py1^T  [16, 512, 256]
    tgemm<0, true, false><<<dim3(2, 4, 16), 256, TG_SMEM>>>(x, py1, e1T, 256, 4096,
        0, 0, 0L,  512L * 4096, 4096L,  256L * 4096, 4096L,  512L * 256,
        nullptr, nullptr, nullptr);

    // 4) e1t[d,o] = e1T @ p1_w^T + p1_b[o]  [16, 512, 256]
    tgemm<3, true, false><<<dim3(2, 4, 16), 256, TG_SMEM>>>(e1T, p1_w, e1t, 256, 256,
        0, 0, 0L,  512L * 256, 256L,  0L, 256L,  512L * 256,
        nullptr, p1_b, nullptr);

    // 5) e2 = py1 @ py2^T  [16, 256, 128]  — split-K x4 + reduce
    tgemm<0, true, true><<<dim3(4, 2, 16), 256, TG_SMEM>>>(py1, py2, e2prt, 128, 4096,
        1, 1024, 16L * 256 * 128,
        256L * 4096, 4096L,  128L * 4096, 4096L,  256L * 128,
        nullptr, nullptr, nullptr);
    reduce4<<<(16 * 256 * 128 + 255) / 256, 256>>>(e2prt, e2, 16 * 256 * 128);

    // 6) e2p[o,c] = p1_w @ e2 + p1_b[o]  [16, 256, 128]
    tgemm<1, false, false><<<dim3(1, 2, 16), 256, TG_SMEM>>>(p1_w, e2, e2p, 128, 256,
        0, 0, 0L,  0L, 256L,  256L * 128, 128L,  256L * 128,
        nullptr, p1_b, nullptr);

    // 7) energy = e1t @ e2p  [16, 512, 128]
    tgemm<0, false, false><<<dim3(1, 4, 16), 256, TG_SMEM>>>(e1t, e2p, eng, 128, 256,
        0, 0, 0L,  512L * 256, 256L,  256L * 128, 128L,  512L * 128,
        nullptr, nullptr, nullptr);

    // 8) attention = softmax(rowmax - energy)  -> fp16
    softmax_neg<<<16 * 512, 128>>>(eng, atth);

    // 9) oprh = fp16(gamma * (attention @ py2) + x)  — fp16 tensor GEMM
    hgemm9<<<dim3(32, 4, 16), 256, HG_SMEM>>>(atth, py2h, oprh, x, gamma);

    // 10) out = relu(bn3(conv3x3(oprh)))  — fragment-packed fp16 conv
    conv3x3_tc_kernel<<<dim3(16, 4, 16), 256, CONV_SMEM>>>(oprh, (float*)d_out);
}

// round 8
// speedup vs baseline: 7.9665x; 1.1047x over previous
#include <cuda_runtime.h>
#include <cuda_fp16.h>
#include <math.h>
#include <stdint.h>

#define EPS 1e-5f

// ---------------- scratch (device globals; no allocation allowed) ----------------
__device__ float g_py1[16L * 256 * 4096];
__device__ float g_py2[16L * 128 * 4096];
__device__ uint32_t g_py2h[16L * 64 * 4096];     // py2 fp16 packed k-pairs [b][kp][n]
__device__ float g_e1T[16L * 512 * 256];         // e1 transposed [b][d][c]
__device__ float g_e1t[16L * 512 * 256];
__device__ float g_e2 [16L * 256 * 128];
__device__ float g_part[2L * 16 * 512 * 256];    // split-K partials (e1T x2 / e2 x4 fits)
__device__ float g_e2p[16L * 256 * 128];
__device__ float g_eng[16L * 512 * 128];
__device__ __half g_atth[16L * 512 * 128];       // attention, fp16
__device__ __half g_oprh[16L * 512 * 4096];      // conv input, fp16, ch-pair packed
__device__ uint4 g_wfrag[294912];                // conv weight MMA fragments

__device__ float g_s1[256], g_t1[256];
__device__ float g_s2[128], g_t2[128];
__device__ float g_s3[512], g_t3[512];

// ---------------- fold BN (+conv bias) into per-channel scale/shift --------------
__global__ void fold_kernel(const float* __restrict__ q1b, const float* __restrict__ g1,
                            const float* __restrict__ b1,  const float* __restrict__ m1,
                            const float* __restrict__ v1,
                            const float* __restrict__ q2b, const float* __restrict__ g2,
                            const float* __restrict__ b2,  const float* __restrict__ m2,
                            const float* __restrict__ v2,
                            const float* __restrict__ fb,  const float* __restrict__ g3,
                            const float* __restrict__ b3,  const float* __restrict__ m3,
                            const float* __restrict__ v3)
{
    int i = threadIdx.x;
    if (i < 256) {
        float s = g1[i] * rsqrtf(v1[i] + EPS);
        g_s1[i] = s;
        g_t1[i] = s * q1b[i] + b1[i] - m1[i] * s;
    }
    if (i < 128) {
        float s = g2[i] * rsqrtf(v2[i] + EPS);
        g_s2[i] = s;
        g_t2[i] = s * q2b[i] + b2[i] - m2[i] * s;
    }
    if (i < 512) {
        float s = g3[i] * rsqrtf(v3[i] + EPS);
        g_s3[i] = s;
        g_t3[i] = s * fb[i] + b3[i] - m3[i] * s;
    }
}

// ---------------- helpers ---------------------------------------------------------
__device__ __forceinline__ void split_tf32(float f, uint32_t& hi, uint32_t& lo) {
    asm("cvt.rna.tf32.f32 %0, %1;" : "=r"(hi) : "f"(f));
    float r = f - __uint_as_float(hi);
    asm("cvt.rna.tf32.f32 %0, %1;" : "=r"(lo) : "f"(r));
}

__device__ __forceinline__ void mma_tf32(float* c, const uint32_t* a, uint32_t b0, uint32_t b1) {
    asm volatile(
        "mma.sync.aligned.m16n8k8.row.col.f32.tf32.tf32.f32 "
        "{%0,%1,%2,%3}, {%4,%5,%6,%7}, {%8,%9}, {%0,%1,%2,%3};"
        : "+f"(c[0]), "+f"(c[1]), "+f"(c[2]), "+f"(c[3])
        : "r"(a[0]), "r"(a[1]), "r"(a[2]), "r"(a[3]), "r"(b0), "r"(b1));
}

__device__ __forceinline__ void mma_f16(float* c, const uint32_t* a, uint32_t b0, uint32_t b1) {
    asm volatile(
        "mma.sync.aligned.m16n8k16.row.col.f32.f16.f16.f32 "
        "{%0,%1,%2,%3}, {%4,%5,%6,%7}, {%8,%9}, {%0,%1,%2,%3};"
        : "+f"(c[0]), "+f"(c[1]), "+f"(c[2]), "+f"(c[3])
        : "r"(a[0]), "r"(a[1]), "r"(a[2]), "r"(a[3]), "r"(b0), "r"(b1));
}

__device__ __forceinline__ void cp16(uint32_t dst, const void* src) {
    asm volatile("cp.async.cg.shared.global [%0], [%1], 16;" :: "r"(dst), "l"(src));
}

// ---------------- conv weight fragment pack --------------------------------------
__device__ __forceinline__ uint32_t wpair(const float* w, int oc, int icp, int tap) {
    float w0 = w[((long)oc * 512 + 2 * icp) * 9 + tap];
    float w1 = w[((long)oc * 512 + 2 * icp + 1) * 9 + tap];
    __half2 h = __floats2half2_rn(w0, w1);
    return *(uint32_t*)&h;
}

__global__ void wpack(const float* __restrict__ w)
{
    int idx = blockIdx.x * 256 + threadIdx.x;
    if (idx >= 294912) return;
    int tig = idx & 3;
    int grp = (idx >> 2) & 7;
    int mslot = (idx >> 5) & 7;
    int t = idx >> 8;
    int tap = t % 9;
    int t2 = t / 9;
    int stage = t2 & 31;
    int ocblk = t2 >> 5;
    int oc = ocblk * 128 + mslot * 16 + grp;
    int icp = stage * 8 + tig;
    uint4 v;
    v.x = wpair(w, oc,     icp,     tap);
    v.y = wpair(w, oc + 8, icp,     tap);
    v.z = wpair(w, oc,     icp + 4, tap);
    v.w = wpair(w, oc + 8, icp + 4, tap);
    g_wfrag[idx] = v;
}

// ====================== tf32x3 tensor-core GEMM ==================================
// Block 128(M) x 128(N), K chunk 32, 8 warps, warp tile 32x64 = 2x8 m16n8k8.
#define TG_SMEM ((128 * 36 * 2 + 4608 * 2) * 4)   // 73728 B
// EPI: 0 none | 1 +tv[m] | 2 relu(sv[m]v+tv[m]) (+opt packed fp16 copy) | 3 +tv[n]
template <int EPI, bool BKC, bool SPLITK>
__global__ __launch_bounds__(256, 2)
void tgemm(const float* __restrict__ A, const float* __restrict__ B,
           float* __restrict__ C, int N, int K,
           int ntx, int splitChunk, long partStride,
           long aBat, long aSm, long bBat, long bS, long cBat,
           const float* __restrict__ sv, const float* __restrict__ tv,
           __half* __restrict__ h16)
{
    extern __shared__ uint32_t dsm[];
    uint32_t* Ah = dsm;                  // 128 x 36
    uint32_t* Al = Ah + 128 * 36;
    uint32_t* Bh = Al + 128 * 36;        // BKC: [n(128)][36]; !BKC: [k(32)][136]
    uint32_t* Bl = Bh + 4608;

    int tid = threadIdx.x;
    int lane = tid & 31, warp = tid >> 5;
    int warpM = warp >> 1, warpN = warp & 1;
    int grp = lane >> 2, tig = lane & 3;
    int sp = SPLITK ? (blockIdx.x / ntx) : 0;
    int n0 = SPLITK ? (blockIdx.x % ntx) * 128 : blockIdx.x * 128;
    int m0 = blockIdx.y * 128;
    int kBeg = SPLITK ? sp * splitChunk : 0;
    int kEnd = SPLITK ? (kBeg + splitChunk < K ? kBeg + splitChunk : K) : K;
    long ab = (long)blockIdx.z * aBat + (long)m0 * aSm;
    long bb = (long)blockIdx.z * bBat;
    long cb = (long)blockIdx.z * cBat + (SPLITK ? (long)sp * partStride : 0L);

    float acc[2][8][4] = {};

    int kq = tid & 7;
    int mrow = tid >> 3;

    for (int k0 = kBeg; k0 < kEnd; k0 += 32) {
        __syncthreads();
        #pragma unroll
        for (int i = 0; i < 4; i++) {
            int m = mrow + 32 * i;
            float4 v = *(const float4*)&A[ab + (long)m * aSm + k0 + 4 * kq];
            uint32_t h0, l0, h1, l1, h2, l2, h3, l3;
            split_tf32(v.x, h0, l0); split_tf32(v.y, h1, l1);
            split_tf32(v.z, h2, l2); split_tf32(v.w, h3, l3);
            *(uint4*)&Ah[m * 36 + 4 * kq] = make_uint4(h0, h1, h2, h3);
            *(uint4*)&Al[m * 36 + 4 * kq] = make_uint4(l0, l1, l2, l3);
        }
        if (BKC) {
            #pragma unroll
            for (int i = 0; i < 4; i++) {
                int n = mrow + 32 * i;
                float4 v = *(const float4*)&B[bb + (long)(n0 + n) * bS + k0 + 4 * kq];
                uint32_t h0, l0, h1, l1, h2, l2, h3, l3;
                split_tf32(v.x, h0, l0); split_tf32(v.y, h1, l1);
                split_tf32(v.z, h2, l2); split_tf32(v.w, h3, l3);
                *(uint4*)&Bh[n * 36 + 4 * kq] = make_uint4(h0, h1, h2, h3);
                *(uint4*)&Bl[n * 36 + 4 * kq] = make_uint4(l0, l1, l2, l3);
            }
        } else {
            int nq = tid & 31, kk = tid >> 5;
            #pragma unroll
            for (int i = 0; i < 4; i++) {
                int k = kk + 8 * i;
                float4 v = *(const float4*)&B[bb + (long)(k0 + k) * bS + n0 + 4 * nq];
                uint32_t h0, l0, h1, l1, h2, l2, h3, l3;
                split_tf32(v.x, h0, l0); split_tf32(v.y, h1, l1);
                split_tf32(v.z, h2, l2); split_tf32(v.w, h3, l3);
                *(uint4*)&Bh[k * 136 + 4 * nq] = make_uint4(h0, h1, h2, h3);
                *(uint4*)&Bl[k * 136 + 4 * nq] = make_uint4(l0, l1, l2, l3);
            }
        }
        __syncthreads();

        #pragma unroll
        for (int s = 0; s < 4; s++) {
            int k = s * 8 + tig;
            uint32_t ahi[2][4], alo[2][4];
            #pragma unroll
            for (int mt = 0; mt < 2; mt++) {
                int m = warpM * 32 + mt * 16 + grp;
                ahi[mt][0] = Ah[m * 36 + k];           alo[mt][0] = Al[m * 36 + k];
                ahi[mt][1] = Ah[(m + 8) * 36 + k];     alo[mt][1] = Al[(m + 8) * 36 + k];
                ahi[mt][2] = Ah[m * 36 + k + 4];       alo[mt][2] = Al[m * 36 + k + 4];
                ahi[mt][3] = Ah[(m + 8) * 36 + k + 4]; alo[mt][3] = Al[(m + 8) * 36 + k + 4];
            }
            #pragma unroll
            for (int nt = 0; nt < 8; nt++) {
                int n = warpN * 64 + nt * 8 + grp;
                int i0 = BKC ? (n * 36 + k)     : (k * 136 + n);
                int i1 = BKC ? (n * 36 + k + 4) : ((k + 4) * 136 + n);
                uint32_t bh0 = Bh[i0], bl0 = Bl[i0];
                uint32_t bh1 = Bh[i1], bl1 = Bl[i1];
                #pragma unroll
                for (int mt = 0; mt < 2; mt++) {
                    mma_tf32(acc[mt][nt], ahi[mt], bl0, bl1);
                    mma_tf32(acc[mt][nt], alo[mt], bh0, bh1);
                    mma_tf32(acc[mt][nt], ahi[mt], bh0, bh1);
                }
            }
        }
    }

    #pragma unroll
    for (int mt = 0; mt < 2; mt++) {
        #pragma unroll
        for (int h = 0; h < 2; h++) {
            int m = m0 + warpM * 32 + mt * 16 + grp + h * 8;
            float s = 0.f, t = 0.f;
            if (EPI == 1) t = tv[m];
            if (EPI == 2) { s = sv[m]; t = tv[m]; }
            #pragma unroll
            for (int nt = 0; nt < 8; nt++) {
                int n = n0 + warpN * 64 + nt * 8 + tig * 2;
                float v0 = acc[mt][nt][2 * h];
                float v1 = acc[mt][nt][2 * h + 1];
                if (EPI == 1) { v0 += t; v1 += t; }
                else if (EPI == 2) {
                    v0 = fmaxf(s * v0 + t, 0.f);
                    v1 = fmaxf(s * v1 + t, 0.f);
                } else if (EPI == 3) { v0 += tv[n]; v1 += tv[n + 1]; }
                C[cb + (long)m * N + n] = v0;
                C[cb + (long)m * N + n + 1] = v1;
                if (EPI == 2 && h16) {
                    long hb = (long)blockIdx.z * 2L * 64 * N
                            + (long)(m >> 1) * 2 * N + (long)n * 2 + (m & 1);
                    h16[hb]     = __float2half(v0);
                    h16[hb + 2] = __float2half(v1);
                }
            }
        }
    }
}

// ---------------- reduce P split-K partials --------------------------------------
template <int P>
__global__ void reduceP(const float* __restrict__ p, float* __restrict__ o, int n)
{
    int i = blockIdx.x * 256 + threadIdx.x;
    if (i < n) {
        float s = 0.f;
        #pragma unroll
        for (int j = 0; j < P; j++) s += p[i + (long)j * n];
        o[i] = s;
    }
}

// ---------------- softmax of (rowmax - E) -> fp16, rows of 128 -------------------
__global__ void softmax_neg(const float* __restrict__ E, __half* __restrict__ A)
{
    int row = blockIdx.x;
    int t = threadIdx.x;
    __shared__ float red[128];
    float v = E[(long)row * 128 + t];
    red[t] = v;
    __syncthreads();
    for (int s = 64; s > 0; s >>= 1) {
        if (t < s) red[t] = fminf(red[t], red[t + s]);
        __syncthreads();
    }
    float mn = red[0];
    __syncthreads();
    float ex = expf(mn - v);
    red[t] = ex;
    __syncthreads();
    for (int s = 64; s > 0; s >>= 1) {
        if (t < s) red[t] += red[t + s];
        __syncthreads();
    }
    A[(long)row * 128 + t] = __float2half(ex / red[0]);
}

// ---------------- step 9: fp16 GEMM, oprh = fp16(gamma * att@py2 + x) ------------
#define HG_SMEM ((128 * 68 + 64 * 136) * 4)   // 69632 B
__global__ __launch_bounds__(256, 2)
void hgemm9(const __half* __restrict__ att, const uint32_t* __restrict__ py2h,
            __half* __restrict__ oprh, const float* __restrict__ res,
            const float* __restrict__ gptr)
{
    extern __shared__ uint32_t dsm[];
    uint32_t* Ap = dsm;             // [m(128)][kp 64] stride 68
    uint32_t* Bp = dsm + 128 * 68;  // [kp(64)][n 128] stride 136

    int tid = threadIdx.x;
    int lane = tid & 31, warp = tid >> 5;
    int warpM = warp >> 1, warpN = warp & 1;
    int grp = lane >> 2, tig = lane & 3;
    int b = blockIdx.z;
    int m0 = blockIdx.y * 128, n0 = blockIdx.x * 128;

    {
        int r = tid >> 1;
        int hf = tid & 1;
        const uint32_t* src = (const uint32_t*)(att + (long)b * 512 * 128 + (long)(m0 + r) * 128);
        #pragma unroll
        for (int i = 0; i < 8; i++) {
            uint4 v = *(const uint4*)&src[hf * 32 + i * 4];
            *(uint4*)&Ap[r * 68 + hf * 32 + i * 4] = v;
        }
    }
    {
        int kp = tid >> 2;
        int ch = tid & 3;
        const uint32_t* src = py2h + (long)b * 64 * 4096 + (long)kp * 4096 + n0;
        #pragma unroll
        for (int i = 0; i < 8; i++) {
            int c = ch + i * 4;
            uint4 v = *(const uint4*)&src[c * 4];
            *(uint4*)&Bp[kp * 136 + c * 4] = v;
        }
    }
    __syncthreads();

    float acc[2][8][4] = {};
    #pragma unroll
    for (int s = 0; s < 8; s++) {
        int kp0 = s * 8;
        uint32_t a[2][4];
        #pragma unroll
        for (int mt = 0; mt < 2; mt++) {
            int m = warpM * 32 + mt * 16 + grp;
            a[mt][0] = Ap[m * 68 + kp0 + tig];
            a[mt][1] = Ap[(m + 8) * 68 + kp0 + tig];
            a[mt][2] = Ap[m * 68 + kp0 + tig + 4];
            a[mt][3] = Ap[(m + 8) * 68 + kp0 + tig + 4];
        }
        #pragma unroll
        for (int nt = 0; nt < 8; nt++) {
            int n = warpN * 64 + nt * 8 + grp;
            uint32_t b0 = Bp[(kp0 + tig) * 136 + n];
            uint32_t b1 = Bp[(kp0 + tig + 4) * 136 + n];
            #pragma unroll
            for (int mt = 0; mt < 2; mt++)
                mma_f16(acc[mt][nt], a[mt], b0, b1);
        }
    }

    float gm = gptr[0];
    long rb = (long)b * 512 * 4096;
    #pragma unroll
    for (int mt = 0; mt < 2; mt++) {
        #pragma unroll
        for (int h = 0; h < 2; h++) {
            int m = m0 + warpM * 32 + mt * 16 + grp + h * 8;
            #pragma unroll
            for (int nt = 0; nt < 8; nt++) {
                int n = n0 + warpN * 64 + nt * 8 + tig * 2;
                float v0 = gm * acc[mt][nt][2 * h]     + res[rb + (long)m * 4096 + n];
                float v1 = gm * acc[mt][nt][2 * h + 1] + res[rb + (long)m * 4096 + n + 1];
                long base = rb + (long)(m >> 1) * 8192 + (long)n * 2 + (m & 1);
                oprh[base]     = __float2half(v0);
                oprh[base + 2] = __float2half(v1);
            }
        }
    }
}

// ---------------- 3x3 conv, fp16 m16n8k16, 4-stage cp.async pipeline -------------
#define SW_WORDS  9216               // 2304 fragments x 4 words per stage
#define SIN_WORDS (8 * 6 * 76)       // 3648
#define CONV_SMEM (4 * (SW_WORDS + SIN_WORDS) * 4)   // 205824 B

__device__ __forceinline__ void conv_issue(int stage, uint32_t swb, uint32_t sinb,
                                           const __half* __restrict__ inB,
                                           int y0, int ocblk, int tid)
{
    const uint4* wsrc = g_wfrag + (long)(ocblk * 32 + stage) * 2304;
    for (int idx = tid; idx < 2304; idx += 256)
        cp16(swb + (uint32_t)idx * 16, wsrc + idx);
    int icp0 = stage * 8;
    for (int idx = tid; idx < 768; idx += 256) {
        int r  = idx >> 4;
        int ch = idx & 15;
        int icp = r / 6, y = r - icp * 6;
        int gy = y0 - 1 + y;
        if (gy >= 0 && gy < 64)
            cp16(sinb + (uint32_t)(r * 76 + 4 + ch * 4) * 4,
                 inB + (long)(icp0 + icp) * 8192 + (long)gy * 128 + ch * 8);
    }
}

__global__ __launch_bounds__(256, 1)
void conv3x3_tc_kernel(const __half* __restrict__ in, float* __restrict__ out)
{
    extern __shared__ uint32_t smem[];
    uint32_t* sW  = smem;                     // 4 stages
    uint32_t* sIn = smem + 4 * SW_WORDS;      // 4 stages
    uint32_t sw_base  = (uint32_t)__cvta_generic_to_shared(sW);
    uint32_t sin_base = (uint32_t)__cvta_generic_to_shared(sIn);

    int tid = threadIdx.x;
    int lane = tid & 31;
    int warp = tid >> 5;
    int warpM = warp >> 2;          // 0..1 -> 64-oc half
    int warpN = warp & 3;           // 0..3 -> row
    int grp = lane >> 2;
    int tig = lane & 3;

    int b     = blockIdx.z;
    int ocblk = blockIdx.y;
    int oc0   = ocblk * 128;
    int y0    = blockIdx.x * 4;

    const __half* inB = in + (long)b * 256 * 8192;

    for (int i = tid; i < 4 * SIN_WORDS; i += 256) sIn[i] = 0;
    __syncthreads();

    conv_issue(0, sw_base, sin_base, inB, y0, ocblk, tid);
    asm volatile("cp.async.commit_group;");
    conv_issue(1, sw_base + SW_WORDS * 4, sin_base + SIN_WORDS * 4, inB, y0, ocblk, tid);
    asm volatile("cp.async.commit_group;");
    conv_issue(2, sw_base + 2 * SW_WORDS * 4, sin_base + 2 * SIN_WORDS * 4, inB, y0, ocblk, tid);
    asm volatile("cp.async.commit_group;");

    float acc[4][8][4] = {};

    for (int it = 0; it < 32; it++) {
        int buf = it & 3;
        if (it < 29) {
            int nb = (it + 3) & 3;
            conv_issue(it + 3, sw_base + nb * SW_WORDS * 4,
                       sin_base + nb * SIN_WORDS * 4, inB, y0, ocblk, tid);
            asm volatile("cp.async.commit_group;");
            asm volatile("cp.async.wait_group 3;");
        } else if (it == 29) {
            asm volatile("cp.async.wait_group 2;");
        } else if (it == 30) {
            asm volatile("cp.async.wait_group 1;");
        } else {
            asm volatile("cp.async.wait_group 0;");
        }
        __syncthreads();

        const uint32_t* sWb  = sW + buf * SW_WORDS;
        const uint32_t* sInb = sIn + buf * SIN_WORDS;

        #pragma unroll
        for (int ky = 0; ky < 3; ky++) {
            #pragma unroll
            for (int kx = 0; kx < 3; kx++) {
                const int tap = ky * 3 + kx;
                uint4 av[4];
                #pragma unroll
                for (int mt = 0; mt < 4; mt++) {
                    int mslot = warpM * 4 + mt;
                    av[mt] = *(const uint4*)&sWb[((tap * 8 + mslot) * 8 + grp) * 16 + tig * 4];
                }
                const int ir0 = (tig * 6 + warpN + ky) * 76;
                const int ir4 = ((tig + 4) * 6 + warpN + ky) * 76;
                #pragma unroll
                for (int j = 0; j < 8; j++) {
                    int xi = 3 + j * 8 + grp + kx;
                    uint32_t b0 = sInb[ir0 + xi];
                    uint32_t b1 = sInb[ir4 + xi];
                    #pragma unroll
                    for (int mt = 0; mt < 4; mt++)
                        mma_f16(acc[mt][j], (const uint32_t*)&av[mt], b0, b1);
                }
            }
        }
        __syncthreads();
    }

    int y = y0 + warpN;
    #pragma unroll
    for (int mt = 0; mt < 4; mt++) {
        int row = oc0 + warpM * 64 + mt * 16 + grp;
        float s0 = g_s3[row],     t0 = g_t3[row];
        float s8 = g_s3[row + 8], t8 = g_t3[row + 8];
        long base0 = ((long)b * 512 + row) * 4096 + (long)y * 64;
        long base8 = base0 + 8L * 4096;
        #pragma unroll
        for (int j = 0; j < 8; j++) {
            int x = j * 8 + tig * 2;
            out[base0 + x    ] = fmaxf(s0 * acc[mt][j][0] + t0, 0.f);
            out[base0 + x + 1] = fmaxf(s0 * acc[mt][j][1] + t0, 0.f);
            out[base8 + x    ] = fmaxf(s8 * acc[mt][j][2] + t8, 0.f);
            out[base8 + x + 1] = fmaxf(s8 * acc[mt][j][3] + t8, 0.f);
        }
    }
}

// ------------------------------- launcher ---------------------------------------
extern "C" void kernel_launch(void* const* d_in, const int* in_sizes, int n_in,
                              void* d_out, int out_size)
{
    const float* x     = (const float*)d_in[0];
    const float* q1_w  = (const float*)d_in[1];
    const float* q1_b  = (const float*)d_in[2];
    const float* bn1_g = (const float*)d_in[3];
    const float* bn1_b = (const float*)d_in[4];
    const float* bn1_m = (const float*)d_in[5];
    const float* bn1_v = (const float*)d_in[6];
    const float* q2_w  = (const float*)d_in[7];
    const float* q2_b  = (const float*)d_in[8];
    const float* bn2_g = (const float*)d_in[9];
    const float* bn2_b = (const float*)d_in[10];
    const float* bn2_m = (const float*)d_in[11];
    const float* bn2_v = (const float*)d_in[12];
    const float* p1_w  = (const float*)d_in[13];
    const float* p1_b  = (const float*)d_in[14];
    const float* fus_w = (const float*)d_in[15];
    const float* fus_b = (const float*)d_in[16];
    const float* bn3_g = (const float*)d_in[17];
    const float* bn3_b = (const float*)d_in[18];
    const float* bn3_m = (const float*)d_in[19];
    const float* bn3_v = (const float*)d_in[20];
    const float* gamma = (const float*)d_in[21];

    float *py1, *py2, *e1T, *e1t, *e2, *part, *e2p, *eng, *s1, *t1, *s2, *t2;
    uint32_t* py2h;
    __half *atth, *oprh;
    cudaGetSymbolAddress((void**)&py1, g_py1);
    cudaGetSymbolAddress((void**)&py2, g_py2);
    cudaGetSymbolAddress((void**)&py2h, g_py2h);
    cudaGetSymbolAddress((void**)&e1T, g_e1T);
    cudaGetSymbolAddress((void**)&e1t, g_e1t);
    cudaGetSymbolAddress((void**)&e2,  g_e2);
    cudaGetSymbolAddress((void**)&part, g_part);
    cudaGetSymbolAddress((void**)&e2p, g_e2p);
    cudaGetSymbolAddress((void**)&eng, g_eng);
    cudaGetSymbolAddress((void**)&atth, g_atth);
    cudaGetSymbolAddress((void**)&oprh, g_oprh);
    cudaGetSymbolAddress((void**)&s1,  g_s1);
    cudaGetSymbolAddress((void**)&t1,  g_t1);
    cudaGetSymbolAddress((void**)&s2,  g_s2);
    cudaGetSymbolAddress((void**)&t2,  g_t2);

    static bool attr_set = false;
    if (!attr_set) {
        cudaFuncSetAttribute(conv3x3_tc_kernel,
                             cudaFuncAttributeMaxDynamicSharedMemorySize, CONV_SMEM);
        cudaFuncSetAttribute(hgemm9,
                             cudaFuncAttributeMaxDynamicSharedMemorySize, HG_SMEM);
        cudaFuncSetAttribute(tgemm<2, false, false>,
                             cudaFuncAttributeMaxDynamicSharedMemorySize, TG_SMEM);
        cudaFuncSetAttribute(tgemm<0, true, false>,
                             cudaFuncAttributeMaxDynamicSharedMemorySize, TG_SMEM);
        cudaFuncSetAttribute(tgemm<0, true, true>,
                             cudaFuncAttributeMaxDynamicSharedMemorySize, TG_SMEM);
        cudaFuncSetAttribute(tgemm<3, true, false>,
                             cudaFuncAttributeMaxDynamicSharedMemorySize, TG_SMEM);
        cudaFuncSetAttribute(tgemm<1, false, false>,
                             cudaFuncAttributeMaxDynamicSharedMemorySize, TG_SMEM);
        cudaFuncSetAttribute(tgemm<0, false, false>,
                             cudaFuncAttributeMaxDynamicSharedMemorySize, TG_SMEM);
        attr_set = true;
    }

    fold_kernel<<<1, 512>>>(q1_b, bn1_g, bn1_b, bn1_m, bn1_v,
                            q2_b, bn2_g, bn2_b, bn2_m, bn2_v,
                            fus_b, bn3_g, bn3_b, bn3_m, bn3_v);

    wpack<<<(294912 + 255) / 256, 256>>>(fus_w);

    // 1) py1 = relu(bn1(q1_w @ x))  [16, 256, 4096]
    tgemm<2, false, false><<<dim3(32, 2, 16), 256, TG_SMEM>>>(q1_w, x, py1, 4096, 512,
        0, 0, 0L,  0L, 512L,  512L * 4096, 4096L,  256L * 4096, s1, t1, nullptr);

    // 2) py2 = relu(bn2(q2_w @ py1))  [16, 128, 4096]  (+ packed fp16 copy)
    tgemm<2, false, false><<<dim3(32, 1, 16), 256, TG_SMEM>>>(q2_w, py1, py2, 4096, 256,
        0, 0, 0L,  0L, 256L,  256L * 4096, 4096L,  128L * 4096, s2, t2, (__half*)py2h);

    // 3) e1T[d,c] = x @ py1^T  [16, 512, 256]  — split-K x2 + reduce
    tgemm<0, true, true><<<dim3(4, 4, 16), 256, TG_SMEM>>>(x, py1, part, 256, 4096,
        2, 2048, 16L * 512 * 256,
        512L * 4096, 4096L,  256L * 4096, 4096L,  512L * 256,
        nullptr, nullptr, nullptr);
    reduceP<2><<<(16 * 512 * 256 + 255) / 256, 256>>>(part, e1T, 16 * 512 * 256);

    // 4) e1t[d,o] = e1T @ p1_w^T + p1_b[o]  [16, 512, 256]
    tgemm<3, true, false><<<dim3(2, 4, 16), 256, TG_SMEM>>>(e1T, p1_w, e1t, 256, 256,
        0, 0, 0L,  512L * 256, 256L,  0L, 256L,  512L * 256,
        nullptr, p1_b, nullptr);

    // 5) e2 = py1 @ py2^T  [16, 256, 128]  — split-K x4 + reduce
    tgemm<0, true, true><<<dim3(4, 2, 16), 256, TG_SMEM>>>(py1, py2, part, 128, 4096,
        1, 1024, 16L * 256 * 128,
        256L * 4096, 4096L,  128L * 4096, 4096L,  256L * 128,
        nullptr, nullptr, nullptr);
    reduceP<4><<<(16 * 256 * 128 + 255) / 256, 256>>>(part, e2, 16 * 256 * 128);

    // 6) e2p[o,c] = p1_w @ e2 + p1_b[o]  [16, 256, 128]
    tgemm<1, false, false><<<dim3(1, 2, 16), 256, TG_SMEM>>>(p1_w, e2, e2p, 128, 256,
        0, 0, 0L,  0L, 256L,  256L * 128, 128L,  256L * 128,
        nullptr, p1_b, nullptr);

    // 7) energy = e1t @ e2p  [16, 512, 128]
    tgemm<0, false, false><<<dim3(1, 4, 16), 256, TG_SMEM>>>(e1t, e2p, eng, 128, 256,
        0, 0, 0L,  512L * 256, 256L,  256L * 128, 128L,  512L * 128,
        nullptr, nullptr, nullptr);

    // 8) attention = softmax(rowmax - energy)  -> fp16
    softmax_neg<<<16 * 512, 128>>>(eng, atth);

    // 9) oprh = fp16(gamma * (attention @ py2) + x)  — fp16 tensor GEMM
    hgemm9<<<dim3(32, 4, 16), 256, HG_SMEM>>>(atth, py2h, oprh, x, gamma);

    // 10) out = relu(bn3(conv3x3(oprh)))  — 4-stage fragment-packed fp16 conv
    conv3x3_tc_kernel<<<dim3(16, 4, 16), 256, CONV_SMEM>>>(oprh, (float*)d_out);
}

// round 9
// speedup vs baseline: 9.3602x; 1.1749x over previous
#include <cuda_runtime.h>
#include <cuda_fp16.h>
#include <math.h>
#include <stdint.h>

#define EPS 1e-5f

// ---------------- scratch (device globals; no allocation allowed) ----------------
__device__ float g_py1[16L * 256 * 4096];
__device__ float g_py2[16L * 128 * 4096];
__device__ uint32_t g_py2h[16L * 64 * 4096];     // py2 fp16 packed k-pairs [b][kp][n]
__device__ float g_e1T[16L * 512 * 256];
__device__ float g_e1t[16L * 512 * 256];
__device__ float g_e2 [16L * 256 * 128];
__device__ float g_part[2L * 16 * 512 * 256];    // split-K partials
__device__ float g_e2p[16L * 256 * 128];
__device__ float g_eng[16L * 512 * 128];
__device__ __half g_atth[16L * 512 * 128];
__device__ __half g_oprh[16L * 512 * 4096];      // conv input, fp16, ch-pair packed
__device__ uint4 g_wfrag[294912];                // conv weight MMA fragments

__device__ float g_s1[256], g_t1[256];
__device__ float g_s2[128], g_t2[128];
__device__ float g_s3[512], g_t3[512];

// ---------------- fold BN (+conv bias) into per-channel scale/shift --------------
__global__ void fold_kernel(const float* __restrict__ q1b, const float* __restrict__ g1,
                            const float* __restrict__ b1,  const float* __restrict__ m1,
                            const float* __restrict__ v1,
                            const float* __restrict__ q2b, const float* __restrict__ g2,
                            const float* __restrict__ b2,  const float* __restrict__ m2,
                            const float* __restrict__ v2,
                            const float* __restrict__ fb,  const float* __restrict__ g3,
                            const float* __restrict__ b3,  const float* __restrict__ m3,
                            const float* __restrict__ v3)
{
    int i = threadIdx.x;
    if (i < 256) {
        float s = g1[i] * rsqrtf(v1[i] + EPS);
        g_s1[i] = s;
        g_t1[i] = s * q1b[i] + b1[i] - m1[i] * s;
    }
    if (i < 128) {
        float s = g2[i] * rsqrtf(v2[i] + EPS);
        g_s2[i] = s;
        g_t2[i] = s * q2b[i] + b2[i] - m2[i] * s;
    }
    if (i < 512) {
        float s = g3[i] * rsqrtf(v3[i] + EPS);
        g_s3[i] = s;
        g_t3[i] = s * fb[i] + b3[i] - m3[i] * s;
    }
}

// ---------------- helpers ---------------------------------------------------------
__device__ __forceinline__ void mma_f16(float* c, const uint32_t* a, uint32_t b0, uint32_t b1) {
    asm volatile(
        "mma.sync.aligned.m16n8k16.row.col.f32.f16.f16.f32 "
        "{%0,%1,%2,%3}, {%4,%5,%6,%7}, {%8,%9}, {%0,%1,%2,%3};"
        : "+f"(c[0]), "+f"(c[1]), "+f"(c[2]), "+f"(c[3])
        : "r"(a[0]), "r"(a[1]), "r"(a[2]), "r"(a[3]), "r"(b0), "r"(b1));
}

__device__ __forceinline__ void cp16(uint32_t dst, const void* src) {
    asm volatile("cp.async.cg.shared.global [%0], [%1], 16;" :: "r"(dst), "l"(src));
}

// pack two floats into hi half2 + lo half2 (2-term fp16 split)
__device__ __forceinline__ uint32_t split2(float a, float b, uint32_t& lo) {
    __half ha = __float2half_rn(a), hb = __float2half_rn(b);
    float ra = a - __half2float(ha);
    float rb = b - __half2float(hb);
    __half2 h = __halves2half2(ha, hb);
    __half2 l = __floats2half2_rn(ra, rb);
    lo = *(uint32_t*)&l;
    return *(uint32_t*)&h;
}

// ---------------- conv weight fragment pack --------------------------------------
__device__ __forceinline__ uint32_t wpair(const float* w, int oc, int icp, int tap) {
    float w0 = w[((long)oc * 512 + 2 * icp) * 9 + tap];
    float w1 = w[((long)oc * 512 + 2 * icp + 1) * 9 + tap];
    __half2 h = __floats2half2_rn(w0, w1);
    return *(uint32_t*)&h;
}

__global__ void wpack(const float* __restrict__ w)
{
    int idx = blockIdx.x * 256 + threadIdx.x;
    if (idx >= 294912) return;
    int tig = idx & 3;
    int grp = (idx >> 2) & 7;
    int mslot = (idx >> 5) & 7;
    int t = idx >> 8;
    int tap = t % 9;
    int t2 = t / 9;
    int stage = t2 & 31;
    int ocblk = t2 >> 5;
    int oc = ocblk * 128 + mslot * 16 + grp;
    int icp = stage * 8 + tig;
    uint4 v;
    v.x = wpair(w, oc,     icp,     tap);
    v.y = wpair(w, oc + 8, icp,     tap);
    v.z = wpair(w, oc,     icp + 4, tap);
    v.w = wpair(w, oc + 8, icp + 4, tap);
    g_wfrag[idx] = v;
}

// ====================== fp16x2-split tensor-core GEMM ============================
// ~fp32 precision: A=Ah+Al, B=Bh+Bl (fp16 each); C += Ah·Bl + Al·Bh + Ah·Bh.
// Inputs pre-scaled by exact powers of 2 (scA/scB), output by scO = 1/(scA*scB).
// Block 128(M) x 128(N), K chunk 32 (16 k-pairs), 8 warps, warp 32x64 = 2x8 m16n8k16.
// A smem [m(128)][kp stride 20]; B: BKC -> [n(128)][kp stride 20],
//                                 !BKC -> k-major [kp(16)][n stride 136].
// EPI: 0 none | 1 +tv[m] | 2 relu(sv[m]v+tv[m]) (+opt packed fp16 copy) | 3 +tv[n]
template <int EPI, bool BKC, bool SPLITK>
__global__ __launch_bounds__(256, 2)
void sgemm16(const float* __restrict__ A, const float* __restrict__ B,
             float* __restrict__ C, int N, int K,
             int ntx, int splitChunk, long partStride,
             long aBat, long aSm, long bBat, long bS, long cBat,
             float scA, float scB, float scO,
             const float* __restrict__ sv, const float* __restrict__ tv,
             __half* __restrict__ h16)
{
    __shared__ uint32_t Ah[128 * 20], Al[128 * 20];
    __shared__ uint32_t Bh[2560], Bl[2560];

    int tid = threadIdx.x;
    int lane = tid & 31, warp = tid >> 5;
    int warpM = warp >> 1, warpN = warp & 1;
    int grp = lane >> 2, tig = lane & 3;
    int sp = SPLITK ? (blockIdx.x / ntx) : 0;
    int n0 = SPLITK ? (blockIdx.x % ntx) * 128 : blockIdx.x * 128;
    int m0 = blockIdx.y * 128;
    int kBeg = SPLITK ? sp * splitChunk : 0;
    int kEnd = SPLITK ? (kBeg + splitChunk < K ? kBeg + splitChunk : K) : K;
    long ab = (long)blockIdx.z * aBat + (long)m0 * aSm;
    long bb = (long)blockIdx.z * bBat;
    long cb = (long)blockIdx.z * cBat + (SPLITK ? (long)sp * partStride : 0L);

    float acc[2][8][4] = {};

    int kq = tid & 7;        // k chunk of 4 floats = 2 kp
    int mrow = tid >> 3;     // 0..31

    for (int k0 = kBeg; k0 < kEnd; k0 += 32) {
        __syncthreads();
        #pragma unroll
        for (int i = 0; i < 4; i++) {
            int m = mrow + 32 * i;
            float4 v = *(const float4*)&A[ab + (long)m * aSm + k0 + 4 * kq];
            uint32_t l0, l1;
            uint32_t h0 = split2(v.x * scA, v.y * scA, l0);
            uint32_t h1 = split2(v.z * scA, v.w * scA, l1);
            *(uint2*)&Ah[m * 20 + 2 * kq] = make_uint2(h0, h1);
            *(uint2*)&Al[m * 20 + 2 * kq] = make_uint2(l0, l1);
        }
        if (BKC) {
            #pragma unroll
            for (int i = 0; i < 4; i++) {
                int n = mrow + 32 * i;
                float4 v = *(const float4*)&B[bb + (long)(n0 + n) * bS + k0 + 4 * kq];
                uint32_t l0, l1;
                uint32_t h0 = split2(v.x * scB, v.y * scB, l0);
                uint32_t h1 = split2(v.z * scB, v.w * scB, l1);
                *(uint2*)&Bh[n * 20 + 2 * kq] = make_uint2(h0, h1);
                *(uint2*)&Bl[n * 20 + 2 * kq] = make_uint2(l0, l1);
            }
        } else {
            int nq = tid & 31, kk = tid >> 5;
            #pragma unroll
            for (int i = 0; i < 2; i++) {
                int kp = kk + 8 * i;
                float4 r0 = *(const float4*)&B[bb + (long)(k0 + 2 * kp) * bS + n0 + 4 * nq];
                float4 r1 = *(const float4*)&B[bb + (long)(k0 + 2 * kp + 1) * bS + n0 + 4 * nq];
                uint4 wh, wl;
                wh.x = split2(r0.x * scB, r1.x * scB, wl.x);
                wh.y = split2(r0.y * scB, r1.y * scB, wl.y);
                wh.z = split2(r0.z * scB, r1.z * scB, wl.z);
                wh.w = split2(r0.w * scB, r1.w * scB, wl.w);
                *(uint4*)&Bh[kp * 136 + 4 * nq] = wh;
                *(uint4*)&Bl[kp * 136 + 4 * nq] = wl;
            }
        }
        __syncthreads();

        #pragma unroll
        for (int s = 0; s < 2; s++) {
            int kp0 = s * 8;
            uint32_t ahi[2][4], alo[2][4];
            #pragma unroll
            for (int mt = 0; mt < 2; mt++) {
                int m = warpM * 32 + mt * 16 + grp;
                ahi[mt][0] = Ah[m * 20 + kp0 + tig];           alo[mt][0] = Al[m * 20 + kp0 + tig];
                ahi[mt][1] = Ah[(m + 8) * 20 + kp0 + tig];     alo[mt][1] = Al[(m + 8) * 20 + kp0 + tig];
                ahi[mt][2] = Ah[m * 20 + kp0 + tig + 4];       alo[mt][2] = Al[m * 20 + kp0 + tig + 4];
                ahi[mt][3] = Ah[(m + 8) * 20 + kp0 + tig + 4]; alo[mt][3] = Al[(m + 8) * 20 + kp0 + tig + 4];
            }
            #pragma unroll
            for (int nt = 0; nt < 8; nt++) {
                int n = warpN * 64 + nt * 8 + grp;
                int i0 = BKC ? (n * 20 + kp0 + tig)     : ((kp0 + tig) * 136 + n);
                int i1 = BKC ? (n * 20 + kp0 + tig + 4) : ((kp0 + tig + 4) * 136 + n);
                uint32_t bh0 = Bh[i0], bl0 = Bl[i0];
                uint32_t bh1 = Bh[i1], bl1 = Bl[i1];
                #pragma unroll
                for (int mt = 0; mt < 2; mt++) {
                    mma_f16(acc[mt][nt], ahi[mt], bl0, bl1);
                    mma_f16(acc[mt][nt], alo[mt], bh0, bh1);
                    mma_f16(acc[mt][nt], ahi[mt], bh0, bh1);
                }
            }
        }
    }

    #pragma unroll
    for (int mt = 0; mt < 2; mt++) {
        #pragma unroll
        for (int h = 0; h < 2; h++) {
            int m = m0 + warpM * 32 + mt * 16 + grp + h * 8;
            float s = 0.f, t = 0.f;
            if (EPI == 1) t = tv[m];
            if (EPI == 2) { s = sv[m]; t = tv[m]; }
            #pragma unroll
            for (int nt = 0; nt < 8; nt++) {
                int n = n0 + warpN * 64 + nt * 8 + tig * 2;
                float v0 = acc[mt][nt][2 * h] * scO;
                float v1 = acc[mt][nt][2 * h + 1] * scO;
                if (EPI == 1) { v0 += t; v1 += t; }
                else if (EPI == 2) {
                    v0 = fmaxf(s * v0 + t, 0.f);
                    v1 = fmaxf(s * v1 + t, 0.f);
                } else if (EPI == 3) { v0 += tv[n]; v1 += tv[n + 1]; }
                C[cb + (long)m * N + n] = v0;
                C[cb + (long)m * N + n + 1] = v1;
                if (EPI == 2 && h16) {
                    long hb = (long)blockIdx.z * 2L * 64 * N
                            + (long)(m >> 1) * 2 * N + (long)n * 2 + (m & 1);
                    h16[hb]     = __float2half(v0);
                    h16[hb + 2] = __float2half(v1);
                }
            }
        }
    }
}

// ---------------- reduce P split-K partials --------------------------------------
template <int P>
__global__ void reduceP(const float* __restrict__ p, float* __restrict__ o, int n)
{
    int i = blockIdx.x * 256 + threadIdx.x;
    if (i < n) {
        float s = 0.f;
        #pragma unroll
        for (int j = 0; j < P; j++) s += p[i + (long)j * n];
        o[i] = s;
    }
}

// ---------------- softmax of (rowmax - E) -> fp16, rows of 128 -------------------
__global__ void softmax_neg(const float* __restrict__ E, __half* __restrict__ A)
{
    int row = blockIdx.x;
    int t = threadIdx.x;
    __shared__ float red[128];
    float v = E[(long)row * 128 + t];
    red[t] = v;
    __syncthreads();
    for (int s = 64; s > 0; s >>= 1) {
        if (t < s) red[t] = fminf(red[t], red[t + s]);
        __syncthreads();
    }
    float mn = red[0];
    __syncthreads();
    float ex = expf(mn - v);
    red[t] = ex;
    __syncthreads();
    for (int s = 64; s > 0; s >>= 1) {
        if (t < s) red[t] += red[t + s];
        __syncthreads();
    }
    A[(long)row * 128 + t] = __float2half(ex / red[0]);
}

// ---------------- step 9: fp16 GEMM, oprh = fp16(gamma * att@py2 + x) ------------
#define HG_SMEM ((128 * 68 + 64 * 136) * 4)   // 69632 B
__global__ __launch_bounds__(256, 2)
void hgemm9(const __half* __restrict__ att, const uint32_t* __restrict__ py2h,
            __half* __restrict__ oprh, const float* __restrict__ res,
            const float* __restrict__ gptr)
{
    extern __shared__ uint32_t dsm[];
    uint32_t* Ap = dsm;             // [m(128)][kp 64] stride 68
    uint32_t* Bp = dsm + 128 * 68;  // [kp(64)][n 128] stride 136

    int tid = threadIdx.x;
    int lane = tid & 31, warp = tid >> 5;
    int warpM = warp >> 1, warpN = warp & 1;
    int grp = lane >> 2, tig = lane & 3;
    int b = blockIdx.z;
    int m0 = blockIdx.y * 128, n0 = blockIdx.x * 128;

    {
        int r = tid >> 1;
        int hf = tid & 1;
        const uint32_t* src = (const uint32_t*)(att + (long)b * 512 * 128 + (long)(m0 + r) * 128);
        #pragma unroll
        for (int i = 0; i < 8; i++) {
            uint4 v = *(const uint4*)&src[hf * 32 + i * 4];
            *(uint4*)&Ap[r * 68 + hf * 32 + i * 4] = v;
        }
    }
    {
        int kp = tid >> 2;
        int ch = tid & 3;
        const uint32_t* src = py2h + (long)b * 64 * 4096 + (long)kp * 4096 + n0;
        #pragma unroll
        for (int i = 0; i < 8; i++) {
            int c = ch + i * 4;
            uint4 v = *(const uint4*)&src[c * 4];
            *(uint4*)&Bp[kp * 136 + c * 4] = v;
        }
    }
    __syncthreads();

    float acc[2][8][4] = {};
    #pragma unroll
    for (int s = 0; s < 8; s++) {
        int kp0 = s * 8;
        uint32_t a[2][4];
        #pragma unroll
        for (int mt = 0; mt < 2; mt++) {
            int m = warpM * 32 + mt * 16 + grp;
            a[mt][0] = Ap[m * 68 + kp0 + tig];
            a[mt][1] = Ap[(m + 8) * 68 + kp0 + tig];
            a[mt][2] = Ap[m * 68 + kp0 + tig + 4];
            a[mt][3] = Ap[(m + 8) * 68 + kp0 + tig + 4];
        }
        #pragma unroll
        for (int nt = 0; nt < 8; nt++) {
            int n = warpN * 64 + nt * 8 + grp;
            uint32_t b0 = Bp[(kp0 + tig) * 136 + n];
            uint32_t b1 = Bp[(kp0 + tig + 4) * 136 + n];
            #pragma unroll
            for (int mt = 0; mt < 2; mt++)
                mma_f16(acc[mt][nt], a[mt], b0, b1);
        }
    }

    float gm = gptr[0];
    long rb = (long)b * 512 * 4096;
    #pragma unroll
    for (int mt = 0; mt < 2; mt++) {
        #pragma unroll
        for (int h = 0; h < 2; h++) {
            int m = m0 + warpM * 32 + mt * 16 + grp + h * 8;
            #pragma unroll
            for (int nt = 0; nt < 8; nt++) {
                int n = n0 + warpN * 64 + nt * 8 + tig * 2;
                float v0 = gm * acc[mt][nt][2 * h]     + res[rb + (long)m * 4096 + n];
                float v1 = gm * acc[mt][nt][2 * h + 1] + res[rb + (long)m * 4096 + n + 1];
                long base = rb + (long)(m >> 1) * 8192 + (long)n * 2 + (m & 1);
                oprh[base]     = __float2half(v0);
                oprh[base + 2] = __float2half(v1);
            }
        }
    }
}

// ---------------- 3x3 conv, fp16 m16n8k16, 4-stage pipeline, 16 warps ------------
// Block: 512 thr = 16 warps (warpM 0..3 -> 32-oc quarter, warpN 0..3 -> row).
#define SW_WORDS  9216               // 2304 fragments x 4 words per stage
#define SIN_WORDS (8 * 6 * 76)       // 3648
#define CONV_SMEM (4 * (SW_WORDS + SIN_WORDS) * 4)   // 205824 B

__device__ __forceinline__ void conv_issue(int stage, uint32_t swb, uint32_t sinb,
                                           const __half* __restrict__ inB,
                                           int y0, int ocblk, int tid)
{
    const uint4* wsrc = g_wfrag + (long)(ocblk * 32 + stage) * 2304;
    for (int idx = tid; idx < 2304; idx += 512)
        cp16(swb + (uint32_t)idx * 16, wsrc + idx);
    int icp0 = stage * 8;
    for (int idx = tid; idx < 768; idx += 512) {
        int r  = idx >> 4;
        int ch = idx & 15;
        int icp = r / 6, y = r - icp * 6;
        int gy = y0 - 1 + y;
        if (gy >= 0 && gy < 64)
            cp16(sinb + (uint32_t)(r * 76 + 4 + ch * 4) * 4,
                 inB + (long)(icp0 + icp) * 8192 + (long)gy * 128 + ch * 8);
    }
}

__global__ __launch_bounds__(512, 1)
void conv3x3_tc_kernel(const __half* __restrict__ in, float* __restrict__ out)
{
    extern __shared__ uint32_t smem[];
    uint32_t* sW  = smem;                     // 4 stages
    uint32_t* sIn = smem + 4 * SW_WORDS;      // 4 stages
    uint32_t sw_base  = (uint32_t)__cvta_generic_to_shared(sW);
    uint32_t sin_base = (uint32_t)__cvta_generic_to_shared(sIn);

    int tid = threadIdx.x;
    int lane = tid & 31;
    int warp = tid >> 5;            // 0..15
    int warpM = warp >> 2;          // 0..3 -> 32-oc quarter
    int warpN = warp & 3;           // 0..3 -> row
    int grp = lane >> 2;
    int tig = lane & 3;

    int b     = blockIdx.z;
    int ocblk = blockIdx.y;
    int oc0   = ocblk * 128;
    int y0    = blockIdx.x * 4;

    const __half* inB = in + (long)b * 256 * 8192;

    for (int i = tid; i < 4 * SIN_WORDS; i += 512) sIn[i] = 0;
    __syncthreads();

    conv_issue(0, sw_base, sin_base, inB, y0, ocblk, tid);
    asm volatile("cp.async.commit_group;");
    conv_issue(1, sw_base + SW_WORDS * 4, sin_base + SIN_WORDS * 4, inB, y0, ocblk, tid);
    asm volatile("cp.async.commit_group;");
    conv_issue(2, sw_base + 2 * SW_WORDS * 4, sin_base + 2 * SIN_WORDS * 4, inB, y0, ocblk, tid);
    asm volatile("cp.async.commit_group;");

    float acc[2][8][4] = {};

    for (int it = 0; it < 32; it++) {
        int buf = it & 3;
        if (it < 29) {
            int nb = (it + 3) & 3;
            conv_issue(it + 3, sw_base + nb * SW_WORDS * 4,
                       sin_base + nb * SIN_WORDS * 4, inB, y0, ocblk, tid);
            asm volatile("cp.async.commit_group;");
            asm volatile("cp.async.wait_group 3;");
        } else if (it == 29) {
            asm volatile("cp.async.wait_group 2;");
        } else if (it == 30) {
            asm volatile("cp.async.wait_group 1;");
        } else {
            asm volatile("cp.async.wait_group 0;");
        }
        __syncthreads();

        const uint32_t* sWb  = sW + buf * SW_WORDS;
        const uint32_t* sInb = sIn + buf * SIN_WORDS;

        #pragma unroll
        for (int ky = 0; ky < 3; ky++) {
            #pragma unroll
            for (int kx = 0; kx < 3; kx++) {
                const int tap = ky * 3 + kx;
                uint4 av[2];
                #pragma unroll
                for (int mt = 0; mt < 2; mt++) {
                    int mslot = warpM * 2 + mt;
                    av[mt] = *(const uint4*)&sWb[((tap * 8 + mslot) * 8 + grp) * 16 + tig * 4];
                }
                const int ir0 = (tig * 6 + warpN + ky) * 76;
                const int ir4 = ((tig + 4) * 6 + warpN + ky) * 76;
                #pragma unroll
                for (int j = 0; j < 8; j++) {
                    int xi = 3 + j * 8 + grp + kx;
                    uint32_t b0 = sInb[ir0 + xi];
                    uint32_t b1 = sInb[ir4 + xi];
                    #pragma unroll
                    for (int mt = 0; mt < 2; mt++)
                        mma_f16(acc[mt][j], (const uint32_t*)&av[mt], b0, b1);
                }
            }
        }
        __syncthreads();
    }

    int y = y0 + warpN;
    #pragma unroll
    for (int mt = 0; mt < 2; mt++) {
        int row = oc0 + warpM * 32 + mt * 16 + grp;
        float s0 = g_s3[row],     t0 = g_t3[row];
        float s8 = g_s3[row + 8], t8 = g_t3[row + 8];
        long base0 = ((long)b * 512 + row) * 4096 + (long)y * 64;
        long base8 = base0 + 8L * 4096;
        #pragma unroll
        for (int j = 0; j < 8; j++) {
            int x = j * 8 + tig * 2;
            out[base0 + x    ] = fmaxf(s0 * acc[mt][j][0] + t0, 0.f);
            out[base0 + x + 1] = fmaxf(s0 * acc[mt][j][1] + t0, 0.f);
            out[base8 + x    ] = fmaxf(s8 * acc[mt][j][2] + t8, 0.f);
            out[base8 + x + 1] = fmaxf(s8 * acc[mt][j][3] + t8, 0.f);
        }
    }
}

// ------------------------------- launcher ---------------------------------------
extern "C" void kernel_launch(void* const* d_in, const int* in_sizes, int n_in,
                              void* d_out, int out_size)
{
    const float* x     = (const float*)d_in[0];
    const float* q1_w  = (const float*)d_in[1];
    const float* q1_b  = (const float*)d_in[2];
    const float* bn1_g = (const float*)d_in[3];
    const float* bn1_b = (const float*)d_in[4];
    const float* bn1_m = (const float*)d_in[5];
    const float* bn1_v = (const float*)d_in[6];
    const float* q2_w  = (const float*)d_in[7];
    const float* q2_b  = (const float*)d_in[8];
    const float* bn2_g = (const float*)d_in[9];
    const float* bn2_b = (const float*)d_in[10];
    const float* bn2_m = (const float*)d_in[11];
    const float* bn2_v = (const float*)d_in[12];
    const float* p1_w  = (const float*)d_in[13];
    const float* p1_b  = (const float*)d_in[14];
    const float* fus_w = (const float*)d_in[15];
    const float* fus_b = (const float*)d_in[16];
    const float* bn3_g = (const float*)d_in[17];
    const float* bn3_b = (const float*)d_in[18];
    const float* bn3_m = (const float*)d_in[19];
    const float* bn3_v = (const float*)d_in[20];
    const float* gamma = (const float*)d_in[21];

    float *py1, *py2, *e1T, *e1t, *e2, *part, *e2p, *eng, *s1, *t1, *s2, *t2;
    uint32_t* py2h;
    __half *atth, *oprh;
    cudaGetSymbolAddress((void**)&py1, g_py1);
    cudaGetSymbolAddress((void**)&py2, g_py2);
    cudaGetSymbolAddress((void**)&py2h, g_py2h);
    cudaGetSymbolAddress((void**)&e1T, g_e1T);
    cudaGetSymbolAddress((void**)&e1t, g_e1t);
    cudaGetSymbolAddress((void**)&e2,  g_e2);
    cudaGetSymbolAddress((void**)&part, g_part);
    cudaGetSymbolAddress((void**)&e2p, g_e2p);
    cudaGetSymbolAddress((void**)&eng, g_eng);
    cudaGetSymbolAddress((void**)&atth, g_atth);
    cudaGetSymbolAddress((void**)&oprh, g_oprh);
    cudaGetSymbolAddress((void**)&s1,  g_s1);
    cudaGetSymbolAddress((void**)&t1,  g_t1);
    cudaGetSymbolAddress((void**)&s2,  g_s2);
    cudaGetSymbolAddress((void**)&t2,  g_t2);

    static bool attr_set = false;
    if (!attr_set) {
        cudaFuncSetAttribute(conv3x3_tc_kernel,
                             cudaFuncAttributeMaxDynamicSharedMemorySize, CONV_SMEM);
        cudaFuncSetAttribute(hgemm9,
                             cudaFuncAttributeMaxDynamicSharedMemorySize, HG_SMEM);
        attr_set = true;
    }

    fold_kernel<<<1, 512>>>(q1_b, bn1_g, bn1_b, bn1_m, bn1_v,
                            q2_b, bn2_g, bn2_b, bn2_m, bn2_v,
                            fus_b, bn3_g, bn3_b, bn3_m, bn3_v);

    wpack<<<(294912 + 255) / 256, 256>>>(fus_w);

    // 1) py1 = relu(bn1(q1_w @ x))  [16, 256, 4096]
    sgemm16<2, false, false><<<dim3(32, 2, 16), 256>>>(q1_w, x, py1, 4096, 512,
        0, 0, 0L,  0L, 512L,  512L * 4096, 4096L,  256L * 4096,
        32.f, 8.f, 1.f / 256.f, s1, t1, nullptr);

    // 2) py2 = relu(bn2(q2_w @ py1))  [16, 128, 4096]  (+ packed fp16 copy)
    sgemm16<2, false, false><<<dim3(32, 1, 16), 256>>>(q2_w, py1, py2, 4096, 256,
        0, 0, 0L,  0L, 256L,  256L * 4096, 4096L,  128L * 4096,
        32.f, 2.f, 1.f / 64.f, s2, t2, (__half*)py2h);

    // 3) e1T[d,c] = x @ py1^T  [16, 512, 256]  — split-K x2 + reduce
    sgemm16<0, true, true><<<dim3(4, 4, 16), 256>>>(x, py1, part, 256, 4096,
        2, 2048, 16L * 512 * 256,
        512L * 4096, 4096L,  256L * 4096, 4096L,  512L * 256,
        8.f, 2.f, 1.f / 16.f, nullptr, nullptr, nullptr);
    reduceP<2><<<(16 * 512 * 256 + 255) / 256, 256>>>(part, e1T, 16 * 512 * 256);

    // 4) e1t[d,o] = e1T @ p1_w^T + p1_b[o]  [16, 512, 256]
    sgemm16<3, true, false><<<dim3(2, 4, 16), 256>>>(e1T, p1_w, e1t, 256, 256,
        0, 0, 0L,  512L * 256, 256L,  0L, 256L,  512L * 256,
        4.f, 32.f, 1.f / 128.f, nullptr, p1_b, nullptr);

    // 5) e2 = py1 @ py2^T  [16, 256, 128]  — split-K x4 + reduce
    sgemm16<0, true, true><<<dim3(4, 2, 16), 256>>>(py1, py2, part, 128, 4096,
        1, 1024, 16L * 256 * 128,
        256L * 4096, 4096L,  128L * 4096, 4096L,  256L * 128,
        2.f, 2.f, 1.f / 4.f, nullptr, nullptr, nullptr);
    reduceP<4><<<(16 * 256 * 128 + 255) / 256, 256>>>(part, e2, 16 * 256 * 128);

    // 6) e2p[o,c] = p1_w @ e2 + p1_b[o]  [16, 256, 128]
    sgemm16<1, false, false><<<dim3(1, 2, 16), 256>>>(p1_w, e2, e2p, 128, 256,
        0, 0, 0L,  0L, 256L,  256L * 128, 128L,  256L * 128,
        32.f, 1.f, 1.f / 32.f, nullptr, p1_b, nullptr);

    // 7) energy = e1t @ e2p  [16, 512, 128]
    sgemm16<0, false, false><<<dim3(1, 4, 16), 256>>>(e1t, e2p, eng, 128, 256,
        0, 0, 0L,  512L * 256, 256L,  256L * 128, 128L,  512L * 128,
        8.f, 1.f, 1.f / 8.f, nullptr, nullptr, nullptr);

    // 8) attention = softmax(rowmax - energy)  -> fp16
    softmax_neg<<<16 * 512, 128>>>(eng, atth);

    // 9) oprh = fp16(gamma * (attention @ py2) + x)  — fp16 tensor GEMM
    hgemm9<<<dim3(32, 4, 16), 256, HG_SMEM>>>(atth, py2h, oprh, x, gamma);

    // 10) out = relu(bn3(conv3x3(oprh)))  — 16-warp 4-stage fp16 conv
    conv3x3_tc_kernel<<<dim3(16, 4, 16), 512, CONV_SMEM>>>(oprh, (float*)d_out);
}

// round 10
// speedup vs baseline: 9.4393x; 1.0084x over previous
#include <cuda_runtime.h>
#include <cuda_fp16.h>
#include <math.h>
#include <stdint.h>

#define EPS 1e-5f

// ---------------- scratch (device globals; no allocation allowed) ----------------
__device__ float g_py1[16L * 256 * 4096];
__device__ float g_py2[16L * 128 * 4096];
__device__ uint32_t g_py2h[16L * 64 * 4096];     // py2 fp16 packed k-pairs [b][kp][n]
__device__ float g_e1T[16L * 512 * 256];
__device__ float g_e1t[16L * 512 * 256];
__device__ float g_e2 [16L * 256 * 128];
__device__ float g_part[2L * 16 * 512 * 256];    // split-K partials
__device__ float g_e2p[16L * 256 * 128];
__device__ float g_eng[16L * 512 * 128];
__device__ __half g_atth[16L * 512 * 128];
__device__ __half g_oprh[16L * 512 * 4096];      // conv input, fp16, ch-pair packed
__device__ uint4 g_wfrag[294912];                // conv weight MMA fragments (64-oc blocks)

__device__ float g_s1[256], g_t1[256];
__device__ float g_s2[128], g_t2[128];
__device__ float g_s3[512], g_t3[512];

// ---------------- fold BN (+conv bias) into per-channel scale/shift --------------
__global__ void fold_kernel(const float* __restrict__ q1b, const float* __restrict__ g1,
                            const float* __restrict__ b1,  const float* __restrict__ m1,
                            const float* __restrict__ v1,
                            const float* __restrict__ q2b, const float* __restrict__ g2,
                            const float* __restrict__ b2,  const float* __restrict__ m2,
                            const float* __restrict__ v2,
                            const float* __restrict__ fb,  const float* __restrict__ g3,
                            const float* __restrict__ b3,  const float* __restrict__ m3,
                            const float* __restrict__ v3)
{
    int i = threadIdx.x;
    if (i < 256) {
        float s = g1[i] * rsqrtf(v1[i] + EPS);
        g_s1[i] = s;
        g_t1[i] = s * q1b[i] + b1[i] - m1[i] * s;
    }
    if (i < 128) {
        float s = g2[i] * rsqrtf(v2[i] + EPS);
        g_s2[i] = s;
        g_t2[i] = s * q2b[i] + b2[i] - m2[i] * s;
    }
    if (i < 512) {
        float s = g3[i] * rsqrtf(v3[i] + EPS);
        g_s3[i] = s;
        g_t3[i] = s * fb[i] + b3[i] - m3[i] * s;
    }
}

// ---------------- helpers ---------------------------------------------------------
__device__ __forceinline__ void mma_f16(float* c, const uint32_t* a, uint32_t b0, uint32_t b1) {
    asm volatile(
        "mma.sync.aligned.m16n8k16.row.col.f32.f16.f16.f32 "
        "{%0,%1,%2,%3}, {%4,%5,%6,%7}, {%8,%9}, {%0,%1,%2,%3};"
        : "+f"(c[0]), "+f"(c[1]), "+f"(c[2]), "+f"(c[3])
        : "r"(a[0]), "r"(a[1]), "r"(a[2]), "r"(a[3]), "r"(b0), "r"(b1));
}

__device__ __forceinline__ void cp16(uint32_t dst, const void* src) {
    asm volatile("cp.async.cg.shared.global [%0], [%1], 16;" :: "r"(dst), "l"(src));
}

// pack two floats into hi half2 + lo half2 (2-term fp16 split)
__device__ __forceinline__ uint32_t split2(float a, float b, uint32_t& lo) {
    __half ha = __float2half_rn(a), hb = __float2half_rn(b);
    float ra = a - __half2float(ha);
    float rb = b - __half2float(hb);
    __half2 h = __halves2half2(ha, hb);
    __half2 l = __floats2half2_rn(ra, rb);
    lo = *(uint32_t*)&l;
    return *(uint32_t*)&h;
}

// ---------------- conv weight fragment pack (64-oc block granularity) ------------
// frag id = ((((ocblk*32+stage)*9+tap)*4+mslot)*8+grp)*4+tig ; ocblk 0..7
// oc = ocblk*64 + mslot*16 + grp ; icp = stage*8 + tig
__device__ __forceinline__ uint32_t wpair(const float* w, int oc, int icp, int tap) {
    float w0 = w[((long)oc * 512 + 2 * icp) * 9 + tap];
    float w1 = w[((long)oc * 512 + 2 * icp + 1) * 9 + tap];
    __half2 h = __floats2half2_rn(w0, w1);
    return *(uint32_t*)&h;
}

__global__ void wpack(const float* __restrict__ w)
{
    int idx = blockIdx.x * 256 + threadIdx.x;
    if (idx >= 294912) return;
    int tig = idx & 3;
    int grp = (idx >> 2) & 7;
    int mslot = (idx >> 5) & 3;
    int t = idx >> 7;
    int tap = t % 9;
    int t2 = t / 9;
    int stage = t2 & 31;
    int ocblk = t2 >> 5;
    int oc = ocblk * 64 + mslot * 16 + grp;
    int icp = stage * 8 + tig;
    uint4 v;
    v.x = wpair(w, oc,     icp,     tap);
    v.y = wpair(w, oc + 8, icp,     tap);
    v.z = wpair(w, oc,     icp + 4, tap);
    v.w = wpair(w, oc + 8, icp + 4, tap);
    g_wfrag[idx] = v;
}

// ====================== fp16x2-split tensor-core GEMM ============================
// ~fp32: A=Ah+Al, B=Bh+Bl; C += Ah·Bl + Al·Bh + Ah·Bh. Power-of-2 pre-scaling.
// Block 128x128, K chunk 32 (16 kp), 8 warps, warp 32x64 = 2x8 m16n8k16.
template <int EPI, bool BKC, bool SPLITK>
__global__ __launch_bounds__(256, 2)
void sgemm16(const float* __restrict__ A, const float* __restrict__ B,
             float* __restrict__ C, int N, int K,
             int ntx, int splitChunk, long partStride,
             long aBat, long aSm, long bBat, long bS, long cBat,
             float scA, float scB, float scO,
             const float* __restrict__ sv, const float* __restrict__ tv,
             __half* __restrict__ h16)
{
    __shared__ uint32_t Ah[128 * 20], Al[128 * 20];
    __shared__ uint32_t Bh[2560], Bl[2560];

    int tid = threadIdx.x;
    int lane = tid & 31, warp = tid >> 5;
    int warpM = warp >> 1, warpN = warp & 1;
    int grp = lane >> 2, tig = lane & 3;
    int sp = SPLITK ? (blockIdx.x / ntx) : 0;
    int n0 = SPLITK ? (blockIdx.x % ntx) * 128 : blockIdx.x * 128;
    int m0 = blockIdx.y * 128;
    int kBeg = SPLITK ? sp * splitChunk : 0;
    int kEnd = SPLITK ? (kBeg + splitChunk < K ? kBeg + splitChunk : K) : K;
    long ab = (long)blockIdx.z * aBat + (long)m0 * aSm;
    long bb = (long)blockIdx.z * bBat;
    long cb = (long)blockIdx.z * cBat + (SPLITK ? (long)sp * partStride : 0L);

    float acc[2][8][4] = {};

    int kq = tid & 7;
    int mrow = tid >> 3;

    for (int k0 = kBeg; k0 < kEnd; k0 += 32) {
        __syncthreads();
        #pragma unroll
        for (int i = 0; i < 4; i++) {
            int m = mrow + 32 * i;
            float4 v = *(const float4*)&A[ab + (long)m * aSm + k0 + 4 * kq];
            uint32_t l0, l1;
            uint32_t h0 = split2(v.x * scA, v.y * scA, l0);
            uint32_t h1 = split2(v.z * scA, v.w * scA, l1);
            *(uint2*)&Ah[m * 20 + 2 * kq] = make_uint2(h0, h1);
            *(uint2*)&Al[m * 20 + 2 * kq] = make_uint2(l0, l1);
        }
        if (BKC) {
            #pragma unroll
            for (int i = 0; i < 4; i++) {
                int n = mrow + 32 * i;
                float4 v = *(const float4*)&B[bb + (long)(n0 + n) * bS + k0 + 4 * kq];
                uint32_t l0, l1;
                uint32_t h0 = split2(v.x * scB, v.y * scB, l0);
                uint32_t h1 = split2(v.z * scB, v.w * scB, l1);
                *(uint2*)&Bh[n * 20 + 2 * kq] = make_uint2(h0, h1);
                *(uint2*)&Bl[n * 20 + 2 * kq] = make_uint2(l0, l1);
            }
        } else {
            int nq = tid & 31, kk = tid >> 5;
            #pragma unroll
            for (int i = 0; i < 2; i++) {
                int kp = kk + 8 * i;
                float4 r0 = *(const float4*)&B[bb + (long)(k0 + 2 * kp) * bS + n0 + 4 * nq];
                float4 r1 = *(const float4*)&B[bb + (long)(k0 + 2 * kp + 1) * bS + n0 + 4 * nq];
                uint4 wh, wl;
                wh.x = split2(r0.x * scB, r1.x * scB, wl.x);
                wh.y = split2(r0.y * scB, r1.y * scB, wl.y);
                wh.z = split2(r0.z * scB, r1.z * scB, wl.z);
                wh.w = split2(r0.w * scB, r1.w * scB, wl.w);
                *(uint4*)&Bh[kp * 136 + 4 * nq] = wh;
                *(uint4*)&Bl[kp * 136 + 4 * nq] = wl;
            }
        }
        __syncthreads();

        #pragma unroll
        for (int s = 0; s < 2; s++) {
            int kp0 = s * 8;
            uint32_t ahi[2][4], alo[2][4];
            #pragma unroll
            for (int mt = 0; mt < 2; mt++) {
                int m = warpM * 32 + mt * 16 + grp;
                ahi[mt][0] = Ah[m * 20 + kp0 + tig];           alo[mt][0] = Al[m * 20 + kp0 + tig];
                ahi[mt][1] = Ah[(m + 8) * 20 + kp0 + tig];     alo[mt][1] = Al[(m + 8) * 20 + kp0 + tig];
                ahi[mt][2] = Ah[m * 20 + kp0 + tig + 4];       alo[mt][2] = Al[m * 20 + kp0 + tig + 4];
                ahi[mt][3] = Ah[(m + 8) * 20 + kp0 + tig + 4]; alo[mt][3] = Al[(m + 8) * 20 + kp0 + tig + 4];
            }
            #pragma unroll
            for (int nt = 0; nt < 8; nt++) {
                int n = warpN * 64 + nt * 8 + grp;
                int i0 = BKC ? (n * 20 + kp0 + tig)     : ((kp0 + tig) * 136 + n);
                int i1 = BKC ? (n * 20 + kp0 + tig + 4) : ((kp0 + tig + 4) * 136 + n);
                uint32_t bh0 = Bh[i0], bl0 = Bl[i0];
                uint32_t bh1 = Bh[i1], bl1 = Bl[i1];
                #pragma unroll
                for (int mt = 0; mt < 2; mt++) {
                    mma_f16(acc[mt][nt], ahi[mt], bl0, bl1);
                    mma_f16(acc[mt][nt], alo[mt], bh0, bh1);
                    mma_f16(acc[mt][nt], ahi[mt], bh0, bh1);
                }
            }
        }
    }

    #pragma unroll
    for (int mt = 0; mt < 2; mt++) {
        #pragma unroll
        for (int h = 0; h < 2; h++) {
            int m = m0 + warpM * 32 + mt * 16 + grp + h * 8;
            float s = 0.f, t = 0.f;
            if (EPI == 1) t = tv[m];
            if (EPI == 2) { s = sv[m]; t = tv[m]; }
            #pragma unroll
            for (int nt = 0; nt < 8; nt++) {
                int n = n0 + warpN * 64 + nt * 8 + tig * 2;
                float v0 = acc[mt][nt][2 * h] * scO;
                float v1 = acc[mt][nt][2 * h + 1] * scO;
                if (EPI == 1) { v0 += t; v1 += t; }
                else if (EPI == 2) {
                    v0 = fmaxf(s * v0 + t, 0.f);
                    v1 = fmaxf(s * v1 + t, 0.f);
                } else if (EPI == 3) { v0 += tv[n]; v1 += tv[n + 1]; }
                C[cb + (long)m * N + n] = v0;
                C[cb + (long)m * N + n + 1] = v1;
                if (EPI == 2 && h16) {
                    long hb = (long)blockIdx.z * 2L * 64 * N
                            + (long)(m >> 1) * 2 * N + (long)n * 2 + (m & 1);
                    h16[hb]     = __float2half(v0);
                    h16[hb + 2] = __float2half(v1);
                }
            }
        }
    }
}

// ---------------- reduce P split-K partials --------------------------------------
template <int P>
__global__ void reduceP(const float* __restrict__ p, float* __restrict__ o, int n)
{
    int i = blockIdx.x * 256 + threadIdx.x;
    if (i < n) {
        float s = 0.f;
        #pragma unroll
        for (int j = 0; j < P; j++) s += p[i + (long)j * n];
        o[i] = s;
    }
}

// ---------------- softmax of (rowmax - E) -> fp16, rows of 128 -------------------
__global__ void softmax_neg(const float* __restrict__ E, __half* __restrict__ A)
{
    int row = blockIdx.x;
    int t = threadIdx.x;
    __shared__ float red[128];
    float v = E[(long)row * 128 + t];
    red[t] = v;
    __syncthreads();
    for (int s = 64; s > 0; s >>= 1) {
        if (t < s) red[t] = fminf(red[t], red[t + s]);
        __syncthreads();
    }
    float mn = red[0];
    __syncthreads();
    float ex = expf(mn - v);
    red[t] = ex;
    __syncthreads();
    for (int s = 64; s > 0; s >>= 1) {
        if (t < s) red[t] += red[t + s];
        __syncthreads();
    }
    A[(long)row * 128 + t] = __float2half(ex / red[0]);
}

// ---------------- step 9: fp16 GEMM, oprh = fp16(gamma * att@py2 + x) ------------
#define HG_SMEM ((128 * 68 + 64 * 136) * 4)   // 69632 B
__global__ __launch_bounds__(256, 2)
void hgemm9(const __half* __restrict__ att, const uint32_t* __restrict__ py2h,
            __half* __restrict__ oprh, const float* __restrict__ res,
            const float* __restrict__ gptr)
{
    extern __shared__ uint32_t dsm[];
    uint32_t* Ap = dsm;             // [m(128)][kp 64] stride 68
    uint32_t* Bp = dsm + 128 * 68;  // [kp(64)][n 128] stride 136

    int tid = threadIdx.x;
    int lane = tid & 31, warp = tid >> 5;
    int warpM = warp >> 1, warpN = warp & 1;
    int grp = lane >> 2, tig = lane & 3;
    int b = blockIdx.z;
    int m0 = blockIdx.y * 128, n0 = blockIdx.x * 128;

    {
        int r = tid >> 1;
        int hf = tid & 1;
        const uint32_t* src = (const uint32_t*)(att + (long)b * 512 * 128 + (long)(m0 + r) * 128);
        #pragma unroll
        for (int i = 0; i < 8; i++) {
            uint4 v = *(const uint4*)&src[hf * 32 + i * 4];
            *(uint4*)&Ap[r * 68 + hf * 32 + i * 4] = v;
        }
    }
    {
        int kp = tid >> 2;
        int ch = tid & 3;
        const uint32_t* src = py2h + (long)b * 64 * 4096 + (long)kp * 4096 + n0;
        #pragma unroll
        for (int i = 0; i < 8; i++) {
            int c = ch + i * 4;
            uint4 v = *(const uint4*)&src[c * 4];
            *(uint4*)&Bp[kp * 136 + c * 4] = v;
        }
    }
    __syncthreads();

    float acc[2][8][4] = {};
    #pragma unroll
    for (int s = 0; s < 8; s++) {
        int kp0 = s * 8;
        uint32_t a[2][4];
        #pragma unroll
        for (int mt = 0; mt < 2; mt++) {
            int m = warpM * 32 + mt * 16 + grp;
            a[mt][0] = Ap[m * 68 + kp0 + tig];
            a[mt][1] = Ap[(m + 8) * 68 + kp0 + tig];
            a[mt][2] = Ap[m * 68 + kp0 + tig + 4];
            a[mt][3] = Ap[(m + 8) * 68 + kp0 + tig + 4];
        }
        #pragma unroll
        for (int nt = 0; nt < 8; nt++) {
            int n = warpN * 64 + nt * 8 + grp;
            uint32_t b0 = Bp[(kp0 + tig) * 136 + n];
            uint32_t b1 = Bp[(kp0 + tig + 4) * 136 + n];
            #pragma unroll
            for (int mt = 0; mt < 2; mt++)
                mma_f16(acc[mt][nt], a[mt], b0, b1);
        }
    }

    float gm = gptr[0];
    long rb = (long)b * 512 * 4096;
    #pragma unroll
    for (int mt = 0; mt < 2; mt++) {
        #pragma unroll
        for (int h = 0; h < 2; h++) {
            int m = m0 + warpM * 32 + mt * 16 + grp + h * 8;
            #pragma unroll
            for (int nt = 0; nt < 8; nt++) {
                int n = n0 + warpN * 64 + nt * 8 + tig * 2;
                float v0 = gm * acc[mt][nt][2 * h]     + res[rb + (long)m * 4096 + n];
                float v1 = gm * acc[mt][nt][2 * h + 1] + res[rb + (long)m * 4096 + n + 1];
                long base = rb + (long)(m >> 1) * 8192 + (long)n * 2 + (m & 1);
                oprh[base]     = __float2half(v0);
                oprh[base + 2] = __float2half(v1);
            }
        }
    }
}

// ---------------- 3x3 conv, fp16 m16n8k16, 3-stage pipeline, 2 blocks/SM ---------
// Block: 256 thr = 8 warps (warpM 0..1 -> 32-oc, warpN 0..3 -> row); 64 oc/block.
#define SW_WORDS  4608               // 1152 fragments x 4 words per stage
#define SIN_WORDS (8 * 6 * 76)       // 3648
#define CONV_SMEM (3 * (SW_WORDS + SIN_WORDS) * 4)   // 99072 B -> 2 blocks/SM

__device__ __forceinline__ void conv_issue(int stage, uint32_t swb, uint32_t sinb,
                                           const __half* __restrict__ inB,
                                           int y0, int ocblk, int tid)
{
    const uint4* wsrc = g_wfrag + (long)(ocblk * 32 + stage) * 1152;
    for (int idx = tid; idx < 1152; idx += 256)
        cp16(swb + (uint32_t)idx * 16, wsrc + idx);
    int icp0 = stage * 8;
    for (int idx = tid; idx < 768; idx += 256) {
        int r  = idx >> 4;
        int ch = idx & 15;
        int icp = r / 6, y = r - icp * 6;
        int gy = y0 - 1 + y;
        if (gy >= 0 && gy < 64)
            cp16(sinb + (uint32_t)(r * 76 + 4 + ch * 4) * 4,
                 inB + (long)(icp0 + icp) * 8192 + (long)gy * 128 + ch * 8);
    }
}

__global__ __launch_bounds__(256, 2)
void conv3x3_tc_kernel(const __half* __restrict__ in, float* __restrict__ out)
{
    extern __shared__ uint32_t smem[];
    uint32_t* sW  = smem;                     // 3 stages
    uint32_t* sIn = smem + 3 * SW_WORDS;      // 3 stages
    uint32_t sw_base  = (uint32_t)__cvta_generic_to_shared(sW);
    uint32_t sin_base = (uint32_t)__cvta_generic_to_shared(sIn);

    int tid = threadIdx.x;
    int lane = tid & 31;
    int warp = tid >> 5;            // 0..7
    int warpM = warp >> 2;          // 0..1 -> 32-oc half
    int warpN = warp & 3;           // 0..3 -> row
    int grp = lane >> 2;
    int tig = lane & 3;

    int b     = blockIdx.z;
    int ocblk = blockIdx.y;         // 0..7
    int oc0   = ocblk * 64;
    int y0    = blockIdx.x * 4;

    const __half* inB = in + (long)b * 256 * 8192;

    for (int i = tid; i < 3 * SIN_WORDS; i += 256) sIn[i] = 0;
    __syncthreads();

    conv_issue(0, sw_base, sin_base, inB, y0, ocblk, tid);
    asm volatile("cp.async.commit_group;");
    conv_issue(1, sw_base + SW_WORDS * 4, sin_base + SIN_WORDS * 4, inB, y0, ocblk, tid);
    asm volatile("cp.async.commit_group;");

    float acc[2][8][4] = {};

    for (int it = 0; it < 32; it++) {
        int buf = it % 3;
        if (it < 30) {
            int nb = (it + 2) % 3;
            conv_issue(it + 2, sw_base + nb * SW_WORDS * 4,
                       sin_base + nb * SIN_WORDS * 4, inB, y0, ocblk, tid);
            asm volatile("cp.async.commit_group;");
            asm volatile("cp.async.wait_group 2;");
        } else if (it == 30) {
            asm volatile("cp.async.wait_group 1;");
        } else {
            asm volatile("cp.async.wait_group 0;");
        }
        __syncthreads();

        const uint32_t* sWb  = sW + buf * SW_WORDS;
        const uint32_t* sInb = sIn + buf * SIN_WORDS;

        #pragma unroll
        for (int ky = 0; ky < 3; ky++) {
            #pragma unroll
            for (int kx = 0; kx < 3; kx++) {
                const int tap = ky * 3 + kx;
                uint4 av[2];
                #pragma unroll
                for (int mt = 0; mt < 2; mt++) {
                    int mslot = warpM * 2 + mt;
                    av[mt] = *(const uint4*)&sWb[((tap * 4 + mslot) * 8 + grp) * 16 + tig * 4];
                }
                const int ir0 = (tig * 6 + warpN + ky) * 76;
                const int ir4 = ((tig + 4) * 6 + warpN + ky) * 76;
                #pragma unroll
                for (int j = 0; j < 8; j++) {
                    int xi = 3 + j * 8 + grp + kx;
                    uint32_t b0 = sInb[ir0 + xi];
                    uint32_t b1 = sInb[ir4 + xi];
                    #pragma unroll
                    for (int mt = 0; mt < 2; mt++)
                        mma_f16(acc[mt][j], (const uint32_t*)&av[mt], b0, b1);
                }
            }
        }
        __syncthreads();
    }

    int y = y0 + warpN;
    #pragma unroll
    for (int mt = 0; mt < 2; mt++) {
        int row = oc0 + warpM * 32 + mt * 16 + grp;
        float s0 = g_s3[row],     t0 = g_t3[row];
        float s8 = g_s3[row + 8], t8 = g_t3[row + 8];
        long base0 = ((long)b * 512 + row) * 4096 + (long)y * 64;
        long base8 = base0 + 8L * 4096;
        #pragma unroll
        for (int j = 0; j < 8; j++) {
            int x = j * 8 + tig * 2;
            out[base0 + x    ] = fmaxf(s0 * acc[mt][j][0] + t0, 0.f);
            out[base0 + x + 1] = fmaxf(s0 * acc[mt][j][1] + t0, 0.f);
            out[base8 + x    ] = fmaxf(s8 * acc[mt][j][2] + t8, 0.f);
            out[base8 + x + 1] = fmaxf(s8 * acc[mt][j][3] + t8, 0.f);
        }
    }
}

// ------------------------------- launcher ---------------------------------------
extern "C" void kernel_launch(void* const* d_in, const int* in_sizes, int n_in,
                              void* d_out, int out_size)
{
    const float* x     = (const float*)d_in[0];
    const float* q1_w  = (const float*)d_in[1];
    const float* q1_b  = (const float*)d_in[2];
    const float* bn1_g = (const float*)d_in[3];
    const float* bn1_b = (const float*)d_in[4];
    const float* bn1_m = (const float*)d_in[5];
    const float* bn1_v = (const float*)d_in[6];
    const float* q2_w  = (const float*)d_in[7];
    const float* q2_b  = (const float*)d_in[8];
    const float* bn2_g = (const float*)d_in[9];
    const float* bn2_b = (const float*)d_in[10];
    const float* bn2_m = (const float*)d_in[11];
    const float* bn2_v = (const float*)d_in[12];
    const float* p1_w  = (const float*)d_in[13];
    const float* p1_b  = (const float*)d_in[14];
    const float* fus_w = (const float*)d_in[15];
    const float* fus_b = (const float*)d_in[16];
    const float* bn3_g = (const float*)d_in[17];
    const float* bn3_b = (const float*)d_in[18];
    const float* bn3_m = (const float*)d_in[19];
    const float* bn3_v = (const float*)d_in[20];
    const float* gamma = (const float*)d_in[21];

    float *py1, *py2, *e1T, *e1t, *e2, *part, *e2p, *eng, *s1, *t1, *s2, *t2;
    uint32_t* py2h;
    __half *atth, *oprh;
    cudaGetSymbolAddress((void**)&py1, g_py1);
    cudaGetSymbolAddress((void**)&py2, g_py2);
    cudaGetSymbolAddress((void**)&py2h, g_py2h);
    cudaGetSymbolAddress((void**)&e1T, g_e1T);
    cudaGetSymbolAddress((void**)&e1t, g_e1t);
    cudaGetSymbolAddress((void**)&e2,  g_e2);
    cudaGetSymbolAddress((void**)&part, g_part);
    cudaGetSymbolAddress((void**)&e2p, g_e2p);
    cudaGetSymbolAddress((void**)&eng, g_eng);
    cudaGetSymbolAddress((void**)&atth, g_atth);
    cudaGetSymbolAddress((void**)&oprh, g_oprh);
    cudaGetSymbolAddress((void**)&s1,  g_s1);
    cudaGetSymbolAddress((void**)&t1,  g_t1);
    cudaGetSymbolAddress((void**)&s2,  g_s2);
    cudaGetSymbolAddress((void**)&t2,  g_t2);

    static bool attr_set = false;
    if (!attr_set) {
        cudaFuncSetAttribute(conv3x3_tc_kernel,
                             cudaFuncAttributeMaxDynamicSharedMemorySize, CONV_SMEM);
        cudaFuncSetAttribute(hgemm9,
                             cudaFuncAttributeMaxDynamicSharedMemorySize, HG_SMEM);
        attr_set = true;
    }

    fold_kernel<<<1, 512>>>(q1_b, bn1_g, bn1_b, bn1_m, bn1_v,
                            q2_b, bn2_g, bn2_b, bn2_m, bn2_v,
                            fus_b, bn3_g, bn3_b, bn3_m, bn3_v);

    wpack<<<(294912 + 255) / 256, 256>>>(fus_w);

    // 1) py1 = relu(bn1(q1_w @ x))  [16, 256, 4096]
    sgemm16<2, false, false><<<dim3(32, 2, 16), 256>>>(q1_w, x, py1, 4096, 512,
        0, 0, 0L,  0L, 512L,  512L * 4096, 4096L,  256L * 4096,
        32.f, 8.f, 1.f / 256.f, s1, t1, nullptr);

    // 2) py2 = relu(bn2(q2_w @ py1))  [16, 128, 4096]  (+ packed fp16 copy)
    sgemm16<2, false, false><<<dim3(32, 1, 16), 256>>>(q2_w, py1, py2, 4096, 256,
        0, 0, 0L,  0L, 256L,  256L * 4096, 4096L,  128L * 4096,
        32.f, 2.f, 1.f / 64.f, s2, t2, (__half*)py2h);

    // 3) e1T[d,c] = x @ py1^T  [16, 512, 256]  — split-K x2 + reduce
    sgemm16<0, true, true><<<dim3(4, 4, 16), 256>>>(x, py1, part, 256, 4096,
        2, 2048, 16L * 512 * 256,
        512L * 4096, 4096L,  256L * 4096, 4096L,  512L * 256,
        8.f, 2.f, 1.f / 16.f, nullptr, nullptr, nullptr);
    reduceP<2><<<(16 * 512 * 256 + 255) / 256, 256>>>(part, e1T, 16 * 512 * 256);

    // 4) e1t[d,o] = e1T @ p1_w^T + p1_b[o]  [16, 512, 256]
    sgemm16<3, true, false><<<dim3(2, 4, 16), 256>>>(e1T, p1_w, e1t, 256, 256,
        0, 0, 0L,  512L * 256, 256L,  0L, 256L,  512L * 256,
        4.f, 32.f, 1.f / 128.f, nullptr, p1_b, nullptr);

    // 5) e2 = py1 @ py2^T  [16, 256, 128]  — split-K x4 + reduce
    sgemm16<0, true, true><<<dim3(4, 2, 16), 256>>>(py1, py2, part, 128, 4096,
        1, 1024, 16L * 256 * 128,
        256L * 4096, 4096L,  128L * 4096, 4096L,  256L * 128,
        2.f, 2.f, 1.f / 4.f, nullptr, nullptr, nullptr);
    reduceP<4><<<(16 * 256 * 128 + 255) / 256, 256>>>(part, e2, 16 * 256 * 128);

    // 6) e2p[o,c] = p1_w @ e2 + p1_b[o]  [16, 256, 128]
    sgemm16<1, false, false><<<dim3(1, 2, 16), 256>>>(p1_w, e2, e2p, 128, 256,
        0, 0, 0L,  0L, 256L,  256L * 128, 128L,  256L * 128,
        32.f, 1.f, 1.f / 32.f, nullptr, p1_b, nullptr);

    // 7) energy = e1t @ e2p  [16, 512, 128]
    sgemm16<0, false, false><<<dim3(1, 4, 16), 256>>>(e1t, e2p, eng, 128, 256,
        0, 0, 0L,  512L * 256, 256L,  256L * 128, 128L,  512L * 128,
        8.f, 1.f, 1.f / 8.f, nullptr, nullptr, nullptr);

    // 8) attention = softmax(rowmax - energy)  -> fp16
    softmax_neg<<<16 * 512, 128>>>(eng, atth);

    // 9) oprh = fp16(gamma * (attention @ py2) + x)  — fp16 tensor GEMM
    hgemm9<<<dim3(32, 4, 16), 256, HG_SMEM>>>(atth, py2h, oprh, x, gamma);

    // 10) out = relu(bn3(conv3x3(oprh)))  — 64-oc blocks, 2 blocks/SM
    conv3x3_tc_kernel<<<dim3(16, 8, 16), 256, CONV_SMEM>>>(oprh, (float*)d_out);
}

// round 12
// speedup vs baseline: 9.7446x; 1.0323x over previous
#include <cuda_runtime.h>
#include <cuda_fp16.h>
#include <math.h>
#include <stdint.h>

#define EPS 1e-5f

// ---------------- scratch (device globals; no allocation allowed) ----------------
__device__ float g_py1[16L * 256 * 4096];
__device__ float g_py2[16L * 128 * 4096];
__device__ uint32_t g_py2h[16L * 64 * 4096];     // py2 fp16 packed k-pairs [b][kp][n]
__device__ float g_e1T[16L * 512 * 256];
__device__ float g_e1t[16L * 512 * 256];
__device__ float g_e2 [16L * 256 * 128];
__device__ float g_part[2L * 16 * 512 * 256];    // split-K partials
__device__ float g_e2p[16L * 256 * 128];
__device__ float g_eng[16L * 512 * 128];
__device__ __half g_atth[16L * 512 * 128];
// conv input fp16: [b][stage 32][px 4096][8 words: ic-pairs in order (0,4),(1,5),(2,6),(3,7)]
__device__ __half g_oprh[16L * 512 * 4096];
__device__ uint4 g_wfrag[294912];                // conv weight MMA fragments (64-oc blocks)

__device__ float g_s1[256], g_t1[256];
__device__ float g_s2[128], g_t2[128];
__device__ float g_s3[512], g_t3[512];

// ---------------- fold BN (+conv bias) into per-channel scale/shift --------------
__global__ void fold_kernel(const float* __restrict__ q1b, const float* __restrict__ g1,
                            const float* __restrict__ b1,  const float* __restrict__ m1,
                            const float* __restrict__ v1,
                            const float* __restrict__ q2b, const float* __restrict__ g2,
                            const float* __restrict__ b2,  const float* __restrict__ m2,
                            const float* __restrict__ v2,
                            const float* __restrict__ fb,  const float* __restrict__ g3,
                            const float* __restrict__ b3,  const float* __restrict__ m3,
                            const float* __restrict__ v3)
{
    int i = threadIdx.x;
    if (i < 256) {
        float s = g1[i] * rsqrtf(v1[i] + EPS);
        g_s1[i] = s;
        g_t1[i] = s * q1b[i] + b1[i] - m1[i] * s;
    }
    if (i < 128) {
        float s = g2[i] * rsqrtf(v2[i] + EPS);
        g_s2[i] = s;
        g_t2[i] = s * q2b[i] + b2[i] - m2[i] * s;
    }
    if (i < 512) {
        float s = g3[i] * rsqrtf(v3[i] + EPS);
        g_s3[i] = s;
        g_t3[i] = s * fb[i] + b3[i] - m3[i] * s;
    }
}

// ---------------- helpers ---------------------------------------------------------
__device__ __forceinline__ void mma_f16(float* c, const uint32_t* a, uint32_t b0, uint32_t b1) {
    asm volatile(
        "mma.sync.aligned.m16n8k16.row.col.f32.f16.f16.f32 "
        "{%0,%1,%2,%3}, {%4,%5,%6,%7}, {%8,%9}, {%0,%1,%2,%3};"
        : "+f"(c[0]), "+f"(c[1]), "+f"(c[2]), "+f"(c[3])
        : "r"(a[0]), "r"(a[1]), "r"(a[2]), "r"(a[3]), "r"(b0), "r"(b1));
}

__device__ __forceinline__ void cp16(uint32_t dst, const void* src) {
    asm volatile("cp.async.cg.shared.global [%0], [%1], 16;" :: "r"(dst), "l"(src));
}

__device__ __forceinline__ uint32_t split2(float a, float b, uint32_t& lo) {
    __half ha = __float2half_rn(a), hb = __float2half_rn(b);
    float ra = a - __half2float(ha);
    float rb = b - __half2float(hb);
    __half2 h = __halves2half2(ha, hb);
    __half2 l = __floats2half2_rn(ra, rb);
    lo = *(uint32_t*)&l;
    return *(uint32_t*)&h;
}

// ---------------- conv weight fragment pack (64-oc block granularity) ------------
__device__ __forceinline__ uint32_t wpair(const float* w, int oc, int icp, int tap) {
    float w0 = w[((long)oc * 512 + 2 * icp) * 9 + tap];
    float w1 = w[((long)oc * 512 + 2 * icp + 1) * 9 + tap];
    __half2 h = __floats2half2_rn(w0, w1);
    return *(uint32_t*)&h;
}

__global__ void wpack(const float* __restrict__ w)
{
    int idx = blockIdx.x * 256 + threadIdx.x;
    if (idx >= 294912) return;
    int tig = idx & 3;
    int grp = (idx >> 2) & 7;
    int mslot = (idx >> 5) & 3;
    int t = idx >> 7;
    int tap = t % 9;
    int t2 = t / 9;
    int stage = t2 & 31;
    int ocblk = t2 >> 5;
    int oc = ocblk * 64 + mslot * 16 + grp;
    int icp = stage * 8 + tig;
    uint4 v;
    v.x = wpair(w, oc,     icp,     tap);
    v.y = wpair(w, oc + 8, icp,     tap);
    v.z = wpair(w, oc,     icp + 4, tap);
    v.w = wpair(w, oc + 8, icp + 4, tap);
    g_wfrag[idx] = v;
}

// ====================== fp16x2-split tensor-core GEMM ============================
template <int EPI, bool BKC, bool SPLITK>
__global__ __launch_bounds__(256, 2)
void sgemm16(const float* __restrict__ A, const float* __restrict__ B,
             float* __restrict__ C, int N, int K,
             int ntx, int splitChunk, long partStride,
             long aBat, long aSm, long bBat, long bS, long cBat,
             float scA, float scB, float scO,
             const float* __restrict__ sv, const float* __restrict__ tv,
             __half* __restrict__ h16)
{
    __shared__ uint32_t Ah[128 * 20], Al[128 * 20];
    __shared__ uint32_t Bh[2560], Bl[2560];

    int tid = threadIdx.x;
    int lane = tid & 31, warp = tid >> 5;
    int warpM = warp >> 1, warpN = warp & 1;
    int grp = lane >> 2, tig = lane & 3;
    int sp = SPLITK ? (blockIdx.x / ntx) : 0;
    int n0 = SPLITK ? (blockIdx.x % ntx) * 128 : blockIdx.x * 128;
    int m0 = blockIdx.y * 128;
    int kBeg = SPLITK ? sp * splitChunk : 0;
    int kEnd = SPLITK ? (kBeg + splitChunk < K ? kBeg + splitChunk : K) : K;
    long ab = (long)blockIdx.z * aBat + (long)m0 * aSm;
    long bb = (long)blockIdx.z * bBat;
    long cb = (long)blockIdx.z * cBat + (SPLITK ? (long)sp * partStride : 0L);

    float acc[2][8][4] = {};

    int kq = tid & 7;
    int mrow = tid >> 3;

    for (int k0 = kBeg; k0 < kEnd; k0 += 32) {
        __syncthreads();
        #pragma unroll
        for (int i = 0; i < 4; i++) {
            int m = mrow + 32 * i;
            float4 v = *(const float4*)&A[ab + (long)m * aSm + k0 + 4 * kq];
            uint32_t l0, l1;
            uint32_t h0 = split2(v.x * scA, v.y * scA, l0);
            uint32_t h1 = split2(v.z * scA, v.w * scA, l1);
            *(uint2*)&Ah[m * 20 + 2 * kq] = make_uint2(h0, h1);
            *(uint2*)&Al[m * 20 + 2 * kq] = make_uint2(l0, l1);
        }
        if (BKC) {
            #pragma unroll
            for (int i = 0; i < 4; i++) {
                int n = mrow + 32 * i;
                float4 v = *(const float4*)&B[bb + (long)(n0 + n) * bS + k0 + 4 * kq];
                uint32_t l0, l1;
                uint32_t h0 = split2(v.x * scB, v.y * scB, l0);
                uint32_t h1 = split2(v.z * scB, v.w * scB, l1);
                *(uint2*)&Bh[n * 20 + 2 * kq] = make_uint2(h0, h1);
                *(uint2*)&Bl[n * 20 + 2 * kq] = make_uint2(l0, l1);
            }
        } else {
            int nq = tid & 31, kk = tid >> 5;
            #pragma unroll
            for (int i = 0; i < 2; i++) {
                int kp = kk + 8 * i;
                float4 r0 = *(const float4*)&B[bb + (long)(k0 + 2 * kp) * bS + n0 + 4 * nq];
                float4 r1 = *(const float4*)&B[bb + (long)(k0 + 2 * kp + 1) * bS + n0 + 4 * nq];
                uint4 wh, wl;
                wh.x = split2(r0.x * scB, r1.x * scB, wl.x);
                wh.y = split2(r0.y * scB, r1.y * scB, wl.y);
                wh.z = split2(r0.z * scB, r1.z * scB, wl.z);
                wh.w = split2(r0.w * scB, r1.w * scB, wl.w);
                *(uint4*)&Bh[kp * 136 + 4 * nq] = wh;
                *(uint4*)&Bl[kp * 136 + 4 * nq] = wl;
            }
        }
        __syncthreads();

        #pragma unroll
        for (int s = 0; s < 2; s++) {
            int kp0 = s * 8;
            uint32_t ahi[2][4], alo[2][4];
            #pragma unroll
            for (int mt = 0; mt < 2; mt++) {
                int m = warpM * 32 + mt * 16 + grp;
                ahi[mt][0] = Ah[m * 20 + kp0 + tig];           alo[mt][0] = Al[m * 20 + kp0 + tig];
                ahi[mt][1] = Ah[(m + 8) * 20 + kp0 + tig];     alo[mt][1] = Al[(m + 8) * 20 + kp0 + tig];
                ahi[mt][2] = Ah[m * 20 + kp0 + tig + 4];       alo[mt][2] = Al[m * 20 + kp0 + tig + 4];
                ahi[mt][3] = Ah[(m + 8) * 20 + kp0 + tig + 4]; alo[mt][3] = Al[(m + 8) * 20 + kp0 + tig + 4];
            }
            #pragma unroll
            for (int nt = 0; nt < 8; nt++) {
                int n = warpN * 64 + nt * 8 + grp;
                int i0 = BKC ? (n * 20 + kp0 + tig)     : ((kp0 + tig) * 136 + n);
                int i1 = BKC ? (n * 20 + kp0 + tig + 4) : ((kp0 + tig + 4) * 136 + n);
                uint32_t bh0 = Bh[i0], bl0 = Bl[i0];
                uint32_t bh1 = Bh[i1], bl1 = Bl[i1];
                #pragma unroll
                for (int mt = 0; mt < 2; mt++) {
                    mma_f16(acc[mt][nt], ahi[mt], bl0, bl1);
                    mma_f16(acc[mt][nt], alo[mt], bh0, bh1);
                    mma_f16(acc[mt][nt], ahi[mt], bh0, bh1);
                }
            }
        }
    }

    #pragma unroll
    for (int mt = 0; mt < 2; mt++) {
        #pragma unroll
        for (int h = 0; h < 2; h++) {
            int m = m0 + warpM * 32 + mt * 16 + grp + h * 8;
            float s = 0.f, t = 0.f;
            if (EPI == 1) t = tv[m];
            if (EPI == 2) { s = sv[m]; t = tv[m]; }
            #pragma unroll
            for (int nt = 0; nt < 8; nt++) {
                int n = n0 + warpN * 64 + nt * 8 + tig * 2;
                float v0 = acc[mt][nt][2 * h] * scO;
                float v1 = acc[mt][nt][2 * h + 1] * scO;
                if (EPI == 1) { v0 += t; v1 += t; }
                else if (EPI == 2) {
                    v0 = fmaxf(s * v0 + t, 0.f);
                    v1 = fmaxf(s * v1 + t, 0.f);
                } else if (EPI == 3) { v0 += tv[n]; v1 += tv[n + 1]; }
                C[cb + (long)m * N + n] = v0;
                C[cb + (long)m * N + n + 1] = v1;
                if (EPI == 2 && h16) {
                    long hb = (long)blockIdx.z * 2L * 64 * N
                            + (long)(m >> 1) * 2 * N + (long)n * 2 + (m & 1);
                    h16[hb]     = __float2half(v0);
                    h16[hb + 2] = __float2half(v1);
                }
            }
        }
    }
}

// ---------------- reduce P split-K partials --------------------------------------
template <int P>
__global__ void reduceP(const float* __restrict__ p, float* __restrict__ o, int n)
{
    int i = blockIdx.x * 256 + threadIdx.x;
    if (i < n) {
        float s = 0.f;
        #pragma unroll
        for (int j = 0; j < P; j++) s += p[i + (long)j * n];
        o[i] = s;
    }
}

// ---------------- softmax of (rowmax - E) -> fp16, rows of 128 -------------------
__global__ void softmax_neg(const float* __restrict__ E, __half* __restrict__ A)
{
    int row = blockIdx.x;
    int t = threadIdx.x;
    __shared__ float red[128];
    float v = E[(long)row * 128 + t];
    red[t] = v;
    __syncthreads();
    for (int s = 64; s > 0; s >>= 1) {
        if (t < s) red[t] = fminf(red[t], red[t + s]);
        __syncthreads();
    }
    float mn = red[0];
    __syncthreads();
    float ex = expf(mn - v);
    red[t] = ex;
    __syncthreads();
    for (int s = 64; s > 0; s >>= 1) {
        if (t < s) red[t] += red[t + s];
        __syncthreads();
    }
    A[(long)row * 128 + t] = __float2half(ex / red[0]);
}

// ---------------- step 9: fp16 GEMM -> oprh in conv-ready interleaved layout ------
#define HG_SMEM ((128 * 68 + 64 * 136) * 4)   // 69632 B
__global__ __launch_bounds__(256, 2)
void hgemm9(const __half* __restrict__ att, const uint32_t* __restrict__ py2h,
            __half* __restrict__ oprh, const float* __restrict__ res,
            const float* __restrict__ gptr)
{
    extern __shared__ uint32_t dsm[];
    uint32_t* Ap = dsm;             // [m(128)][kp 64] stride 68
    uint32_t* Bp = dsm + 128 * 68;  // [kp(64)][n 128] stride 136

    int tid = threadIdx.x;
    int lane = tid & 31, warp = tid >> 5;
    int warpM = warp >> 1, warpN = warp & 1;
    int grp = lane >> 2, tig = lane & 3;
    int b = blockIdx.z;
    int m0 = blockIdx.y * 128, n0 = blockIdx.x * 128;

    {
        int r = tid >> 1;
        int hf = tid & 1;
        const uint32_t* src = (const uint32_t*)(att + (long)b * 512 * 128 + (long)(m0 + r) * 128);
        #pragma unroll
        for (int i = 0; i < 8; i++) {
            uint4 v = *(const uint4*)&src[hf * 32 + i * 4];
            *(uint4*)&Ap[r * 68 + hf * 32 + i * 4] = v;
        }
    }
    {
        int kp = tid >> 2;
        int ch = tid & 3;
        const uint32_t* src = py2h + (long)b * 64 * 4096 + (long)kp * 4096 + n0;
        #pragma unroll
        for (int i = 0; i < 8; i++) {
            int c = ch + i * 4;
            uint4 v = *(const uint4*)&src[c * 4];
            *(uint4*)&Bp[kp * 136 + c * 4] = v;
        }
    }
    __syncthreads();

    float acc[2][8][4] = {};
    #pragma unroll
    for (int s = 0; s < 8; s++) {
        int kp0 = s * 8;
        uint32_t a[2][4];
        #pragma unroll
        for (int mt = 0; mt < 2; mt++) {
            int m = warpM * 32 + mt * 16 + grp;
            a[mt][0] = Ap[m * 68 + kp0 + tig];
            a[mt][1] = Ap[(m + 8) * 68 + kp0 + tig];
            a[mt][2] = Ap[m * 68 + kp0 + tig + 4];
            a[mt][3] = Ap[(m + 8) * 68 + kp0 + tig + 4];
        }
        #pragma unroll
        for (int nt = 0; nt < 8; nt++) {
            int n = warpN * 64 + nt * 8 + grp;
            uint32_t b0 = Bp[(kp0 + tig) * 136 + n];
            uint32_t b1 = Bp[(kp0 + tig + 4) * 136 + n];
            #pragma unroll
            for (int mt = 0; mt < 2; mt++)
                mma_f16(acc[mt][nt], a[mt], b0, b1);
        }
    }

    float gm = gptr[0];
    long rb = (long)b * 512 * 4096;
    #pragma unroll
    for (int mt = 0; mt < 2; mt++) {
        #pragma unroll
        for (int h = 0; h < 2; h++) {
            int m = m0 + warpM * 32 + mt * 16 + grp + h * 8;
            // oprh word layout: [b][stage = m>>4][px][pos], pos interleaves ic pairs
            int stage = m >> 4;
            int icp_l = (m >> 1) & 7;
            int pos = 2 * (icp_l & 3) + (icp_l >> 2);
            long ob = ((long)(b * 32 + stage) * 4096) * 16 + pos * 2 + (m & 1);
            #pragma unroll
            for (int nt = 0; nt < 8; nt++) {
                int n = n0 + warpN * 64 + nt * 8 + tig * 2;
                float v0 = gm * acc[mt][nt][2 * h]     + res[rb + (long)m * 4096 + n];
                float v1 = gm * acc[mt][nt][2 * h + 1] + res[rb + (long)m * 4096 + n + 1];
                oprh[ob + (long)n * 16]       = __float2half(v0);
                oprh[ob + (long)(n + 1) * 16] = __float2half(v1);
            }
        }
    }
}

// ---------------- 3x3 conv, fp16 m16n8k16, pixel-major LDS.64 B path -------------
// Block: 256 thr = 8 warps (warpM 0..1 -> 32-oc, warpN 0..3 -> row); 64 oc/block.
// sIn stage: [y(6)][x(66)][8 words ic-interleaved] = 3168 words; b-frag = 1 LDS.64.
#define SW_WORDS  4608               // 1152 fragments x 4 words per stage
#define SIN_WORDS (6 * 66 * 8)       // 3168
#define CONV_SMEM (3 * (SW_WORDS + SIN_WORDS) * 4)   // 93312 B -> 2 blocks/SM

__device__ __forceinline__ void conv_issue(int stage, uint32_t swb, uint32_t sinb,
                                           const __half* __restrict__ in, int b,
                                           int y0, int ocblk, int tid)
{
    const uint4* wsrc = g_wfrag + (long)(ocblk * 32 + stage) * 1152;
    for (int idx = tid; idx < 1152; idx += 256)
        cp16(swb + (uint32_t)idx * 16, wsrc + idx);
    const __half* src = in + ((long)(b * 32 + stage) * 4096) * 16;
    for (int idx = tid; idx < 768; idx += 256) {
        int p  = idx >> 1;
        int hf = idx & 1;
        int y  = p >> 6;
        int xo = p & 63;
        int gy = y0 - 1 + y;
        if (gy >= 0 && gy < 64)
            cp16(sinb + (uint32_t)((y * 66 + xo + 1) * 32 + hf * 16),
                 src + ((long)(gy * 64 + xo)) * 16 + hf * 8);
    }
}

__global__ __launch_bounds__(256, 2)
void conv3x3_tc_kernel(const __half* __restrict__ in, float* __restrict__ out)
{
    extern __shared__ uint32_t smem[];
    uint32_t* sW  = smem;                     // 3 stages
    uint32_t* sIn = smem + 3 * SW_WORDS;      // 3 stages
    uint32_t sw_base  = (uint32_t)__cvta_generic_to_shared(sW);
    uint32_t sin_base = (uint32_t)__cvta_generic_to_shared(sIn);

    int tid = threadIdx.x;
    int lane = tid & 31;
    int warp = tid >> 5;            // 0..7
    int warpM = warp >> 2;          // 0..1 -> 32-oc half
    int warpN = warp & 3;           // 0..3 -> row
    int grp = lane >> 2;
    int tig = lane & 3;

    int b     = blockIdx.z;
    int ocblk = blockIdx.y;         // 0..7
    int oc0   = ocblk * 64;
    int y0    = blockIdx.x * 4;

    for (int i = tid; i < 3 * SIN_WORDS; i += 256) sIn[i] = 0;
    __syncthreads();

    conv_issue(0, sw_base, sin_base, in, b, y0, ocblk, tid);
    asm volatile("cp.async.commit_group;");
    conv_issue(1, sw_base + SW_WORDS * 4, sin_base + SIN_WORDS * 4, in, b, y0, ocblk, tid);
    asm volatile("cp.async.commit_group;");

    float acc[2][8][4] = {};

    for (int it = 0; it < 32; it++) {
        int buf = it % 3;
        if (it < 30) {
            int nb = (it + 2) % 3;
            conv_issue(it + 2, sw_base + nb * SW_WORDS * 4,
                       sin_base + nb * SIN_WORDS * 4, in, b, y0, ocblk, tid);
            asm volatile("cp.async.commit_group;");
            asm volatile("cp.async.wait_group 2;");
        } else if (it == 30) {
            asm volatile("cp.async.wait_group 1;");
        } else {
            asm volatile("cp.async.wait_group 0;");
        }
        __syncthreads();

        const uint32_t* sWb  = sW + buf * SW_WORDS;
        const uint32_t* sInb = sIn + buf * SIN_WORDS;

        #pragma unroll
        for (int ky = 0; ky < 3; ky++) {
            #pragma unroll
            for (int kx = 0; kx < 3; kx++) {
                const int tap = ky * 3 + kx;
                uint4 av[2];
                #pragma unroll
                for (int mt = 0; mt < 2; mt++) {
                    int mslot = warpM * 2 + mt;
                    av[mt] = *(const uint4*)&sWb[((tap * 4 + mslot) * 8 + grp) * 16 + tig * 4];
                }
                const int rowb = ((warpN + ky) * 66 + kx) * 8 + 2 * tig;
                uint2 bf[8];
                #pragma unroll
                for (int j = 0; j < 8; j++)
                    bf[j] = *(const uint2*)&sInb[rowb + (j * 8 + grp) * 8];
                #pragma unroll
                for (int j = 0; j < 8; j++) {
                    #pragma unroll
                    for (int mt = 0; mt < 2; mt++)
                        mma_f16(acc[mt][j], (const uint32_t*)&av[mt], bf[j].x, bf[j].y);
                }
            }
        }
        __syncthreads();
    }

    int y = y0 + warpN;
    #pragma unroll
    for (int mt = 0; mt < 2; mt++) {
        int row = oc0 + warpM * 32 + mt * 16 + grp;
        float s0 = g_s3[row],     t0 = g_t3[row];
        float s8 = g_s3[row + 8], t8 = g_t3[row + 8];
        long base0 = ((long)b * 512 + row) * 4096 + (long)y * 64;
        long base8 = base0 + 8L * 4096;
        #pragma unroll
        for (int j = 0; j < 8; j++) {
            int x = j * 8 + tig * 2;
            out[base0 + x    ] = fmaxf(s0 * acc[mt][j][0] + t0, 0.f);
            out[base0 + x + 1] = fmaxf(s0 * acc[mt][j][1] + t0, 0.f);
            out[base8 + x    ] = fmaxf(s8 * acc[mt][j][2] + t8, 0.f);
            out[base8 + x + 1] = fmaxf(s8 * acc[mt][j][3] + t8, 0.f);
        }
    }
}

// ------------------------------- launcher ---------------------------------------
extern "C" void kernel_launch(void* const* d_in, const int* in_sizes, int n_in,
                              void* d_out, int out_size)
{
    const float* x     = (const float*)d_in[0];
    const float* q1_w  = (const float*)d_in[1];
    const float* q1_b  = (const float*)d_in[2];
    const float* bn1_g = (const float*)d_in[3];
    const float* bn1_b = (const float*)d_in[4];
    const float* bn1_m = (const float*)d_in[5];
    const float* bn1_v = (const float*)d_in[6];
    const float* q2_w  = (const float*)d_in[7];
    const float* q2_b  = (const float*)d_in[8];
    const float* bn2_g = (const float*)d_in[9];
    const float* bn2_b = (const float*)d_in[10];
    const float* bn2_m = (const float*)d_in[11];
    const float* bn2_v = (const float*)d_in[12];
    const float* p1_w  = (const float*)d_in[13];
    const float* p1_b  = (const float*)d_in[14];
    const float* fus_w = (const float*)d_in[15];
    const float* fus_b = (const float*)d_in[16];
    const float* bn3_g = (const float*)d_in[17];
    const float* bn3_b = (const float*)d_in[18];
    const float* bn3_m = (const float*)d_in[19];
    const float* bn3_v = (const float*)d_in[20];
    const float* gamma = (const float*)d_in[21];

    float *py1, *py2, *e1T, *e1t, *e2, *part, *e2p, *eng, *s1, *t1, *s2, *t2;
    uint32_t* py2h;
    __half *atth, *oprh;
    cudaGetSymbolAddress((void**)&py1, g_py1);
    cudaGetSymbolAddress((void**)&py2, g_py2);
    cudaGetSymbolAddress((void**)&py2h, g_py2h);
    cudaGetSymbolAddress((void**)&e1T, g_e1T);
    cudaGetSymbolAddress((void**)&e1t, g_e1t);
    cudaGetSymbolAddress((void**)&e2,  g_e2);
    cudaGetSymbolAddress((void**)&part, g_part);
    cudaGetSymbolAddress((void**)&e2p, g_e2p);
    cudaGetSymbolAddress((void**)&eng, g_eng);
    cudaGetSymbolAddress((void**)&atth, g_atth);
    cudaGetSymbolAddress((void**)&oprh, g_oprh);
    cudaGetSymbolAddress((void**)&s1,  g_s1);
    cudaGetSymbolAddress((void**)&t1,  g_t1);
    cudaGetSymbolAddress((void**)&s2,  g_s2);
    cudaGetSymbolAddress((void**)&t2,  g_t2);

    static bool attr_set = false;
    if (!attr_set) {
        cudaFuncSetAttribute(conv3x3_tc_kernel,
                             cudaFuncAttributeMaxDynamicSharedMemorySize, CONV_SMEM);
        cudaFuncSetAttribute(hgemm9,
                             cudaFuncAttributeMaxDynamicSharedMemorySize, HG_SMEM);
        attr_set = true;
    }

    fold_kernel<<<1, 512>>>(q1_b, bn1_g, bn1_b, bn1_m, bn1_v,
                            q2_b, bn2_g, bn2_b, bn2_m, bn2_v,
                            fus_b, bn3_g, bn3_b, bn3_m, bn3_v);

    wpack<<<(294912 + 255) / 256, 256>>>(fus_w);

    // 1) py1 = relu(bn1(q1_w @ x))
    sgemm16<2, false, false><<<dim3(32, 2, 16), 256>>>(q1_w, x, py1, 4096, 512,
        0, 0, 0L,  0L, 512L,  512L * 4096, 4096L,  256L * 4096,
        32.f, 8.f, 1.f / 256.f, s1, t1, nullptr);

    // 2) py2 = relu(bn2(q2_w @ py1))  (+ packed fp16 copy)
    sgemm16<2, false, false><<<dim3(32, 1, 16), 256>>>(q2_w, py1, py2, 4096, 256,
        0, 0, 0L,  0L, 256L,  256L * 4096, 4096L,  128L * 4096,
        32.f, 2.f, 1.f / 64.f, s2, t2, (__half*)py2h);

    // 3) e1T = x @ py1^T  — split-K x2 + reduce
    sgemm16<0, true, true><<<dim3(4, 4, 16), 256>>>(x, py1, part, 256, 4096,
        2, 2048, 16L * 512 * 256,
        512L * 4096, 4096L,  256L * 4096, 4096L,  512L * 256,
        8.f, 2.f, 1.f / 16.f, nullptr, nullptr, nullptr);
    reduceP<2><<<(16 * 512 * 256 + 255) / 256, 256>>>(part, e1T, 16 * 512 * 256);

    // 4) e1t = e1T @ p1_w^T + p1_b
    sgemm16<3, true, false><<<dim3(2, 4, 16), 256>>>(e1T, p1_w, e1t, 256, 256,
        0, 0, 0L,  512L * 256, 256L,  0L, 256L,  512L * 256,
        4.f, 32.f, 1.f / 128.f, nullptr, p1_b, nullptr);

    // 5) e2 = py1 @ py2^T  — split-K x4 + reduce
    sgemm16<0, true, true><<<dim3(4, 2, 16), 256>>>(py1, py2, part, 128, 4096,
        1, 1024, 16L * 256 * 128,
        256L * 4096, 4096L,  128L * 4096, 4096L,  256L * 128,
        2.f, 2.f, 1.f / 4.f, nullptr, nullptr, nullptr);
    reduceP<4><<<(16 * 256 * 128 + 255) / 256, 256>>>(part, e2, 16 * 256 * 128);

    // 6) e2p = p1_w @ e2 + p1_b
    sgemm16<1, false, false><<<dim3(1, 2, 16), 256>>>(p1_w, e2, e2p, 128, 256,
        0, 0, 0L,  0L, 256L,  256L * 128, 128L,  256L * 128,
        32.f, 1.f, 1.f / 32.f, nullptr, p1_b, nullptr);

    // 7) energy = e1t @ e2p
    sgemm16<0, false, false><<<dim3(1, 4, 16), 256>>>(e1t, e2p, eng, 128, 256,
        0, 0, 0L,  512L * 256, 256L,  256L * 128, 128L,  512L * 128,
        8.f, 1.f, 1.f / 8.f, nullptr, nullptr, nullptr);

    // 8) attention = softmax(rowmax - energy) -> fp16
    softmax_neg<<<16 * 512, 128>>>(eng, atth);

    // 9) oprh = fp16(gamma * att@py2 + x), conv-ready interleaved layout
    hgemm9<<<dim3(32, 4, 16), 256, HG_SMEM>>>(atth, py2h, oprh, x, gamma);

    // 10) out = relu(bn3(conv3x3(oprh)))  — LDS.64 b-path, batched MMA runs
    conv3x3_tc_kernel<<<dim3(16, 8, 16), 256, CONV_SMEM>>>(oprh, (float*)d_out);
}

// round 13
// speedup vs baseline: 9.9161x; 1.0176x over previous
#include <cuda_runtime.h>
#include <cuda_fp16.h>
#include <math.h>
#include <stdint.h>

#define EPS 1e-5f

// ---------------- scratch (device globals; no allocation allowed) ----------------
__device__ float g_py1[16L * 256 * 4096];
__device__ float g_py2[16L * 128 * 4096];
__device__ uint32_t g_py2h[16L * 64 * 4096];     // py2 fp16 packed k-pairs [b][kp][n]
__device__ float g_e1T[16L * 512 * 256];
__device__ float g_e1t[16L * 512 * 256];
__device__ float g_e2 [16L * 256 * 128];
__device__ float g_part[4L * 16 * 512 * 256];    // split-K partials (up to 4 x 2.1M)
__device__ float g_e2p[16L * 256 * 128];
__device__ float g_eng[16L * 512 * 128];
__device__ __half g_atth[16L * 512 * 128];
// conv input fp16: [b][stage 32][px 4096][8 words: ic-pairs in order (0,4),(1,5),(2,6),(3,7)]
__device__ __half g_oprh[16L * 512 * 4096];
__device__ uint4 g_wfrag[294912];                // conv weight MMA fragments (64-oc blocks)

__device__ float g_s1[256], g_t1[256];
__device__ float g_s2[128], g_t2[128];
__device__ float g_s3[512], g_t3[512];

// ---------------- fold BN (+conv bias) into per-channel scale/shift --------------
__global__ void fold_kernel(const float* __restrict__ q1b, const float* __restrict__ g1,
                            const float* __restrict__ b1,  const float* __restrict__ m1,
                            const float* __restrict__ v1,
                            const float* __restrict__ q2b, const float* __restrict__ g2,
                            const float* __restrict__ b2,  const float* __restrict__ m2,
                            const float* __restrict__ v2,
                            const float* __restrict__ fb,  const float* __restrict__ g3,
                            const float* __restrict__ b3,  const float* __restrict__ m3,
                            const float* __restrict__ v3)
{
    int i = threadIdx.x;
    if (i < 256) {
        float s = g1[i] * rsqrtf(v1[i] + EPS);
        g_s1[i] = s;
        g_t1[i] = s * q1b[i] + b1[i] - m1[i] * s;
    }
    if (i < 128) {
        float s = g2[i] * rsqrtf(v2[i] + EPS);
        g_s2[i] = s;
        g_t2[i] = s * q2b[i] + b2[i] - m2[i] * s;
    }
    if (i < 512) {
        float s = g3[i] * rsqrtf(v3[i] + EPS);
        g_s3[i] = s;
        g_t3[i] = s * fb[i] + b3[i] - m3[i] * s;
    }
}

// ---------------- helpers ---------------------------------------------------------
__device__ __forceinline__ void mma_f16(float* c, const uint32_t* a, uint32_t b0, uint32_t b1) {
    asm volatile(
        "mma.sync.aligned.m16n8k16.row.col.f32.f16.f16.f32 "
        "{%0,%1,%2,%3}, {%4,%5,%6,%7}, {%8,%9}, {%0,%1,%2,%3};"
        : "+f"(c[0]), "+f"(c[1]), "+f"(c[2]), "+f"(c[3])
        : "r"(a[0]), "r"(a[1]), "r"(a[2]), "r"(a[3]), "r"(b0), "r"(b1));
}

__device__ __forceinline__ void cp16(uint32_t dst, const void* src) {
    asm volatile("cp.async.cg.shared.global [%0], [%1], 16;" :: "r"(dst), "l"(src));
}

__device__ __forceinline__ uint32_t split2(float a, float b, uint32_t& lo) {
    __half ha = __float2half_rn(a), hb = __float2half_rn(b);
    float ra = a - __half2float(ha);
    float rb = b - __half2float(hb);
    __half2 h = __halves2half2(ha, hb);
    __half2 l = __floats2half2_rn(ra, rb);
    lo = *(uint32_t*)&l;
    return *(uint32_t*)&h;
}

// ---------------- conv weight fragment pack (64-oc block granularity) ------------
__device__ __forceinline__ uint32_t wpair(const float* w, int oc, int icp, int tap) {
    float w0 = w[((long)oc * 512 + 2 * icp) * 9 + tap];
    float w1 = w[((long)oc * 512 + 2 * icp + 1) * 9 + tap];
    __half2 h = __floats2half2_rn(w0, w1);
    return *(uint32_t*)&h;
}

__global__ void wpack(const float* __restrict__ w)
{
    int idx = blockIdx.x * 256 + threadIdx.x;
    if (idx >= 294912) return;
    int tig = idx & 3;
    int grp = (idx >> 2) & 7;
    int mslot = (idx >> 5) & 3;
    int t = idx >> 7;
    int tap = t % 9;
    int t2 = t / 9;
    int stage = t2 & 31;
    int ocblk = t2 >> 5;
    int oc = ocblk * 64 + mslot * 16 + grp;
    int icp = stage * 8 + tig;
    uint4 v;
    v.x = wpair(w, oc,     icp,     tap);
    v.y = wpair(w, oc + 8, icp,     tap);
    v.z = wpair(w, oc,     icp + 4, tap);
    v.w = wpair(w, oc + 8, icp + 4, tap);
    g_wfrag[idx] = v;
}

// ====================== fp16x2-split tensor-core GEMM ============================
template <int EPI, bool BKC, bool SPLITK>
__global__ __launch_bounds__(256, 2)
void sgemm16(const float* __restrict__ A, const float* __restrict__ B,
             float* __restrict__ C, int N, int K,
             int ntx, int splitChunk, long partStride,
             long aBat, long aSm, long bBat, long bS, long cBat,
             float scA, float scB, float scO,
             const float* __restrict__ sv, const float* __restrict__ tv,
             __half* __restrict__ h16)
{
    __shared__ uint32_t Ah[128 * 20], Al[128 * 20];
    __shared__ uint32_t Bh[2560], Bl[2560];

    int tid = threadIdx.x;
    int lane = tid & 31, warp = tid >> 5;
    int warpM = warp >> 1, warpN = warp & 1;
    int grp = lane >> 2, tig = lane & 3;
    int sp = SPLITK ? (blockIdx.x / ntx) : 0;
    int n0 = SPLITK ? (blockIdx.x % ntx) * 128 : blockIdx.x * 128;
    int m0 = blockIdx.y * 128;
    int kBeg = SPLITK ? sp * splitChunk : 0;
    int kEnd = SPLITK ? (kBeg + splitChunk < K ? kBeg + splitChunk : K) : K;
    long ab = (long)blockIdx.z * aBat + (long)m0 * aSm;
    long bb = (long)blockIdx.z * bBat;
    long cb = (long)blockIdx.z * cBat + (SPLITK ? (long)sp * partStride : 0L);

    float acc[2][8][4] = {};

    int kq = tid & 7;
    int mrow = tid >> 3;

    for (int k0 = kBeg; k0 < kEnd; k0 += 32) {
        __syncthreads();
        #pragma unroll
        for (int i = 0; i < 4; i++) {
            int m = mrow + 32 * i;
            float4 v = *(const float4*)&A[ab + (long)m * aSm + k0 + 4 * kq];
            uint32_t l0, l1;
            uint32_t h0 = split2(v.x * scA, v.y * scA, l0);
            uint32_t h1 = split2(v.z * scA, v.w * scA, l1);
            *(uint2*)&Ah[m * 20 + 2 * kq] = make_uint2(h0, h1);
            *(uint2*)&Al[m * 20 + 2 * kq] = make_uint2(l0, l1);
        }
        if (BKC) {
            #pragma unroll
            for (int i = 0; i < 4; i++) {
                int n = mrow + 32 * i;
                float4 v = *(const float4*)&B[bb + (long)(n0 + n) * bS + k0 + 4 * kq];
                uint32_t l0, l1;
                uint32_t h0 = split2(v.x * scB, v.y * scB, l0);
                uint32_t h1 = split2(v.z * scB, v.w * scB, l1);
                *(uint2*)&Bh[n * 20 + 2 * kq] = make_uint2(h0, h1);
                *(uint2*)&Bl[n * 20 + 2 * kq] = make_uint2(l0, l1);
            }
        } else {
            int nq = tid & 31, kk = tid >> 5;
            #pragma unroll
            for (int i = 0; i < 2; i++) {
                int kp = kk + 8 * i;
                float4 r0 = *(const float4*)&B[bb + (long)(k0 + 2 * kp) * bS + n0 + 4 * nq];
                float4 r1 = *(const float4*)&B[bb + (long)(k0 + 2 * kp + 1) * bS + n0 + 4 * nq];
                uint4 wh, wl;
                wh.x = split2(r0.x * scB, r1.x * scB, wl.x);
                wh.y = split2(r0.y * scB, r1.y * scB, wl.y);
                wh.z = split2(r0.z * scB, r1.z * scB, wl.z);
                wh.w = split2(r0.w * scB, r1.w * scB, wl.w);
                *(uint4*)&Bh[kp * 136 + 4 * nq] = wh;
                *(uint4*)&Bl[kp * 136 + 4 * nq] = wl;
            }
        }
        __syncthreads();

        #pragma unroll
        for (int s = 0; s < 2; s++) {
            int kp0 = s * 8;
            uint32_t ahi[2][4], alo[2][4];
            #pragma unroll
            for (int mt = 0; mt < 2; mt++) {
                int m = warpM * 32 + mt * 16 + grp;
                ahi[mt][0] = Ah[m * 20 + kp0 + tig];           alo[mt][0] = Al[m * 20 + kp0 + tig];
                ahi[mt][1] = Ah[(m + 8) * 20 + kp0 + tig];     alo[mt][1] = Al[(m + 8) * 20 + kp0 + tig];
                ahi[mt][2] = Ah[m * 20 + kp0 + tig + 4];       alo[mt][2] = Al[m * 20 + kp0 + tig + 4];
                ahi[mt][3] = Ah[(m + 8) * 20 + kp0 + tig + 4]; alo[mt][3] = Al[(m + 8) * 20 + kp0 + tig + 4];
            }
            #pragma unroll
            for (int nt = 0; nt < 8; nt++) {
                int n = warpN * 64 + nt * 8 + grp;
                int i0 = BKC ? (n * 20 + kp0 + tig)     : ((kp0 + tig) * 136 + n);
                int i1 = BKC ? (n * 20 + kp0 + tig + 4) : ((kp0 + tig + 4) * 136 + n);
                uint32_t bh0 = Bh[i0], bl0 = Bl[i0];
                uint32_t bh1 = Bh[i1], bl1 = Bl[i1];
                #pragma unroll
                for (int mt = 0; mt < 2; mt++) {
                    mma_f16(acc[mt][nt], ahi[mt], bl0, bl1);
                    mma_f16(acc[mt][nt], alo[mt], bh0, bh1);
                    mma_f16(acc[mt][nt], ahi[mt], bh0, bh1);
                }
            }
        }
    }

    #pragma unroll
    for (int mt = 0; mt < 2; mt++) {
        #pragma unroll
        for (int h = 0; h < 2; h++) {
            int m = m0 + warpM * 32 + mt * 16 + grp + h * 8;
            float s = 0.f, t = 0.f;
            if (EPI == 1) t = tv[m];
            if (EPI == 2) { s = sv[m]; t = tv[m]; }
            #pragma unroll
            for (int nt = 0; nt < 8; nt++) {
                int n = n0 + warpN * 64 + nt * 8 + tig * 2;
                float v0 = acc[mt][nt][2 * h] * scO;
                float v1 = acc[mt][nt][2 * h + 1] * scO;
                if (EPI == 1) { v0 += t; v1 += t; }
                else if (EPI == 2) {
                    v0 = fmaxf(s * v0 + t, 0.f);
                    v1 = fmaxf(s * v1 + t, 0.f);
                } else if (EPI == 3) { v0 += tv[n]; v1 += tv[n + 1]; }
                C[cb + (long)m * N + n] = v0;
                C[cb + (long)m * N + n + 1] = v1;
                if (EPI == 2 && h16) {
                    long hb = (long)blockIdx.z * 2L * 64 * N
                            + (long)(m >> 1) * 2 * N + (long)n * 2 + (m & 1);
                    h16[hb]     = __float2half(v0);
                    h16[hb + 2] = __float2half(v1);
                }
            }
        }
    }
}

// ---------------- reduce P split-K partials (optional bias over n % nmod) --------
template <int P>
__global__ void reduceP(const float* __restrict__ p, float* __restrict__ o, int n,
                        const float* __restrict__ bias, int nmod)
{
    int i = blockIdx.x * 256 + threadIdx.x;
    if (i < n) {
        float s = bias ? bias[i % nmod] : 0.f;
        #pragma unroll
        for (int j = 0; j < P; j++) s += p[i + (long)j * n];
        o[i] = s;
    }
}

// ---------------- softmax of (rowmax - E) -> fp16, rows of 128 -------------------
__global__ void softmax_neg(const float* __restrict__ E, __half* __restrict__ A)
{
    int row = blockIdx.x;
    int t = threadIdx.x;
    __shared__ float red[128];
    float v = E[(long)row * 128 + t];
    red[t] = v;
    __syncthreads();
    for (int s = 64; s > 0; s >>= 1) {
        if (t < s) red[t] = fminf(red[t], red[t + s]);
        __syncthreads();
    }
    float mn = red[0];
    __syncthreads();
    float ex = expf(mn - v);
    red[t] = ex;
    __syncthreads();
    for (int s = 64; s > 0; s >>= 1) {
        if (t < s) red[t] += red[t + s];
        __syncthreads();
    }
    A[(long)row * 128 + t] = __float2half(ex / red[0]);
}

// ---------------- step 9: fp16 GEMM -> oprh in conv-ready interleaved layout ------
#define HG_SMEM ((128 * 68 + 64 * 136) * 4)   // 69632 B
__global__ __launch_bounds__(256, 2)
void hgemm9(const __half* __restrict__ att, const uint32_t* __restrict__ py2h,
            __half* __restrict__ oprh, const float* __restrict__ res,
            const float* __restrict__ gptr)
{
    extern __shared__ uint32_t dsm[];
    uint32_t* Ap = dsm;             // [m(128)][kp 64] stride 68
    uint32_t* Bp = dsm + 128 * 68;  // [kp(64)][n 128] stride 136

    int tid = threadIdx.x;
    int lane = tid & 31, warp = tid >> 5;
    int warpM = warp >> 1, warpN = warp & 1;
    int grp = lane >> 2, tig = lane & 3;
    int b = blockIdx.z;
    int m0 = blockIdx.y * 128, n0 = blockIdx.x * 128;

    {
        int r = tid >> 1;
        int hf = tid & 1;
        const uint32_t* src = (const uint32_t*)(att + (long)b * 512 * 128 + (long)(m0 + r) * 128);
        #pragma unroll
        for (int i = 0; i < 8; i++) {
            uint4 v = *(const uint4*)&src[hf * 32 + i * 4];
            *(uint4*)&Ap[r * 68 + hf * 32 + i * 4] = v;
        }
    }
    {
        int kp = tid >> 2;
        int ch = tid & 3;
        const uint32_t* src = py2h + (long)b * 64 * 4096 + (long)kp * 4096 + n0;
        #pragma unroll
        for (int i = 0; i < 8; i++) {
            int c = ch + i * 4;
            uint4 v = *(const uint4*)&src[c * 4];
            *(uint4*)&Bp[kp * 136 + c * 4] = v;
        }
    }
    __syncthreads();

    float acc[2][8][4] = {};
    #pragma unroll
    for (int s = 0; s < 8; s++) {
        int kp0 = s * 8;
        uint32_t a[2][4];
        #pragma unroll
        for (int mt = 0; mt < 2; mt++) {
            int m = warpM * 32 + mt * 16 + grp;
            a[mt][0] = Ap[m * 68 + kp0 + tig];
            a[mt][1] = Ap[(m + 8) * 68 + kp0 + tig];
            a[mt][2] = Ap[m * 68 + kp0 + tig + 4];
            a[mt][3] = Ap[(m + 8) * 68 + kp0 + tig + 4];
        }
        #pragma unroll
        for (int nt = 0; nt < 8; nt++) {
            int n = warpN * 64 + nt * 8 + grp;
            uint32_t b0 = Bp[(kp0 + tig) * 136 + n];
            uint32_t b1 = Bp[(kp0 + tig + 4) * 136 + n];
            #pragma unroll
            for (int mt = 0; mt < 2; mt++)
                mma_f16(acc[mt][nt], a[mt], b0, b1);
        }
    }

    float gm = gptr[0];
    long rb = (long)b * 512 * 4096;
    #pragma unroll
    for (int mt = 0; mt < 2; mt++) {
        #pragma unroll
        for (int h = 0; h < 2; h++) {
            int m = m0 + warpM * 32 + mt * 16 + grp + h * 8;
            int stage = m >> 4;
            int icp_l = (m >> 1) & 7;
            int pos = 2 * (icp_l & 3) + (icp_l >> 2);
            long ob = ((long)(b * 32 + stage) * 4096) * 16 + pos * 2 + (m & 1);
            #pragma unroll
            for (int nt = 0; nt < 8; nt++) {
                int n = n0 + warpN * 64 + nt * 8 + tig * 2;
                float v0 = gm * acc[mt][nt][2 * h]     + res[rb + (long)m * 4096 + n];
                float v1 = gm * acc[mt][nt][2 * h + 1] + res[rb + (long)m * 4096 + n + 1];
                oprh[ob + (long)n * 16]       = __float2half(v0);
                oprh[ob + (long)(n + 1) * 16] = __float2half(v1);
            }
        }
    }
}

// ---------------- 3x3 conv, fp16 m16n8k16, 1 barrier/stage ----------------------
#define SW_WORDS  4608               // 1152 fragments x 4 words per stage
#define SIN_WORDS (6 * 66 * 8)       // 3168
#define CONV_SMEM (3 * (SW_WORDS + SIN_WORDS) * 4)   // 93312 B -> 2 blocks/SM

__device__ __forceinline__ void conv_issue(int stage, uint32_t swb, uint32_t sinb,
                                           const __half* __restrict__ in, int b,
                                           int y0, int ocblk, int tid)
{
    const uint4* wsrc = g_wfrag + (long)(ocblk * 32 + stage) * 1152;
    for (int idx = tid; idx < 1152; idx += 256)
        cp16(swb + (uint32_t)idx * 16, wsrc + idx);
    const __half* src = in + ((long)(b * 32 + stage) * 4096) * 16;
    for (int idx = tid; idx < 768; idx += 256) {
        int p  = idx >> 1;
        int hf = idx & 1;
        int y  = p >> 6;
        int xo = p & 63;
        int gy = y0 - 1 + y;
        if (gy >= 0 && gy < 64)
            cp16(sinb + (uint32_t)((y * 66 + xo + 1) * 32 + hf * 16),
                 src + ((long)(gy * 64 + xo)) * 16 + hf * 8);
    }
}

__global__ __launch_bounds__(256, 2)
void conv3x3_tc_kernel(const __half* __restrict__ in, float* __restrict__ out)
{
    extern __shared__ uint32_t smem[];
    uint32_t* sW  = smem;                     // 3 stages
    uint32_t* sIn = smem + 3 * SW_WORDS;      // 3 stages
    uint32_t sw_base  = (uint32_t)__cvta_generic_to_shared(sW);
    uint32_t sin_base = (uint32_t)__cvta_generic_to_shared(sIn);

    int tid = threadIdx.x;
    int lane = tid & 31;
    int warp = tid >> 5;
    int warpM = warp >> 2;
    int warpN = warp & 3;
    int grp = lane >> 2;
    int tig = lane & 3;

    int b     = blockIdx.z;
    int ocblk = blockIdx.y;
    int oc0   = ocblk * 64;
    int y0    = blockIdx.x * 4;

    for (int i = tid; i < 3 * SIN_WORDS; i += 256) sIn[i] = 0;
    __syncthreads();

    conv_issue(0, sw_base, sin_base, in, b, y0, ocblk, tid);
    asm volatile("cp.async.commit_group;");
    conv_issue(1, sw_base + SW_WORDS * 4, sin_base + SIN_WORDS * 4, in, b, y0, ocblk, tid);
    asm volatile("cp.async.commit_group;");

    float acc[2][8][4] = {};

    for (int it = 0; it < 32; it++) {
        int buf = it % 3;
        if (it < 30) asm volatile("cp.async.wait_group 1;");
        else         asm volatile("cp.async.wait_group 0;");
        __syncthreads();
        if (it < 30) {
            int nb = (it + 2) % 3;
            conv_issue(it + 2, sw_base + nb * SW_WORDS * 4,
                       sin_base + nb * SIN_WORDS * 4, in, b, y0, ocblk, tid);
            asm volatile("cp.async.commit_group;");
        }

        const uint32_t* sWb  = sW + buf * SW_WORDS;
        const uint32_t* sInb = sIn + buf * SIN_WORDS;

        #pragma unroll
        for (int ky = 0; ky < 3; ky++) {
            #pragma unroll
            for (int kx = 0; kx < 3; kx++) {
                const int tap = ky * 3 + kx;
                uint4 av[2];
                #pragma unroll
                for (int mt = 0; mt < 2; mt++) {
                    int mslot = warpM * 2 + mt;
                    av[mt] = *(const uint4*)&sWb[((tap * 4 + mslot) * 8 + grp) * 16 + tig * 4];
                }
                const int rowb = ((warpN + ky) * 66 + kx) * 8 + 2 * tig;
                uint2 bf[8];
                #pragma unroll
                for (int j = 0; j < 8; j++)
                    bf[j] = *(const uint2*)&sInb[rowb + (j * 8 + grp) * 8];
                #pragma unroll
                for (int j = 0; j < 8; j++) {
                    #pragma unroll
                    for (int mt = 0; mt < 2; mt++)
                        mma_f16(acc[mt][j], (const uint32_t*)&av[mt], bf[j].x, bf[j].y);
                }
            }
        }
    }

    int y = y0 + warpN;
    #pragma unroll
    for (int mt = 0; mt < 2; mt++) {
        int row = oc0 + warpM * 32 + mt * 16 + grp;
        float s0 = g_s3[row],     t0 = g_t3[row];
        float s8 = g_s3[row + 8], t8 = g_t3[row + 8];
        long base0 = ((long)b * 512 + row) * 4096 + (long)y * 64;
        long base8 = base0 + 8L * 4096;
        #pragma unroll
        for (int j = 0; j < 8; j++) {
            int x = j * 8 + tig * 2;
            out[base0 + x    ] = fmaxf(s0 * acc[mt][j][0] + t0, 0.f);
            out[base0 + x + 1] = fmaxf(s0 * acc[mt][j][1] + t0, 0.f);
            out[base8 + x    ] = fmaxf(s8 * acc[mt][j][2] + t8, 0.f);
            out[base8 + x + 1] = fmaxf(s8 * acc[mt][j][3] + t8, 0.f);
        }
    }
}

// ------------------------------- launcher ---------------------------------------
extern "C" void kernel_launch(void* const* d_in, const int* in_sizes, int n_in,
                              void* d_out, int out_size)
{
    const float* x     = (const float*)d_in[0];
    const float* q1_w  = (const float*)d_in[1];
    const float* q1_b  = (const float*)d_in[2];
    const float* bn1_g = (const float*)d_in[3];
    const float* bn1_b = (const float*)d_in[4];
    const float* bn1_m = (const float*)d_in[5];
    const float* bn1_v = (const float*)d_in[6];
    const float* q2_w  = (const float*)d_in[7];
    const float* q2_b  = (const float*)d_in[8];
    const float* bn2_g = (const float*)d_in[9];
    const float* bn2_b = (const float*)d_in[10];
    const float* bn2_m = (const float*)d_in[11];
    const float* bn2_v = (const float*)d_in[12];
    const float* p1_w  = (const float*)d_in[13];
    const float* p1_b  = (const float*)d_in[14];
    const float* fus_w = (const float*)d_in[15];
    const float* fus_b = (const float*)d_in[16];
    const float* bn3_g = (const float*)d_in[17];
    const float* bn3_b = (const float*)d_in[18];
    const float* bn3_m = (const float*)d_in[19];
    const float* bn3_v = (const float*)d_in[20];
    const float* gamma = (const float*)d_in[21];

    float *py1, *py2, *e1T, *e1t, *e2, *part, *e2p, *eng, *s1, *t1, *s2, *t2;
    uint32_t* py2h;
    __half *atth, *oprh;
    cudaGetSymbolAddress((void**)&py1, g_py1);
    cudaGetSymbolAddress((void**)&py2, g_py2);
    cudaGetSymbolAddress((void**)&py2h, g_py2h);
    cudaGetSymbolAddress((void**)&e1T, g_e1T);
    cudaGetSymbolAddress((void**)&e1t, g_e1t);
    cudaGetSymbolAddress((void**)&e2,  g_e2);
    cudaGetSymbolAddress((void**)&part, g_part);
    cudaGetSymbolAddress((void**)&e2p, g_e2p);
    cudaGetSymbolAddress((void**)&eng, g_eng);
    cudaGetSymbolAddress((void**)&atth, g_atth);
    cudaGetSymbolAddress((void**)&oprh, g_oprh);
    cudaGetSymbolAddress((void**)&s1,  g_s1);
    cudaGetSymbolAddress((void**)&t1,  g_t1);
    cudaGetSymbolAddress((void**)&s2,  g_s2);
    cudaGetSymbolAddress((void**)&t2,  g_t2);

    static bool attr_set = false;
    if (!attr_set) {
        cudaFuncSetAttribute(conv3x3_tc_kernel,
                             cudaFuncAttributeMaxDynamicSharedMemorySize, CONV_SMEM);
        cudaFuncSetAttribute(hgemm9,
                             cudaFuncAttributeMaxDynamicSharedMemorySize, HG_SMEM);
        attr_set = true;
    }

    fold_kernel<<<1, 512>>>(q1_b, bn1_g, bn1_b, bn1_m, bn1_v,
                            q2_b, bn2_g, bn2_b, bn2_m, bn2_v,
                            fus_b, bn3_g, bn3_b, bn3_m, bn3_v);

    wpack<<<(294912 + 255) / 256, 256>>>(fus_w);

    // 1) py1 = relu(bn1(q1_w @ x))
    sgemm16<2, false, false><<<dim3(32, 2, 16), 256>>>(q1_w, x, py1, 4096, 512,
        0, 0, 0L,  0L, 512L,  512L * 4096, 4096L,  256L * 4096,
        32.f, 8.f, 1.f / 256.f, s1, t1, nullptr);

    // 2) py2 = relu(bn2(q2_w @ py1))  (+ packed fp16 copy)
    sgemm16<2, false, false><<<dim3(32, 1, 16), 256>>>(q2_w, py1, py2, 4096, 256,
        0, 0, 0L,  0L, 256L,  256L * 4096, 4096L,  128L * 4096,
        32.f, 2.f, 1.f / 64.f, s2, t2, (__half*)py2h);

    // 3) e1T = x @ py1^T  — split-K x4 + reduce   (512 blocks)
    sgemm16<0, true, true><<<dim3(8, 4, 16), 256>>>(x, py1, part, 256, 4096,
        2, 1024, 16L * 512 * 256,
        512L * 4096, 4096L,  256L * 4096, 4096L,  512L * 256,
        8.f, 2.f, 1.f / 16.f, nullptr, nullptr, nullptr);
    reduceP<4><<<(16 * 512 * 256 + 255) / 256, 256>>>(part, e1T, 16 * 512 * 256,
                                                      nullptr, 1);

    // 4) e1t = e1T @ p1_w^T (+bias in reduce)  — split-K x2   (256 blocks)
    sgemm16<0, true, true><<<dim3(4, 4, 16), 256>>>(e1T, p1_w, part, 256, 256,
        2, 128, 16L * 512 * 256,
        512L * 256, 256L,  0L, 256L,  512L * 256,
        4.f, 32.f, 1.f / 128.f, nullptr, nullptr, nullptr);
    reduceP<2><<<(16 * 512 * 256 + 255) / 256, 256>>>(part, e1t, 16 * 512 * 256,
                                                      p1_b, 256);

    // 5) e2 = py1 @ py2^T  — split-K x8 + reduce   (256 blocks)
    sgemm16<0, true, true><<<dim3(8, 2, 16), 256>>>(py1, py2, part, 128, 4096,
        1, 512, 16L * 256 * 128,
        256L * 4096, 4096L,  128L * 4096, 4096L,  256L * 128,
        2.f, 2.f, 1.f / 4.f, nullptr, nullptr, nullptr);
    reduceP<8><<<(16 * 256 * 128 + 255) / 256, 256>>>(part, e2, 16 * 256 * 128,
                                                      nullptr, 1);

    // 6) e2p = p1_w @ e2 + p1_b
    sgemm16<1, false, false><<<dim3(1, 2, 16), 256>>>(p1_w, e2, e2p, 128, 256,
        0, 0, 0L,  0L, 256L,  256L * 128, 128L,  256L * 128,
        32.f, 1.f, 1.f / 32.f, nullptr, p1_b, nullptr);

    // 7) energy = e1t @ e2p  — split-K x2   (128 blocks)
    sgemm16<0, false, true><<<dim3(2, 4, 16), 256>>>(e1t, e2p, part, 128, 256,
        1, 128, 16L * 512 * 128,
        512L * 256, 256L,  256L * 128, 128L,  512L * 128,
        8.f, 1.f, 1.f / 8.f, nullptr, nullptr, nullptr);
    reduceP<2><<<(16 * 512 * 128 + 255) / 256, 256>>>(part, eng, 16 * 512 * 128,
                                                      nullptr, 1);

    // 8) attention = softmax(rowmax - energy) -> fp16
    softmax_neg<<<16 * 512, 128>>>(eng, atth);

    // 9) oprh = fp16(gamma * att@py2 + x), conv-ready interleaved layout
    hgemm9<<<dim3(32, 4, 16), 256, HG_SMEM>>>(atth, py2h, oprh, x, gamma);

    // 10) out = relu(bn3(conv3x3(oprh)))  — 1 barrier/stage
    conv3x3_tc_kernel<<<dim3(16, 8, 16), 256, CONV_SMEM>>>(oprh, (float*)d_out);
}